// round 5
// baseline (speedup 1.0000x reference)
#include <cuda_runtime.h>
#include <math.h>

#define S_LEN 2048
#define DMODEL 1024
#define NHEADS 16
#define HDIM 64
#define RADIUS 256
#define NGLOB 4

__device__ float g_P[(size_t)5 * S_LEN * DMODEL];
__device__ float g_O[(size_t)S_LEN * DMODEL];

// pre-split tf32 hi/lo: [0:ACT) activations, then 4 weights (Wqs,Wks,Wvs,Wo)
#define ACT_ELEMS (S_LEN * DMODEL)
#define W_ELEMS   (DMODEL * DMODEL)
__device__ unsigned g_Sh[(size_t)ACT_ELEMS + 4 * W_ELEMS];
__device__ unsigned g_Sl[(size_t)ACT_ELEMS + 4 * W_ELEMS];

struct P4 { const float* p[4]; };

__device__ __forceinline__ unsigned f2tf32(float x) {
    unsigned r;
    asm("cvt.rna.tf32.f32 %0, %1;" : "=r"(r) : "f"(x));
    return r;
}

__device__ __forceinline__ void mma_tf32(float* c, const unsigned* a, const unsigned* b) {
    asm volatile(
        "mma.sync.aligned.m16n8k8.row.col.f32.tf32.tf32.f32 "
        "{%0,%1,%2,%3}, {%4,%5,%6,%7}, {%8,%9}, {%0,%1,%2,%3};"
        : "+f"(c[0]), "+f"(c[1]), "+f"(c[2]), "+f"(c[3])
        : "r"(a[0]), "r"(a[1]), "r"(a[2]), "r"(a[3]), "r"(b[0]), "r"(b[1]));
}

__device__ __forceinline__ void cpa16(unsigned* dst, const unsigned* src) {
    unsigned s = (unsigned)__cvta_generic_to_shared(dst);
    asm volatile("cp.async.cg.shared.global [%0], [%1], 16;" :: "r"(s), "l"(src));
}

// ---------------------------------------------------------------------------
// split kernels: fp32 -> (tf32 hi, tf32 lo)
// ---------------------------------------------------------------------------
__global__ __launch_bounds__(256) void split_kernel(const float* __restrict__ src,
                                                    unsigned* __restrict__ h,
                                                    unsigned* __restrict__ l, int n4)
{
    int i = blockIdx.x * blockDim.x + threadIdx.x;
    if (i >= n4) return;
    float4 v = ((const float4*)src)[i];
    float f[4] = {v.x, v.y, v.z, v.w};
    uint4 hv, lv;
    unsigned* hp = &hv.x;
    unsigned* lp = &lv.x;
#pragma unroll
    for (int e = 0; e < 4; e++) {
        unsigned hb = f2tf32(f[e]);
        hp[e] = hb;
        lp[e] = f2tf32(f[e] - __uint_as_float(hb));
    }
    ((uint4*)h)[i] = hv;
    ((uint4*)l)[i] = lv;
}

__global__ __launch_bounds__(256) void split_w_kernel(P4 srcs,
                                                      unsigned* __restrict__ hbase,
                                                      unsigned* __restrict__ lbase)
{
    const float* src = srcs.p[blockIdx.z];
    unsigned* h = hbase + ACT_ELEMS + (size_t)blockIdx.z * W_ELEMS;
    unsigned* l = lbase + ACT_ELEMS + (size_t)blockIdx.z * W_ELEMS;
    int i = blockIdx.x * blockDim.x + threadIdx.x;   // W_ELEMS/4 total
    float4 v = ((const float4*)src)[i];
    float f[4] = {v.x, v.y, v.z, v.w};
    uint4 hv, lv;
    unsigned* hp = &hv.x;
    unsigned* lp = &lv.x;
#pragma unroll
    for (int e = 0; e < 4; e++) {
        unsigned hb = f2tf32(f[e]);
        hp[e] = hb;
        lp[e] = f2tf32(f[e] - __uint_as_float(hb));
    }
    ((uint4*)h)[i] = hv;
    ((uint4*)l)[i] = lv;
}

// ---------------------------------------------------------------------------
// 3xTF32 GEMM, pre-split inputs, 3-stage cp.async pipeline, optional fused RoPE
// block 128x128x16, 8 warps (4M x 2N), warp tile 32x64 (warp N-tile == 1 head)
// ---------------------------------------------------------------------------
#define GBK 16
#define ASTRIDE 20
#define BSTRIDE 136
#define SA_WORDS (128 * ASTRIDE)
#define SB_WORDS (GBK * BSTRIDE)
#define GEMM_SMEM_WORDS (3 * 2 * (SA_WORDS + SB_WORDS))
#define GEMM_SMEM_BYTES (GEMM_SMEM_WORDS * 4)

__device__ __forceinline__ void gemm3_body(const unsigned* __restrict__ Agh,
                                           const unsigned* __restrict__ Agl,
                                           const unsigned* __restrict__ Bgh,
                                           const unsigned* __restrict__ Bgl,
                                           float* __restrict__ C,
                                           bool do_rope,
                                           const float* __restrict__ cos_t,
                                           const float* __restrict__ sin_t,
                                           const int* __restrict__ pos)
{
    extern __shared__ unsigned sm[];
    unsigned* uAh = sm;
    unsigned* uAl = sm + 3 * SA_WORDS;
    unsigned* uBh = sm + 6 * SA_WORDS;
    unsigned* uBl = uBh + 3 * SB_WORDS;

    const int tid = threadIdx.x;
    const int lane = tid & 31;
    const int warp = tid >> 5;
    const int wm = warp >> 1;
    const int wn = warp & 1;
    const int bx = blockIdx.x, by = blockIdx.y;

    float acc[2][8][4];
#pragma unroll
    for (int mt = 0; mt < 2; mt++)
#pragma unroll
        for (int nt = 0; nt < 8; nt++)
#pragma unroll
            for (int e = 0; e < 4; e++) acc[mt][nt][e] = 0.f;

    auto load_stage = [&](int st, int k0) {
        unsigned* ah = uAh + st * SA_WORDS;
        unsigned* al = uAl + st * SA_WORDS;
        unsigned* bh = uBh + st * SB_WORDS;
        unsigned* bl = uBl + st * SB_WORDS;
#pragma unroll
        for (int it = 0; it < 2; it++) {
            int idx = tid + it * 256;
            int m = idx >> 2, kq = (idx & 3) << 2;
            size_t ga = (size_t)(by * 128 + m) * DMODEL + k0 + kq;
            cpa16(ah + m * ASTRIDE + kq, Agh + ga);
            cpa16(al + m * ASTRIDE + kq, Agl + ga);
            int kk = idx >> 5, nq = (idx & 31) << 2;
            size_t gb = (size_t)(k0 + kk) * DMODEL + bx * 128 + nq;
            cpa16(bh + kk * BSTRIDE + nq, Bgh + gb);
            cpa16(bl + kk * BSTRIDE + nq, Bgl + gb);
        }
    };

    load_stage(0, 0);
    asm volatile("cp.async.commit_group;");
    load_stage(1, GBK);
    asm volatile("cp.async.commit_group;");

    const int NT = DMODEL / GBK;
#pragma unroll 1
    for (int i = 0; i < NT; i++) {
        int st = i % 3;
        asm volatile("cp.async.wait_group 1;");
        __syncthreads();

        unsigned* ah_s = uAh + st * SA_WORDS;
        unsigned* al_s = uAl + st * SA_WORDS;
        unsigned* bh_s = uBh + st * SB_WORDS;
        unsigned* bl_s = uBl + st * SB_WORDS;

#pragma unroll
        for (int ks = 0; ks < GBK; ks += 8) {
            unsigned ah[2][4], al[2][4];
#pragma unroll
            for (int mt = 0; mt < 2; mt++) {
                int r = wm * 32 + mt * 16 + (lane >> 2);
                int c = ks + (lane & 3);
                ah[mt][0] = ah_s[r * ASTRIDE + c];
                ah[mt][1] = ah_s[(r + 8) * ASTRIDE + c];
                ah[mt][2] = ah_s[r * ASTRIDE + c + 4];
                ah[mt][3] = ah_s[(r + 8) * ASTRIDE + c + 4];
                al[mt][0] = al_s[r * ASTRIDE + c];
                al[mt][1] = al_s[(r + 8) * ASTRIDE + c];
                al[mt][2] = al_s[r * ASTRIDE + c + 4];
                al[mt][3] = al_s[(r + 8) * ASTRIDE + c + 4];
            }
#pragma unroll
            for (int nt = 0; nt < 8; nt++) {
                int n = wn * 64 + nt * 8 + (lane >> 2);
                int k = ks + (lane & 3);
                unsigned bh[2], bl[2];
                bh[0] = bh_s[k * BSTRIDE + n];
                bh[1] = bh_s[(k + 4) * BSTRIDE + n];
                bl[0] = bl_s[k * BSTRIDE + n];
                bl[1] = bl_s[(k + 4) * BSTRIDE + n];
#pragma unroll
                for (int mt = 0; mt < 2; mt++) {
                    mma_tf32(acc[mt][nt], ah[mt], bh);
                    mma_tf32(acc[mt][nt], ah[mt], bl);
                    mma_tf32(acc[mt][nt], al[mt], bh);
                }
            }
        }

        if (i + 2 < NT) load_stage((i + 2) % 3, (i + 2) * GBK);
        asm volatile("cp.async.commit_group;");
    }

    // ---- optional fused RoPE: warp covers exactly one head (64 cols) ----
    if (do_rope) {
#pragma unroll
        for (int mt = 0; mt < 2; mt++) {
            int r0 = by * 128 + wm * 32 + mt * 16 + (lane >> 2);
            int p0 = __ldg(pos + r0);
            int p1 = __ldg(pos + r0 + 8);
#pragma unroll
            for (int nt = 0; nt < 4; nt++) {
#pragma unroll
                for (int e = 0; e < 2; e++) {
                    int d = nt * 8 + 2 * (lane & 3) + e;
                    // row r0
                    {
                        float c0 = __ldg(cos_t + p0 * HDIM + d);
                        float s0 = __ldg(sin_t + p0 * HDIM + d);
                        float c1 = __ldg(cos_t + p0 * HDIM + d + 32);
                        float s1 = __ldg(sin_t + p0 * HDIM + d + 32);
                        float x0 = acc[mt][nt][e];
                        float x1 = acc[mt][nt + 4][e];
                        acc[mt][nt][e]     = x0 * c0 - x1 * s0;
                        acc[mt][nt + 4][e] = x1 * c1 + x0 * s1;
                    }
                    // row r0+8
                    {
                        float c0 = __ldg(cos_t + p1 * HDIM + d);
                        float s0 = __ldg(sin_t + p1 * HDIM + d);
                        float c1 = __ldg(cos_t + p1 * HDIM + d + 32);
                        float s1 = __ldg(sin_t + p1 * HDIM + d + 32);
                        float x0 = acc[mt][nt][e + 2];
                        float x1 = acc[mt][nt + 4][e + 2];
                        acc[mt][nt][e + 2]     = x0 * c0 - x1 * s0;
                        acc[mt][nt + 4][e + 2] = x1 * c1 + x0 * s1;
                    }
                }
            }
        }
    }

#pragma unroll
    for (int mt = 0; mt < 2; mt++) {
        int r0 = by * 128 + wm * 32 + mt * 16 + (lane >> 2);
#pragma unroll
        for (int nt = 0; nt < 8; nt++) {
            int c = bx * 128 + wn * 64 + nt * 8 + ((lane & 3) << 1);
            *(float2*)(C + (size_t)r0 * DMODEL + c) =
                make_float2(acc[mt][nt][0], acc[mt][nt][1]);
            *(float2*)(C + (size_t)(r0 + 8) * DMODEL + c) =
                make_float2(acc[mt][nt][2], acc[mt][nt][3]);
        }
    }
}

__global__ __launch_bounds__(256, 1) void proj_kernel(const float* __restrict__ cos_t,
                                                      const float* __restrict__ sin_t,
                                                      const int* __restrict__ pos)
{
    int z = blockIdx.z;   // 0=Q(rope) 1=K(rope) 2=V
    gemm3_body(g_Sh, g_Sl,
               g_Sh + ACT_ELEMS + (size_t)z * W_ELEMS,
               g_Sl + ACT_ELEMS + (size_t)z * W_ELEMS,
               g_P + (size_t)z * ACT_ELEMS,
               z < 2, cos_t, sin_t, pos);
}

__global__ __launch_bounds__(256, 1) void out_gemm_kernel(float* __restrict__ out)
{
    gemm3_body(g_Sh, g_Sl,
               g_Sh + ACT_ELEMS + (size_t)3 * W_ELEMS,
               g_Sl + ACT_ELEMS + (size_t)3 * W_ELEMS,
               out, false, nullptr, nullptr, nullptr);
}

// ---------------------------------------------------------------------------
// KG/VG: only rows 0..3 are ever read -> tiny fp32 kernel.
// grid (DMODEL/256, 1), 256 threads; each thread = one output column.
// ---------------------------------------------------------------------------
__global__ __launch_bounds__(256) void kgvg_kernel(const float* __restrict__ x,
                                                   const float* __restrict__ Wkg,
                                                   const float* __restrict__ Wvg)
{
    __shared__ float xs[NGLOB][DMODEL];
    for (int i = threadIdx.x; i < NGLOB * DMODEL; i += 256)
        xs[i >> 10][i & 1023] = x[i];
    __syncthreads();

    int d = blockIdx.x * 256 + threadIdx.x;
    float ak[NGLOB] = {0.f, 0.f, 0.f, 0.f};
    float av[NGLOB] = {0.f, 0.f, 0.f, 0.f};
    for (int k = 0; k < DMODEL; k++) {
        float wk = Wkg[(size_t)k * DMODEL + d];
        float wv = Wvg[(size_t)k * DMODEL + d];
#pragma unroll
        for (int t = 0; t < NGLOB; t++) {
            ak[t] = fmaf(xs[t][k], wk, ak[t]);
            av[t] = fmaf(xs[t][k], wv, av[t]);
        }
    }
#pragma unroll
    for (int t = 0; t < NGLOB; t++) {
        g_P[(size_t)3 * ACT_ELEMS + (size_t)t * DMODEL + d] = ak[t];
        g_P[(size_t)4 * ACT_ELEMS + (size_t)t * DMODEL + d] = av[t];
    }
}

// ---------------------------------------------------------------------------
// Block-tiled MMA flash attention (unchanged)
// ---------------------------------------------------------------------------
#define KSTR 68
#define VSTR 72
#define PSTR 68
#define OFF_KH 0
#define OFF_KL (OFF_KH + 64 * KSTR)
#define OFF_VH (OFF_KL + 64 * KSTR)
#define OFF_VL (OFF_VH + 64 * VSTR)
#define OFF_PH (OFF_VL + 64 * VSTR)
#define OFF_PL (OFF_PH + 64 * PSTR)
#define OFF_VG (OFF_PL + 64 * PSTR)
#define ATT_SMEM_WORDS (OFF_VG + HDIM)

__global__ __launch_bounds__(128, 2) void attn_kernel()
{
    extern __shared__ unsigned smem_u[];
    unsigned* Kh = smem_u + OFF_KH;
    unsigned* Kl = smem_u + OFF_KL;
    unsigned* Vh = smem_u + OFF_VH;
    unsigned* Vl = smem_u + OFF_VL;
    unsigned* Ph = smem_u + OFF_PH;
    unsigned* Pl = smem_u + OFF_PL;
    float*    Vg4 = (float*)(smem_u + OFF_VG);

    const int h  = blockIdx.x;
    const int i0 = blockIdx.y * 64;
    const int tid = threadIdx.x;
    const int lane = tid & 31;
    const int wq = tid >> 5;

    const float* Q = g_P;
    const float* K = g_P + (size_t)1 * ACT_ELEMS;
    const float* V = g_P + (size_t)2 * ACT_ELEMS;

    if (tid < HDIM) {
        const float* vb = V + h * HDIM + tid;
        Vg4[tid] = vb[0] + vb[DMODEL] + vb[2 * DMODEL] + vb[3 * DMODEL];
    }

    unsigned qh[8][4], ql[8][4];
    {
        const int r0 = i0 + wq * 16 + (lane >> 2);
#pragma unroll
        for (int ks = 0; ks < 8; ks++) {
            int c = h * HDIM + ks * 8 + (lane & 3);
            float f[4];
            f[0] = Q[(size_t)r0 * DMODEL + c];
            f[1] = Q[(size_t)(r0 + 8) * DMODEL + c];
            f[2] = Q[(size_t)r0 * DMODEL + c + 4];
            f[3] = Q[(size_t)(r0 + 8) * DMODEL + c + 4];
#pragma unroll
            for (int e = 0; e < 4; e++) {
                unsigned hi = f2tf32(f[e]);
                qh[ks][e] = hi;
                ql[ks][e] = f2tf32(f[e] - __uint_as_float(hi));
            }
        }
    }

    float out[8][4];
#pragma unroll
    for (int nt = 0; nt < 8; nt++)
#pragma unroll
        for (int e = 0; e < 4; e++) out[nt][e] = 0.f;
    float m0 = -3.4e38f, m1 = -3.4e38f, sum0 = 0.f, sum1 = 0.f;

    const int j_start = (i0 - RADIUS) > 0 ? (i0 - RADIUS) : 0;

    for (int jc = j_start; jc < i0 + 64; jc += 64) {
        __syncthreads();
#pragma unroll
        for (int it = 0; it < 8; it++) {
            int idx = it * 128 + tid;
            int key = idx >> 4;
            int dq = (idx & 15) << 2;
            size_t gofs = (size_t)(jc + key) * DMODEL + h * HDIM + dq;
            float4 kv = *(const float4*)(K + gofs);
            float4 vv = *(const float4*)(V + gofs);
            float kf[4] = {kv.x, kv.y, kv.z, kv.w};
            float vf[4] = {vv.x, vv.y, vv.z, vv.w};
#pragma unroll
            for (int e = 0; e < 4; e++) {
                unsigned hk = f2tf32(kf[e]);
                Kh[key * KSTR + dq + e] = hk;
                Kl[key * KSTR + dq + e] = f2tf32(kf[e] - __uint_as_float(hk));
                unsigned hv = f2tf32(vf[e]);
                Vh[key * VSTR + dq + e] = hv;
                Vl[key * VSTR + dq + e] = f2tf32(vf[e] - __uint_as_float(hv));
            }
        }
        __syncthreads();

        float sc[8][4];
#pragma unroll
        for (int nt = 0; nt < 8; nt++)
#pragma unroll
            for (int e = 0; e < 4; e++) sc[nt][e] = 0.f;

#pragma unroll
        for (int ks = 0; ks < 8; ks++) {
#pragma unroll
            for (int nt = 0; nt < 8; nt++) {
                int n = nt * 8 + (lane >> 2);
                int k = ks * 8 + (lane & 3);
                unsigned bh[2], bl[2];
                bh[0] = Kh[n * KSTR + k];
                bh[1] = Kh[n * KSTR + k + 4];
                bl[0] = Kl[n * KSTR + k];
                bl[1] = Kl[n * KSTR + k + 4];
                mma_tf32(sc[nt], qh[ks], bh);
                mma_tf32(sc[nt], qh[ks], bl);
                mma_tf32(sc[nt], ql[ks], bh);
            }
        }

        const int ibase = i0 + wq * 16 + (lane >> 2);
        float mn0 = m0, mn1 = m1;
#pragma unroll
        for (int nt = 0; nt < 8; nt++) {
#pragma unroll
            for (int e = 0; e < 4; e++) {
                int i = ibase + ((e & 2) ? 8 : 0);
                int j = jc + nt * 8 + 2 * (lane & 3) + (e & 1);
                bool inw = (j <= i) && (i - j <= RADIUS);
                float raw = sc[nt][e] * 0.125f;
                float s;
                if (j < NGLOB) s = inw ? (raw + 1e9f) : 0.f;
                else           s = inw ? raw : -3.0e38f;
                sc[nt][e] = s;
                if (e & 2) mn1 = fmaxf(mn1, s); else mn0 = fmaxf(mn0, s);
            }
        }
#pragma unroll
        for (int o = 1; o < 4; o <<= 1) {
            mn0 = fmaxf(mn0, __shfl_xor_sync(0xffffffff, mn0, o));
            mn1 = fmaxf(mn1, __shfl_xor_sync(0xffffffff, mn1, o));
        }
        float esc0 = __expf(m0 - mn0);
        float esc1 = __expf(m1 - mn1);
        m0 = mn0; m1 = mn1;

        float ps0 = 0.f, ps1 = 0.f;
#pragma unroll
        for (int nt = 0; nt < 8; nt++) {
#pragma unroll
            for (int e = 0; e < 4; e++) {
                float p = __expf(sc[nt][e] - ((e & 2) ? m1 : m0));
                sc[nt][e] = p;
                if (e & 2) ps1 += p; else ps0 += p;
            }
        }
#pragma unroll
        for (int o = 1; o < 4; o <<= 1) {
            ps0 += __shfl_xor_sync(0xffffffff, ps0, o);
            ps1 += __shfl_xor_sync(0xffffffff, ps1, o);
        }
        sum0 = sum0 * esc0 + ps0;
        sum1 = sum1 * esc1 + ps1;
#pragma unroll
        for (int nt = 0; nt < 8; nt++) {
            out[nt][0] *= esc0; out[nt][1] *= esc0;
            out[nt][2] *= esc1; out[nt][3] *= esc1;
        }

#pragma unroll
        for (int nt = 0; nt < 8; nt++) {
#pragma unroll
            for (int e = 0; e < 4; e++) {
                int row = wq * 16 + (lane >> 2) + ((e & 2) ? 8 : 0);
                int col = nt * 8 + 2 * (lane & 3) + (e & 1);
                float p = sc[nt][e];
                unsigned hp = f2tf32(p);
                Ph[row * PSTR + col] = hp;
                Pl[row * PSTR + col] = f2tf32(p - __uint_as_float(hp));
            }
        }
        __syncwarp();

#pragma unroll
        for (int ks = 0; ks < 8; ks++) {
            int r = wq * 16 + (lane >> 2);
            int c = ks * 8 + (lane & 3);
            unsigned pah[4], pal[4];
            pah[0] = Ph[r * PSTR + c];
            pah[1] = Ph[(r + 8) * PSTR + c];
            pah[2] = Ph[r * PSTR + c + 4];
            pah[3] = Ph[(r + 8) * PSTR + c + 4];
            pal[0] = Pl[r * PSTR + c];
            pal[1] = Pl[(r + 8) * PSTR + c];
            pal[2] = Pl[r * PSTR + c + 4];
            pal[3] = Pl[(r + 8) * PSTR + c + 4];
#pragma unroll
            for (int nt = 0; nt < 8; nt++) {
                int k = ks * 8 + (lane & 3);
                int n = nt * 8 + (lane >> 2);
                unsigned vbh[2], vbl[2];
                vbh[0] = Vh[k * VSTR + n];
                vbh[1] = Vh[(k + 4) * VSTR + n];
                vbl[0] = Vl[k * VSTR + n];
                vbl[1] = Vl[(k + 4) * VSTR + n];
                mma_tf32(out[nt], pah, vbh);
                mma_tf32(out[nt], pah, vbl);
                mma_tf32(out[nt], pal, vbh);
            }
        }
        __syncwarp();
    }

    if (j_start > 0) {
        float mn0 = fmaxf(m0, 0.f), mn1 = fmaxf(m1, 0.f);
        float esc0 = __expf(m0 - mn0), esc1 = __expf(m1 - mn1);
        float e0 = __expf(0.f - mn0), e1 = __expf(0.f - mn1);
        sum0 = sum0 * esc0 + 4.f * e0;
        sum1 = sum1 * esc1 + 4.f * e1;
#pragma unroll
        for (int nt = 0; nt < 8; nt++) {
            int col = nt * 8 + 2 * (lane & 3);
            out[nt][0] = out[nt][0] * esc0 + e0 * Vg4[col];
            out[nt][1] = out[nt][1] * esc0 + e0 * Vg4[col + 1];
            out[nt][2] = out[nt][2] * esc1 + e1 * Vg4[col];
            out[nt][3] = out[nt][3] * esc1 + e1 * Vg4[col + 1];
        }
    }

    float inv0 = 1.f / sum0, inv1 = 1.f / sum1;
    const int r0 = i0 + wq * 16 + (lane >> 2);
#pragma unroll
    for (int nt = 0; nt < 8; nt++) {
        int cb = h * HDIM + nt * 8 + 2 * (lane & 3);
        *(float2*)(g_O + (size_t)r0 * DMODEL + cb) =
            make_float2(out[nt][0] * inv0, out[nt][1] * inv0);
        *(float2*)(g_O + (size_t)(r0 + 8) * DMODEL + cb) =
            make_float2(out[nt][2] * inv1, out[nt][3] * inv1);
    }
}

// ---------------------------------------------------------------------------
// Global attention (KG/VG rows 0..3) — adds into g_O. Warp per (i, h).
// ---------------------------------------------------------------------------
__global__ __launch_bounds__(128) void global_attn_kernel()
{
    int warp = (blockIdx.x * blockDim.x + threadIdx.x) >> 5;
    int lane = threadIdx.x & 31;
    int h = warp & (NHEADS - 1);
    int i = warp >> 4;
    if (i >= S_LEN) return;

    const float scale = 0.125f;
    const float* Q  = g_P;
    const float* KG = g_P + (size_t)3 * ACT_ELEMS;
    const float* VG = g_P + (size_t)4 * ACT_ELEMS;

    const float* qp = Q + (size_t)i * DMODEL + h * HDIM;
    float q0 = qp[lane], q1 = qp[lane + 32];

    float sg[NGLOB];
    float mg = -3.4e38f;
#pragma unroll
    for (int t = 0; t < NGLOB; t++) {
        const float* kp = KG + (size_t)t * DMODEL + h * HDIM;
        float p = q0 * kp[lane] + q1 * kp[lane + 32];
#pragma unroll
        for (int o = 16; o > 0; o >>= 1) p += __shfl_xor_sync(0xffffffff, p, o);
        sg[t] = p * scale;
        mg = fmaxf(mg, sg[t]);
    }
    float den = 0.f, gsum0 = 0.f, gsum1 = 0.f;
#pragma unroll
    for (int t = 0; t < NGLOB; t++) {
        float e = __expf(sg[t] - mg);
        const float* vp = VG + (size_t)t * DMODEL + h * HDIM;
        den += e;
        gsum0 += e * vp[lane];
        gsum1 += e * vp[lane + 32];
    }
    float ginv = 1.f / den;

    float* op = g_O + (size_t)i * DMODEL + h * HDIM;
    op[lane]      += gsum0 * ginv;
    op[lane + 32] += gsum1 * ginv;
}

// ---------------------------------------------------------------------------
// launch
// ---------------------------------------------------------------------------
extern "C" void kernel_launch(void* const* d_in, const int* in_sizes, int n_in,
                              void* d_out, int out_size)
{
    const float* x     = (const float*)d_in[0];
    const float* cos_t = (const float*)d_in[1];
    const float* sin_t = (const float*)d_in[2];
    const int*   pos   = (const int*)d_in[3];
    P4 ws;
    ws.p[0] = (const float*)d_in[4];    // Wqs
    ws.p[1] = (const float*)d_in[5];    // Wks
    ws.p[2] = (const float*)d_in[6];    // Wvs
    ws.p[3] = (const float*)d_in[10];   // Wo
    const float* Wkg = (const float*)d_in[8];
    const float* Wvg = (const float*)d_in[9];
    float* out = (float*)d_out;

    static int attrs_set = 0;
    int attn_smem = ATT_SMEM_WORDS * 4;
    if (!attrs_set) {
        cudaFuncSetAttribute(attn_kernel,
                             cudaFuncAttributeMaxDynamicSharedMemorySize, attn_smem);
        cudaFuncSetAttribute(proj_kernel,
                             cudaFuncAttributeMaxDynamicSharedMemorySize, GEMM_SMEM_BYTES);
        cudaFuncSetAttribute(out_gemm_kernel,
                             cudaFuncAttributeMaxDynamicSharedMemorySize, GEMM_SMEM_BYTES);
        attrs_set = 1;
    }

    unsigned* Sh;
    unsigned* Sl;
    cudaGetSymbolAddress((void**)&Sh, g_Sh);
    cudaGetSymbolAddress((void**)&Sl, g_Sl);

    split_kernel<<<(ACT_ELEMS / 4 + 255) / 256, 256>>>(x, Sh, Sl, ACT_ELEMS / 4);
    dim3 gw(W_ELEMS / 4 / 256, 1, 4);
    split_w_kernel<<<gw, 256>>>(ws, Sh, Sl);

    dim3 gp(DMODEL / 128, S_LEN / 128, 3);
    proj_kernel<<<gp, 256, GEMM_SMEM_BYTES>>>(cos_t, sin_t, pos);

    kgvg_kernel<<<DMODEL / 256, 256>>>(x, Wkg, Wvg);

    dim3 ga(NHEADS, S_LEN / 64);
    attn_kernel<<<ga, 128, attn_smem>>>();

    global_attn_kernel<<<(S_LEN * NHEADS) / 4, 128>>>();

    float* gO;
    cudaGetSymbolAddress((void**)&gO, g_O);
    split_kernel<<<(ACT_ELEMS / 4 + 255) / 256, 256>>>(gO, Sh, Sl, ACT_ELEMS / 4);

    dim3 go(DMODEL / 128, S_LEN / 128);
    out_gemm_kernel<<<go, 256, GEMM_SMEM_BYTES>>>(out);
}

// round 6
// speedup vs baseline: 1.4738x; 1.4738x over previous
#include <cuda_runtime.h>
#include <math.h>

#define S_LEN 2048
#define DMODEL 1024
#define NHEADS 16
#define HDIM 64
#define RADIUS 256
#define NGLOB 4

__device__ float g_P[(size_t)5 * S_LEN * DMODEL];
__device__ float g_O[(size_t)S_LEN * DMODEL];

// kgvg split-K partials: [32 ksplits][2 mats][4 rows][1024 cols]
#define KGVG_KSPLIT 32
__device__ float g_KVGp[KGVG_KSPLIT][2][NGLOB][DMODEL];

// pre-split tf32 hi/lo: [0:ACT) activations, then 4 weights (Wqs,Wks,Wvs,Wo)
#define ACT_ELEMS (S_LEN * DMODEL)
#define W_ELEMS   (DMODEL * DMODEL)
__device__ unsigned g_Sh[(size_t)ACT_ELEMS + 4 * W_ELEMS];
__device__ unsigned g_Sl[(size_t)ACT_ELEMS + 4 * W_ELEMS];

struct P4 { const float* p[4]; };

__device__ __forceinline__ unsigned f2tf32(float x) {
    unsigned r;
    asm("cvt.rna.tf32.f32 %0, %1;" : "=r"(r) : "f"(x));
    return r;
}

__device__ __forceinline__ void mma_tf32(float* c, const unsigned* a, const unsigned* b) {
    asm volatile(
        "mma.sync.aligned.m16n8k8.row.col.f32.tf32.tf32.f32 "
        "{%0,%1,%2,%3}, {%4,%5,%6,%7}, {%8,%9}, {%0,%1,%2,%3};"
        : "+f"(c[0]), "+f"(c[1]), "+f"(c[2]), "+f"(c[3])
        : "r"(a[0]), "r"(a[1]), "r"(a[2]), "r"(a[3]), "r"(b[0]), "r"(b[1]));
}

__device__ __forceinline__ void cpa16(unsigned* dst, const unsigned* src) {
    unsigned s = (unsigned)__cvta_generic_to_shared(dst);
    asm volatile("cp.async.cg.shared.global [%0], [%1], 16;" :: "r"(s), "l"(src));
}

// ---------------------------------------------------------------------------
// split kernels: fp32 -> (tf32 hi, tf32 lo)
// ---------------------------------------------------------------------------
__global__ __launch_bounds__(256) void split_kernel(const float* __restrict__ src,
                                                    unsigned* __restrict__ h,
                                                    unsigned* __restrict__ l, int n4)
{
    int i = blockIdx.x * blockDim.x + threadIdx.x;
    if (i >= n4) return;
    float4 v = ((const float4*)src)[i];
    float f[4] = {v.x, v.y, v.z, v.w};
    uint4 hv, lv;
    unsigned* hp = &hv.x;
    unsigned* lp = &lv.x;
#pragma unroll
    for (int e = 0; e < 4; e++) {
        unsigned hb = f2tf32(f[e]);
        hp[e] = hb;
        lp[e] = f2tf32(f[e] - __uint_as_float(hb));
    }
    ((uint4*)h)[i] = hv;
    ((uint4*)l)[i] = lv;
}

__global__ __launch_bounds__(256) void split_w_kernel(P4 srcs,
                                                      unsigned* __restrict__ hbase,
                                                      unsigned* __restrict__ lbase)
{
    const float* src = srcs.p[blockIdx.z];
    unsigned* h = hbase + ACT_ELEMS + (size_t)blockIdx.z * W_ELEMS;
    unsigned* l = lbase + ACT_ELEMS + (size_t)blockIdx.z * W_ELEMS;
    int i = blockIdx.x * blockDim.x + threadIdx.x;
    float4 v = ((const float4*)src)[i];
    float f[4] = {v.x, v.y, v.z, v.w};
    uint4 hv, lv;
    unsigned* hp = &hv.x;
    unsigned* lp = &lv.x;
#pragma unroll
    for (int e = 0; e < 4; e++) {
        unsigned hb = f2tf32(f[e]);
        hp[e] = hb;
        lp[e] = f2tf32(f[e] - __uint_as_float(hb));
    }
    ((uint4*)h)[i] = hv;
    ((uint4*)l)[i] = lv;
}

// ---------------------------------------------------------------------------
// 3xTF32 GEMM, pre-split inputs, 3-stage cp.async pipeline, optional fused RoPE
// ---------------------------------------------------------------------------
#define GBK 16
#define ASTRIDE 20
#define BSTRIDE 136
#define SA_WORDS (128 * ASTRIDE)
#define SB_WORDS (GBK * BSTRIDE)
#define GEMM_SMEM_WORDS (3 * 2 * (SA_WORDS + SB_WORDS))
#define GEMM_SMEM_BYTES (GEMM_SMEM_WORDS * 4)

__device__ __forceinline__ void gemm3_body(const unsigned* __restrict__ Agh,
                                           const unsigned* __restrict__ Agl,
                                           const unsigned* __restrict__ Bgh,
                                           const unsigned* __restrict__ Bgl,
                                           float* __restrict__ C,
                                           bool do_rope,
                                           const float* __restrict__ cos_t,
                                           const float* __restrict__ sin_t,
                                           const int* __restrict__ pos)
{
    extern __shared__ unsigned sm[];
    unsigned* uAh = sm;
    unsigned* uAl = sm + 3 * SA_WORDS;
    unsigned* uBh = sm + 6 * SA_WORDS;
    unsigned* uBl = uBh + 3 * SB_WORDS;

    const int tid = threadIdx.x;
    const int lane = tid & 31;
    const int warp = tid >> 5;
    const int wm = warp >> 1;
    const int wn = warp & 1;
    const int bx = blockIdx.x, by = blockIdx.y;

    float acc[2][8][4];
#pragma unroll
    for (int mt = 0; mt < 2; mt++)
#pragma unroll
        for (int nt = 0; nt < 8; nt++)
#pragma unroll
            for (int e = 0; e < 4; e++) acc[mt][nt][e] = 0.f;

    auto load_stage = [&](int st, int k0) {
        unsigned* ah = uAh + st * SA_WORDS;
        unsigned* al = uAl + st * SA_WORDS;
        unsigned* bh = uBh + st * SB_WORDS;
        unsigned* bl = uBl + st * SB_WORDS;
#pragma unroll
        for (int it = 0; it < 2; it++) {
            int idx = tid + it * 256;
            int m = idx >> 2, kq = (idx & 3) << 2;
            size_t ga = (size_t)(by * 128 + m) * DMODEL + k0 + kq;
            cpa16(ah + m * ASTRIDE + kq, Agh + ga);
            cpa16(al + m * ASTRIDE + kq, Agl + ga);
            int kk = idx >> 5, nq = (idx & 31) << 2;
            size_t gb = (size_t)(k0 + kk) * DMODEL + bx * 128 + nq;
            cpa16(bh + kk * BSTRIDE + nq, Bgh + gb);
            cpa16(bl + kk * BSTRIDE + nq, Bgl + gb);
        }
    };

    load_stage(0, 0);
    asm volatile("cp.async.commit_group;");
    load_stage(1, GBK);
    asm volatile("cp.async.commit_group;");

    const int NT = DMODEL / GBK;
#pragma unroll 1
    for (int i = 0; i < NT; i++) {
        int st = i % 3;
        asm volatile("cp.async.wait_group 1;");
        __syncthreads();

        unsigned* ah_s = uAh + st * SA_WORDS;
        unsigned* al_s = uAl + st * SA_WORDS;
        unsigned* bh_s = uBh + st * SB_WORDS;
        unsigned* bl_s = uBl + st * SB_WORDS;

#pragma unroll
        for (int ks = 0; ks < GBK; ks += 8) {
            unsigned ah[2][4], al[2][4];
#pragma unroll
            for (int mt = 0; mt < 2; mt++) {
                int r = wm * 32 + mt * 16 + (lane >> 2);
                int c = ks + (lane & 3);
                ah[mt][0] = ah_s[r * ASTRIDE + c];
                ah[mt][1] = ah_s[(r + 8) * ASTRIDE + c];
                ah[mt][2] = ah_s[r * ASTRIDE + c + 4];
                ah[mt][3] = ah_s[(r + 8) * ASTRIDE + c + 4];
                al[mt][0] = al_s[r * ASTRIDE + c];
                al[mt][1] = al_s[(r + 8) * ASTRIDE + c];
                al[mt][2] = al_s[r * ASTRIDE + c + 4];
                al[mt][3] = al_s[(r + 8) * ASTRIDE + c + 4];
            }
#pragma unroll
            for (int nt = 0; nt < 8; nt++) {
                int n = wn * 64 + nt * 8 + (lane >> 2);
                int k = ks + (lane & 3);
                unsigned bh[2], bl[2];
                bh[0] = bh_s[k * BSTRIDE + n];
                bh[1] = bh_s[(k + 4) * BSTRIDE + n];
                bl[0] = bl_s[k * BSTRIDE + n];
                bl[1] = bl_s[(k + 4) * BSTRIDE + n];
#pragma unroll
                for (int mt = 0; mt < 2; mt++) {
                    mma_tf32(acc[mt][nt], ah[mt], bh);
                    mma_tf32(acc[mt][nt], ah[mt], bl);
                    mma_tf32(acc[mt][nt], al[mt], bh);
                }
            }
        }

        if (i + 2 < NT) load_stage((i + 2) % 3, (i + 2) * GBK);
        asm volatile("cp.async.commit_group;");
    }

    if (do_rope) {
#pragma unroll
        for (int mt = 0; mt < 2; mt++) {
            int r0 = by * 128 + wm * 32 + mt * 16 + (lane >> 2);
            int p0 = __ldg(pos + r0);
            int p1 = __ldg(pos + r0 + 8);
#pragma unroll
            for (int nt = 0; nt < 4; nt++) {
#pragma unroll
                for (int e = 0; e < 2; e++) {
                    int d = nt * 8 + 2 * (lane & 3) + e;
                    {
                        float c0 = __ldg(cos_t + p0 * HDIM + d);
                        float s0 = __ldg(sin_t + p0 * HDIM + d);
                        float c1 = __ldg(cos_t + p0 * HDIM + d + 32);
                        float s1 = __ldg(sin_t + p0 * HDIM + d + 32);
                        float x0 = acc[mt][nt][e];
                        float x1 = acc[mt][nt + 4][e];
                        acc[mt][nt][e]     = x0 * c0 - x1 * s0;
                        acc[mt][nt + 4][e] = x1 * c1 + x0 * s1;
                    }
                    {
                        float c0 = __ldg(cos_t + p1 * HDIM + d);
                        float s0 = __ldg(sin_t + p1 * HDIM + d);
                        float c1 = __ldg(cos_t + p1 * HDIM + d + 32);
                        float s1 = __ldg(sin_t + p1 * HDIM + d + 32);
                        float x0 = acc[mt][nt][e + 2];
                        float x1 = acc[mt][nt + 4][e + 2];
                        acc[mt][nt][e + 2]     = x0 * c0 - x1 * s0;
                        acc[mt][nt + 4][e + 2] = x1 * c1 + x0 * s1;
                    }
                }
            }
        }
    }

#pragma unroll
    for (int mt = 0; mt < 2; mt++) {
        int r0 = by * 128 + wm * 32 + mt * 16 + (lane >> 2);
#pragma unroll
        for (int nt = 0; nt < 8; nt++) {
            int c = bx * 128 + wn * 64 + nt * 8 + ((lane & 3) << 1);
            *(float2*)(C + (size_t)r0 * DMODEL + c) =
                make_float2(acc[mt][nt][0], acc[mt][nt][1]);
            *(float2*)(C + (size_t)(r0 + 8) * DMODEL + c) =
                make_float2(acc[mt][nt][2], acc[mt][nt][3]);
        }
    }
}

__global__ __launch_bounds__(256, 1) void proj_kernel(const float* __restrict__ cos_t,
                                                      const float* __restrict__ sin_t,
                                                      const int* __restrict__ pos)
{
    int z = blockIdx.z;   // 0=Q(rope) 1=K(rope) 2=V
    gemm3_body(g_Sh, g_Sl,
               g_Sh + ACT_ELEMS + (size_t)z * W_ELEMS,
               g_Sl + ACT_ELEMS + (size_t)z * W_ELEMS,
               g_P + (size_t)z * ACT_ELEMS,
               z < 2, cos_t, sin_t, pos);
}

__global__ __launch_bounds__(256, 1) void out_gemm_kernel(float* __restrict__ out)
{
    gemm3_body(g_Sh, g_Sl,
               g_Sh + ACT_ELEMS + (size_t)3 * W_ELEMS,
               g_Sl + ACT_ELEMS + (size_t)3 * W_ELEMS,
               out, false, nullptr, nullptr, nullptr);
}

// ---------------------------------------------------------------------------
// KG/VG rows 0..3 only, split-K parallel.
// stage 1: grid (4 colblk, 32 ksplit) x 256 thr; each thread 1 col, 32 ks.
// ---------------------------------------------------------------------------
__global__ __launch_bounds__(256) void kgvg_part_kernel(const float* __restrict__ x,
                                                        const float* __restrict__ Wkg,
                                                        const float* __restrict__ Wvg)
{
    const int d = blockIdx.x * 256 + threadIdx.x;
    const int kz = blockIdx.y;
    __shared__ float xs[NGLOB][32];
    if (threadIdx.x < NGLOB * 32) {
        int t = threadIdx.x >> 5, k = threadIdx.x & 31;
        xs[t][k] = x[(size_t)t * DMODEL + kz * 32 + k];
    }
    __syncthreads();

    float ak[NGLOB] = {0.f, 0.f, 0.f, 0.f};
    float av[NGLOB] = {0.f, 0.f, 0.f, 0.f};
#pragma unroll 4
    for (int kk = 0; kk < 32; kk++) {
        size_t row = (size_t)(kz * 32 + kk) * DMODEL + d;
        float wk = __ldg(Wkg + row);
        float wv = __ldg(Wvg + row);
#pragma unroll
        for (int t = 0; t < NGLOB; t++) {
            ak[t] = fmaf(xs[t][kk], wk, ak[t]);
            av[t] = fmaf(xs[t][kk], wv, av[t]);
        }
    }
#pragma unroll
    for (int t = 0; t < NGLOB; t++) {
        g_KVGp[kz][0][t][d] = ak[t];
        g_KVGp[kz][1][t][d] = av[t];
    }
}

// stage 2: reduce 32 partials -> g_P slots 3 (KG) and 4 (VG)
__global__ __launch_bounds__(256) void kgvg_reduce_kernel()
{
    int idx = blockIdx.x * 256 + threadIdx.x;     // 2*4*1024 = 8192
    int d = idx & (DMODEL - 1);
    int t = (idx >> 10) & 3;
    int m = idx >> 12;
    float s = 0.f;
#pragma unroll
    for (int kz = 0; kz < KGVG_KSPLIT; kz++) s += g_KVGp[kz][m][t][d];
    g_P[(size_t)(3 + m) * ACT_ELEMS + (size_t)t * DMODEL + d] = s;
}

// ---------------------------------------------------------------------------
// Block-tiled MMA flash attention (unchanged)
// ---------------------------------------------------------------------------
#define KSTR 68
#define VSTR 72
#define PSTR 68
#define OFF_KH 0
#define OFF_KL (OFF_KH + 64 * KSTR)
#define OFF_VH (OFF_KL + 64 * KSTR)
#define OFF_VL (OFF_VH + 64 * VSTR)
#define OFF_PH (OFF_VL + 64 * VSTR)
#define OFF_PL (OFF_PH + 64 * PSTR)
#define OFF_VG (OFF_PL + 64 * PSTR)
#define ATT_SMEM_WORDS (OFF_VG + HDIM)

__global__ __launch_bounds__(128, 2) void attn_kernel()
{
    extern __shared__ unsigned smem_u[];
    unsigned* Kh = smem_u + OFF_KH;
    unsigned* Kl = smem_u + OFF_KL;
    unsigned* Vh = smem_u + OFF_VH;
    unsigned* Vl = smem_u + OFF_VL;
    unsigned* Ph = smem_u + OFF_PH;
    unsigned* Pl = smem_u + OFF_PL;
    float*    Vg4 = (float*)(smem_u + OFF_VG);

    const int h  = blockIdx.x;
    const int i0 = blockIdx.y * 64;
    const int tid = threadIdx.x;
    const int lane = tid & 31;
    const int wq = tid >> 5;

    const float* Q = g_P;
    const float* K = g_P + (size_t)1 * ACT_ELEMS;
    const float* V = g_P + (size_t)2 * ACT_ELEMS;

    if (tid < HDIM) {
        const float* vb = V + h * HDIM + tid;
        Vg4[tid] = vb[0] + vb[DMODEL] + vb[2 * DMODEL] + vb[3 * DMODEL];
    }

    unsigned qh[8][4], ql[8][4];
    {
        const int r0 = i0 + wq * 16 + (lane >> 2);
#pragma unroll
        for (int ks = 0; ks < 8; ks++) {
            int c = h * HDIM + ks * 8 + (lane & 3);
            float f[4];
            f[0] = Q[(size_t)r0 * DMODEL + c];
            f[1] = Q[(size_t)(r0 + 8) * DMODEL + c];
            f[2] = Q[(size_t)r0 * DMODEL + c + 4];
            f[3] = Q[(size_t)(r0 + 8) * DMODEL + c + 4];
#pragma unroll
            for (int e = 0; e < 4; e++) {
                unsigned hi = f2tf32(f[e]);
                qh[ks][e] = hi;
                ql[ks][e] = f2tf32(f[e] - __uint_as_float(hi));
            }
        }
    }

    float out[8][4];
#pragma unroll
    for (int nt = 0; nt < 8; nt++)
#pragma unroll
        for (int e = 0; e < 4; e++) out[nt][e] = 0.f;
    float m0 = -3.4e38f, m1 = -3.4e38f, sum0 = 0.f, sum1 = 0.f;

    const int j_start = (i0 - RADIUS) > 0 ? (i0 - RADIUS) : 0;

    for (int jc = j_start; jc < i0 + 64; jc += 64) {
        __syncthreads();
#pragma unroll
        for (int it = 0; it < 8; it++) {
            int idx = it * 128 + tid;
            int key = idx >> 4;
            int dq = (idx & 15) << 2;
            size_t gofs = (size_t)(jc + key) * DMODEL + h * HDIM + dq;
            float4 kv = *(const float4*)(K + gofs);
            float4 vv = *(const float4*)(V + gofs);
            float kf[4] = {kv.x, kv.y, kv.z, kv.w};
            float vf[4] = {vv.x, vv.y, vv.z, vv.w};
#pragma unroll
            for (int e = 0; e < 4; e++) {
                unsigned hk = f2tf32(kf[e]);
                Kh[key * KSTR + dq + e] = hk;
                Kl[key * KSTR + dq + e] = f2tf32(kf[e] - __uint_as_float(hk));
                unsigned hv = f2tf32(vf[e]);
                Vh[key * VSTR + dq + e] = hv;
                Vl[key * VSTR + dq + e] = f2tf32(vf[e] - __uint_as_float(hv));
            }
        }
        __syncthreads();

        float sc[8][4];
#pragma unroll
        for (int nt = 0; nt < 8; nt++)
#pragma unroll
            for (int e = 0; e < 4; e++) sc[nt][e] = 0.f;

#pragma unroll
        for (int ks = 0; ks < 8; ks++) {
#pragma unroll
            for (int nt = 0; nt < 8; nt++) {
                int n = nt * 8 + (lane >> 2);
                int k = ks * 8 + (lane & 3);
                unsigned bh[2], bl[2];
                bh[0] = Kh[n * KSTR + k];
                bh[1] = Kh[n * KSTR + k + 4];
                bl[0] = Kl[n * KSTR + k];
                bl[1] = Kl[n * KSTR + k + 4];
                mma_tf32(sc[nt], qh[ks], bh);
                mma_tf32(sc[nt], qh[ks], bl);
                mma_tf32(sc[nt], ql[ks], bh);
            }
        }

        const int ibase = i0 + wq * 16 + (lane >> 2);
        float mn0 = m0, mn1 = m1;
#pragma unroll
        for (int nt = 0; nt < 8; nt++) {
#pragma unroll
            for (int e = 0; e < 4; e++) {
                int i = ibase + ((e & 2) ? 8 : 0);
                int j = jc + nt * 8 + 2 * (lane & 3) + (e & 1);
                bool inw = (j <= i) && (i - j <= RADIUS);
                float raw = sc[nt][e] * 0.125f;
                float s;
                if (j < NGLOB) s = inw ? (raw + 1e9f) : 0.f;
                else           s = inw ? raw : -3.0e38f;
                sc[nt][e] = s;
                if (e & 2) mn1 = fmaxf(mn1, s); else mn0 = fmaxf(mn0, s);
            }
        }
#pragma unroll
        for (int o = 1; o < 4; o <<= 1) {
            mn0 = fmaxf(mn0, __shfl_xor_sync(0xffffffff, mn0, o));
            mn1 = fmaxf(mn1, __shfl_xor_sync(0xffffffff, mn1, o));
        }
        float esc0 = __expf(m0 - mn0);
        float esc1 = __expf(m1 - mn1);
        m0 = mn0; m1 = mn1;

        float ps0 = 0.f, ps1 = 0.f;
#pragma unroll
        for (int nt = 0; nt < 8; nt++) {
#pragma unroll
            for (int e = 0; e < 4; e++) {
                float p = __expf(sc[nt][e] - ((e & 2) ? m1 : m0));
                sc[nt][e] = p;
                if (e & 2) ps1 += p; else ps0 += p;
            }
        }
#pragma unroll
        for (int o = 1; o < 4; o <<= 1) {
            ps0 += __shfl_xor_sync(0xffffffff, ps0, o);
            ps1 += __shfl_xor_sync(0xffffffff, ps1, o);
        }
        sum0 = sum0 * esc0 + ps0;
        sum1 = sum1 * esc1 + ps1;
#pragma unroll
        for (int nt = 0; nt < 8; nt++) {
            out[nt][0] *= esc0; out[nt][1] *= esc0;
            out[nt][2] *= esc1; out[nt][3] *= esc1;
        }

#pragma unroll
        for (int nt = 0; nt < 8; nt++) {
#pragma unroll
            for (int e = 0; e < 4; e++) {
                int row = wq * 16 + (lane >> 2) + ((e & 2) ? 8 : 0);
                int col = nt * 8 + 2 * (lane & 3) + (e & 1);
                float p = sc[nt][e];
                unsigned hp = f2tf32(p);
                Ph[row * PSTR + col] = hp;
                Pl[row * PSTR + col] = f2tf32(p - __uint_as_float(hp));
            }
        }
        __syncwarp();

#pragma unroll
        for (int ks = 0; ks < 8; ks++) {
            int r = wq * 16 + (lane >> 2);
            int c = ks * 8 + (lane & 3);
            unsigned pah[4], pal[4];
            pah[0] = Ph[r * PSTR + c];
            pah[1] = Ph[(r + 8) * PSTR + c];
            pah[2] = Ph[r * PSTR + c + 4];
            pah[3] = Ph[(r + 8) * PSTR + c + 4];
            pal[0] = Pl[r * PSTR + c];
            pal[1] = Pl[(r + 8) * PSTR + c];
            pal[2] = Pl[r * PSTR + c + 4];
            pal[3] = Pl[(r + 8) * PSTR + c + 4];
#pragma unroll
            for (int nt = 0; nt < 8; nt++) {
                int k = ks * 8 + (lane & 3);
                int n = nt * 8 + (lane >> 2);
                unsigned vbh[2], vbl[2];
                vbh[0] = Vh[k * VSTR + n];
                vbh[1] = Vh[(k + 4) * VSTR + n];
                vbl[0] = Vl[k * VSTR + n];
                vbl[1] = Vl[(k + 4) * VSTR + n];
                mma_tf32(out[nt], pah, vbh);
                mma_tf32(out[nt], pah, vbl);
                mma_tf32(out[nt], pal, vbh);
            }
        }
        __syncwarp();
    }

    if (j_start > 0) {
        float mn0 = fmaxf(m0, 0.f), mn1 = fmaxf(m1, 0.f);
        float esc0 = __expf(m0 - mn0), esc1 = __expf(m1 - mn1);
        float e0 = __expf(0.f - mn0), e1 = __expf(0.f - mn1);
        sum0 = sum0 * esc0 + 4.f * e0;
        sum1 = sum1 * esc1 + 4.f * e1;
#pragma unroll
        for (int nt = 0; nt < 8; nt++) {
            int col = nt * 8 + 2 * (lane & 3);
            out[nt][0] = out[nt][0] * esc0 + e0 * Vg4[col];
            out[nt][1] = out[nt][1] * esc0 + e0 * Vg4[col + 1];
            out[nt][2] = out[nt][2] * esc1 + e1 * Vg4[col];
            out[nt][3] = out[nt][3] * esc1 + e1 * Vg4[col + 1];
        }
    }

    float inv0 = 1.f / sum0, inv1 = 1.f / sum1;
    const int r0 = i0 + wq * 16 + (lane >> 2);
#pragma unroll
    for (int nt = 0; nt < 8; nt++) {
        int cb = h * HDIM + nt * 8 + 2 * (lane & 3);
        *(float2*)(g_O + (size_t)r0 * DMODEL + cb) =
            make_float2(out[nt][0] * inv0, out[nt][1] * inv0);
        *(float2*)(g_O + (size_t)(r0 + 8) * DMODEL + cb) =
            make_float2(out[nt][2] * inv1, out[nt][3] * inv1);
    }
}

// ---------------------------------------------------------------------------
// Global attention (KG/VG rows 0..3) — adds into g_O. Warp per (i, h).
// ---------------------------------------------------------------------------
__global__ __launch_bounds__(128) void global_attn_kernel()
{
    int warp = (blockIdx.x * blockDim.x + threadIdx.x) >> 5;
    int lane = threadIdx.x & 31;
    int h = warp & (NHEADS - 1);
    int i = warp >> 4;
    if (i >= S_LEN) return;

    const float scale = 0.125f;
    const float* Q  = g_P;
    const float* KG = g_P + (size_t)3 * ACT_ELEMS;
    const float* VG = g_P + (size_t)4 * ACT_ELEMS;

    const float* qp = Q + (size_t)i * DMODEL + h * HDIM;
    float q0 = qp[lane], q1 = qp[lane + 32];

    float sg[NGLOB];
    float mg = -3.4e38f;
#pragma unroll
    for (int t = 0; t < NGLOB; t++) {
        const float* kp = KG + (size_t)t * DMODEL + h * HDIM;
        float p = q0 * kp[lane] + q1 * kp[lane + 32];
#pragma unroll
        for (int o = 16; o > 0; o >>= 1) p += __shfl_xor_sync(0xffffffff, p, o);
        sg[t] = p * scale;
        mg = fmaxf(mg, sg[t]);
    }
    float den = 0.f, gsum0 = 0.f, gsum1 = 0.f;
#pragma unroll
    for (int t = 0; t < NGLOB; t++) {
        float e = __expf(sg[t] - mg);
        const float* vp = VG + (size_t)t * DMODEL + h * HDIM;
        den += e;
        gsum0 += e * vp[lane];
        gsum1 += e * vp[lane + 32];
    }
    float ginv = 1.f / den;

    float* op = g_O + (size_t)i * DMODEL + h * HDIM;
    op[lane]      += gsum0 * ginv;
    op[lane + 32] += gsum1 * ginv;
}

// ---------------------------------------------------------------------------
// launch
// ---------------------------------------------------------------------------
extern "C" void kernel_launch(void* const* d_in, const int* in_sizes, int n_in,
                              void* d_out, int out_size)
{
    const float* x     = (const float*)d_in[0];
    const float* cos_t = (const float*)d_in[1];
    const float* sin_t = (const float*)d_in[2];
    const int*   pos   = (const int*)d_in[3];
    P4 ws;
    ws.p[0] = (const float*)d_in[4];    // Wqs
    ws.p[1] = (const float*)d_in[5];    // Wks
    ws.p[2] = (const float*)d_in[6];    // Wvs
    ws.p[3] = (const float*)d_in[10];   // Wo
    const float* Wkg = (const float*)d_in[8];
    const float* Wvg = (const float*)d_in[9];
    float* out = (float*)d_out;

    static int attrs_set = 0;
    int attn_smem = ATT_SMEM_WORDS * 4;
    if (!attrs_set) {
        cudaFuncSetAttribute(attn_kernel,
                             cudaFuncAttributeMaxDynamicSharedMemorySize, attn_smem);
        cudaFuncSetAttribute(proj_kernel,
                             cudaFuncAttributeMaxDynamicSharedMemorySize, GEMM_SMEM_BYTES);
        cudaFuncSetAttribute(out_gemm_kernel,
                             cudaFuncAttributeMaxDynamicSharedMemorySize, GEMM_SMEM_BYTES);
        attrs_set = 1;
    }

    unsigned* Sh;
    unsigned* Sl;
    cudaGetSymbolAddress((void**)&Sh, g_Sh);
    cudaGetSymbolAddress((void**)&Sl, g_Sl);

    split_kernel<<<(ACT_ELEMS / 4 + 255) / 256, 256>>>(x, Sh, Sl, ACT_ELEMS / 4);
    dim3 gw(W_ELEMS / 4 / 256, 1, 4);
    split_w_kernel<<<gw, 256>>>(ws, Sh, Sl);

    dim3 gkg(DMODEL / 256, KGVG_KSPLIT);
    kgvg_part_kernel<<<gkg, 256>>>(x, Wkg, Wvg);
    kgvg_reduce_kernel<<<(2 * NGLOB * DMODEL) / 256, 256>>>();

    dim3 gp(DMODEL / 128, S_LEN / 128, 3);
    proj_kernel<<<gp, 256, GEMM_SMEM_BYTES>>>(cos_t, sin_t, pos);

    dim3 ga(NHEADS, S_LEN / 64);
    attn_kernel<<<ga, 128, attn_smem>>>();

    global_attn_kernel<<<(S_LEN * NHEADS) / 4, 128>>>();

    float* gO;
    cudaGetSymbolAddress((void**)&gO, g_O);
    split_kernel<<<(ACT_ELEMS / 4 + 255) / 256, 256>>>(gO, Sh, Sl, ACT_ELEMS / 4);

    dim3 go(DMODEL / 128, S_LEN / 128);
    out_gemm_kernel<<<go, 256, GEMM_SMEM_BYTES>>>(out);
}

// round 7
// speedup vs baseline: 1.6154x; 1.0961x over previous
#include <cuda_runtime.h>
#include <math.h>

#define S_LEN 2048
#define DMODEL 1024
#define NHEADS 16
#define HDIM 64
#define RADIUS 256
#define NGLOB 4

__device__ float g_P[(size_t)5 * S_LEN * DMODEL];

// kgvg split-K partials: [32 ksplits][2 mats][4 rows][1024 cols]
#define KGVG_KSPLIT 32
__device__ float g_KVGp[KGVG_KSPLIT][2][NGLOB][DMODEL];

// pre-split tf32 hi/lo: [0:ACT) activations, then 4 weights (Wqs,Wks,Wvs,Wo)
#define ACT_ELEMS (S_LEN * DMODEL)
#define W_ELEMS   (DMODEL * DMODEL)
__device__ unsigned g_Sh[(size_t)ACT_ELEMS + 4 * W_ELEMS];
__device__ unsigned g_Sl[(size_t)ACT_ELEMS + 4 * W_ELEMS];

struct P4 { const float* p[4]; };

__device__ __forceinline__ unsigned f2tf32(float x) {
    unsigned r;
    asm("cvt.rna.tf32.f32 %0, %1;" : "=r"(r) : "f"(x));
    return r;
}

__device__ __forceinline__ void mma_tf32(float* c, const unsigned* a, const unsigned* b) {
    asm volatile(
        "mma.sync.aligned.m16n8k8.row.col.f32.tf32.tf32.f32 "
        "{%0,%1,%2,%3}, {%4,%5,%6,%7}, {%8,%9}, {%0,%1,%2,%3};"
        : "+f"(c[0]), "+f"(c[1]), "+f"(c[2]), "+f"(c[3])
        : "r"(a[0]), "r"(a[1]), "r"(a[2]), "r"(a[3]), "r"(b[0]), "r"(b[1]));
}

__device__ __forceinline__ void cpa16(unsigned* dst, const unsigned* src) {
    unsigned s = (unsigned)__cvta_generic_to_shared(dst);
    asm volatile("cp.async.cg.shared.global [%0], [%1], 16;" :: "r"(s), "l"(src));
}

// ---------------------------------------------------------------------------
// split kernels: fp32 -> (tf32 hi, tf32 lo)
// ---------------------------------------------------------------------------
__global__ __launch_bounds__(256) void split_kernel(const float* __restrict__ src,
                                                    unsigned* __restrict__ h,
                                                    unsigned* __restrict__ l, int n4)
{
    int i = blockIdx.x * blockDim.x + threadIdx.x;
    if (i >= n4) return;
    float4 v = ((const float4*)src)[i];
    float f[4] = {v.x, v.y, v.z, v.w};
    uint4 hv, lv;
    unsigned* hp = &hv.x;
    unsigned* lp = &lv.x;
#pragma unroll
    for (int e = 0; e < 4; e++) {
        unsigned hb = f2tf32(f[e]);
        hp[e] = hb;
        lp[e] = f2tf32(f[e] - __uint_as_float(hb));
    }
    ((uint4*)h)[i] = hv;
    ((uint4*)l)[i] = lv;
}

__global__ __launch_bounds__(256) void split_w_kernel(P4 srcs,
                                                      unsigned* __restrict__ hbase,
                                                      unsigned* __restrict__ lbase)
{
    const float* src = srcs.p[blockIdx.z];
    unsigned* h = hbase + ACT_ELEMS + (size_t)blockIdx.z * W_ELEMS;
    unsigned* l = lbase + ACT_ELEMS + (size_t)blockIdx.z * W_ELEMS;
    int i = blockIdx.x * blockDim.x + threadIdx.x;
    float4 v = ((const float4*)src)[i];
    float f[4] = {v.x, v.y, v.z, v.w};
    uint4 hv, lv;
    unsigned* hp = &hv.x;
    unsigned* lp = &lv.x;
#pragma unroll
    for (int e = 0; e < 4; e++) {
        unsigned hb = f2tf32(f[e]);
        hp[e] = hb;
        lp[e] = f2tf32(f[e] - __uint_as_float(hb));
    }
    ((uint4*)h)[i] = hv;
    ((uint4*)l)[i] = lv;
}

// ---------------------------------------------------------------------------
// 3xTF32 GEMM, pre-split inputs, 3-stage cp.async pipeline, optional fused RoPE
// ---------------------------------------------------------------------------
#define GBK 16
#define ASTRIDE 20
#define BSTRIDE 136
#define SA_WORDS (128 * ASTRIDE)
#define SB_WORDS (GBK * BSTRIDE)
#define GEMM_SMEM_WORDS (3 * 2 * (SA_WORDS + SB_WORDS))
#define GEMM_SMEM_BYTES (GEMM_SMEM_WORDS * 4)

__device__ __forceinline__ void gemm3_body(const unsigned* __restrict__ Agh,
                                           const unsigned* __restrict__ Agl,
                                           const unsigned* __restrict__ Bgh,
                                           const unsigned* __restrict__ Bgl,
                                           float* __restrict__ C,
                                           bool do_rope,
                                           const float* __restrict__ cos_t,
                                           const float* __restrict__ sin_t,
                                           const int* __restrict__ pos)
{
    extern __shared__ unsigned sm[];
    unsigned* uAh = sm;
    unsigned* uAl = sm + 3 * SA_WORDS;
    unsigned* uBh = sm + 6 * SA_WORDS;
    unsigned* uBl = uBh + 3 * SB_WORDS;

    const int tid = threadIdx.x;
    const int lane = tid & 31;
    const int warp = tid >> 5;
    const int wm = warp >> 1;
    const int wn = warp & 1;
    const int bx = blockIdx.x, by = blockIdx.y;

    float acc[2][8][4];
#pragma unroll
    for (int mt = 0; mt < 2; mt++)
#pragma unroll
        for (int nt = 0; nt < 8; nt++)
#pragma unroll
            for (int e = 0; e < 4; e++) acc[mt][nt][e] = 0.f;

    auto load_stage = [&](int st, int k0) {
        unsigned* ah = uAh + st * SA_WORDS;
        unsigned* al = uAl + st * SA_WORDS;
        unsigned* bh = uBh + st * SB_WORDS;
        unsigned* bl = uBl + st * SB_WORDS;
#pragma unroll
        for (int it = 0; it < 2; it++) {
            int idx = tid + it * 256;
            int m = idx >> 2, kq = (idx & 3) << 2;
            size_t ga = (size_t)(by * 128 + m) * DMODEL + k0 + kq;
            cpa16(ah + m * ASTRIDE + kq, Agh + ga);
            cpa16(al + m * ASTRIDE + kq, Agl + ga);
            int kk = idx >> 5, nq = (idx & 31) << 2;
            size_t gb = (size_t)(k0 + kk) * DMODEL + bx * 128 + nq;
            cpa16(bh + kk * BSTRIDE + nq, Bgh + gb);
            cpa16(bl + kk * BSTRIDE + nq, Bgl + gb);
        }
    };

    load_stage(0, 0);
    asm volatile("cp.async.commit_group;");
    load_stage(1, GBK);
    asm volatile("cp.async.commit_group;");

    const int NT = DMODEL / GBK;
#pragma unroll 1
    for (int i = 0; i < NT; i++) {
        int st = i % 3;
        asm volatile("cp.async.wait_group 1;");
        __syncthreads();

        unsigned* ah_s = uAh + st * SA_WORDS;
        unsigned* al_s = uAl + st * SA_WORDS;
        unsigned* bh_s = uBh + st * SB_WORDS;
        unsigned* bl_s = uBl + st * SB_WORDS;

#pragma unroll
        for (int ks = 0; ks < GBK; ks += 8) {
            unsigned ah[2][4], al[2][4];
#pragma unroll
            for (int mt = 0; mt < 2; mt++) {
                int r = wm * 32 + mt * 16 + (lane >> 2);
                int c = ks + (lane & 3);
                ah[mt][0] = ah_s[r * ASTRIDE + c];
                ah[mt][1] = ah_s[(r + 8) * ASTRIDE + c];
                ah[mt][2] = ah_s[r * ASTRIDE + c + 4];
                ah[mt][3] = ah_s[(r + 8) * ASTRIDE + c + 4];
                al[mt][0] = al_s[r * ASTRIDE + c];
                al[mt][1] = al_s[(r + 8) * ASTRIDE + c];
                al[mt][2] = al_s[r * ASTRIDE + c + 4];
                al[mt][3] = al_s[(r + 8) * ASTRIDE + c + 4];
            }
#pragma unroll
            for (int nt = 0; nt < 8; nt++) {
                int n = wn * 64 + nt * 8 + (lane >> 2);
                int k = ks + (lane & 3);
                unsigned bh[2], bl[2];
                bh[0] = bh_s[k * BSTRIDE + n];
                bh[1] = bh_s[(k + 4) * BSTRIDE + n];
                bl[0] = bl_s[k * BSTRIDE + n];
                bl[1] = bl_s[(k + 4) * BSTRIDE + n];
#pragma unroll
                for (int mt = 0; mt < 2; mt++) {
                    mma_tf32(acc[mt][nt], ah[mt], bh);
                    mma_tf32(acc[mt][nt], ah[mt], bl);
                    mma_tf32(acc[mt][nt], al[mt], bh);
                }
            }
        }

        if (i + 2 < NT) load_stage((i + 2) % 3, (i + 2) * GBK);
        asm volatile("cp.async.commit_group;");
    }

    if (do_rope) {
#pragma unroll
        for (int mt = 0; mt < 2; mt++) {
            int r0 = by * 128 + wm * 32 + mt * 16 + (lane >> 2);
            int p0 = __ldg(pos + r0);
            int p1 = __ldg(pos + r0 + 8);
#pragma unroll
            for (int nt = 0; nt < 4; nt++) {
#pragma unroll
                for (int e = 0; e < 2; e++) {
                    int d = nt * 8 + 2 * (lane & 3) + e;
                    {
                        float c0 = __ldg(cos_t + p0 * HDIM + d);
                        float s0 = __ldg(sin_t + p0 * HDIM + d);
                        float c1 = __ldg(cos_t + p0 * HDIM + d + 32);
                        float s1 = __ldg(sin_t + p0 * HDIM + d + 32);
                        float x0 = acc[mt][nt][e];
                        float x1 = acc[mt][nt + 4][e];
                        acc[mt][nt][e]     = x0 * c0 - x1 * s0;
                        acc[mt][nt + 4][e] = x1 * c1 + x0 * s1;
                    }
                    {
                        float c0 = __ldg(cos_t + p1 * HDIM + d);
                        float s0 = __ldg(sin_t + p1 * HDIM + d);
                        float c1 = __ldg(cos_t + p1 * HDIM + d + 32);
                        float s1 = __ldg(sin_t + p1 * HDIM + d + 32);
                        float x0 = acc[mt][nt][e + 2];
                        float x1 = acc[mt][nt + 4][e + 2];
                        acc[mt][nt][e + 2]     = x0 * c0 - x1 * s0;
                        acc[mt][nt + 4][e + 2] = x1 * c1 + x0 * s1;
                    }
                }
            }
        }
    }

#pragma unroll
    for (int mt = 0; mt < 2; mt++) {
        int r0 = by * 128 + wm * 32 + mt * 16 + (lane >> 2);
#pragma unroll
        for (int nt = 0; nt < 8; nt++) {
            int c = bx * 128 + wn * 64 + nt * 8 + ((lane & 3) << 1);
            *(float2*)(C + (size_t)r0 * DMODEL + c) =
                make_float2(acc[mt][nt][0], acc[mt][nt][1]);
            *(float2*)(C + (size_t)(r0 + 8) * DMODEL + c) =
                make_float2(acc[mt][nt][2], acc[mt][nt][3]);
        }
    }
}

// proj: 384 blocks -> 2 blocks/SM reachable; cap regs at 128.
__global__ __launch_bounds__(256, 2) void proj_kernel(const float* __restrict__ cos_t,
                                                      const float* __restrict__ sin_t,
                                                      const int* __restrict__ pos)
{
    int z = blockIdx.z;   // 0=Q(rope) 1=K(rope) 2=V
    gemm3_body(g_Sh, g_Sl,
               g_Sh + ACT_ELEMS + (size_t)z * W_ELEMS,
               g_Sl + ACT_ELEMS + (size_t)z * W_ELEMS,
               g_P + (size_t)z * ACT_ELEMS,
               z < 2, cos_t, sin_t, pos);
}

// out: 128 blocks < 148 SMs -> 2 blocks/SM unreachable; keep full regs.
__global__ __launch_bounds__(256, 1) void out_gemm_kernel(float* __restrict__ out)
{
    gemm3_body(g_Sh, g_Sl,
               g_Sh + ACT_ELEMS + (size_t)3 * W_ELEMS,
               g_Sl + ACT_ELEMS + (size_t)3 * W_ELEMS,
               out, false, nullptr, nullptr, nullptr);
}

// ---------------------------------------------------------------------------
// KG/VG rows 0..3 only, split-K parallel.
// ---------------------------------------------------------------------------
__global__ __launch_bounds__(256) void kgvg_part_kernel(const float* __restrict__ x,
                                                        const float* __restrict__ Wkg,
                                                        const float* __restrict__ Wvg)
{
    const int d = blockIdx.x * 256 + threadIdx.x;
    const int kz = blockIdx.y;
    __shared__ float xs[NGLOB][32];
    if (threadIdx.x < NGLOB * 32) {
        int t = threadIdx.x >> 5, k = threadIdx.x & 31;
        xs[t][k] = x[(size_t)t * DMODEL + kz * 32 + k];
    }
    __syncthreads();

    float ak[NGLOB] = {0.f, 0.f, 0.f, 0.f};
    float av[NGLOB] = {0.f, 0.f, 0.f, 0.f};
#pragma unroll 4
    for (int kk = 0; kk < 32; kk++) {
        size_t row = (size_t)(kz * 32 + kk) * DMODEL + d;
        float wk = __ldg(Wkg + row);
        float wv = __ldg(Wvg + row);
#pragma unroll
        for (int t = 0; t < NGLOB; t++) {
            ak[t] = fmaf(xs[t][kk], wk, ak[t]);
            av[t] = fmaf(xs[t][kk], wv, av[t]);
        }
    }
#pragma unroll
    for (int t = 0; t < NGLOB; t++) {
        g_KVGp[kz][0][t][d] = ak[t];
        g_KVGp[kz][1][t][d] = av[t];
    }
}

__global__ __launch_bounds__(256) void kgvg_reduce_kernel()
{
    int idx = blockIdx.x * 256 + threadIdx.x;
    int d = idx & (DMODEL - 1);
    int t = (idx >> 10) & 3;
    int m = idx >> 12;
    float s = 0.f;
#pragma unroll
    for (int kz = 0; kz < KGVG_KSPLIT; kz++) s += g_KVGp[kz][m][t][d];
    g_P[(size_t)(3 + m) * ACT_ELEMS + (size_t)t * DMODEL + d] = s;
}

// ---------------------------------------------------------------------------
// Block-tiled MMA flash attention + fused global attention + fused O split.
// Writes the tf32 hi/lo split of (out_local + out_global) directly to the
// activation region of g_Sh/g_Sl (consumed by out_gemm).
// ---------------------------------------------------------------------------
#define KSTR 68
#define VSTR 72
#define PSTR 68
#define OFF_KH 0
#define OFF_KL (OFF_KH + 64 * KSTR)
#define OFF_VH (OFF_KL + 64 * KSTR)
#define OFF_VL (OFF_VH + 64 * VSTR)
#define OFF_PH (OFF_VL + 64 * VSTR)
#define OFF_PL (OFF_PH + 64 * PSTR)
#define OFF_VG (OFF_PL + 64 * PSTR)
#define OFF_KG4 (OFF_VG + HDIM)
#define OFF_VG4 (OFF_KG4 + NGLOB * HDIM)
#define ATT_SMEM_WORDS (OFF_VG4 + NGLOB * HDIM)

__global__ __launch_bounds__(128, 2) void attn_kernel()
{
    extern __shared__ unsigned smem_u[];
    unsigned* Kh = smem_u + OFF_KH;
    unsigned* Kl = smem_u + OFF_KL;
    unsigned* Vh = smem_u + OFF_VH;
    unsigned* Vl = smem_u + OFF_VL;
    unsigned* Ph = smem_u + OFF_PH;
    unsigned* Pl = smem_u + OFF_PL;
    float*    Vg4 = (float*)(smem_u + OFF_VG);
    float*    KG4 = (float*)(smem_u + OFF_KG4);
    float*    VG4 = (float*)(smem_u + OFF_VG4);

    const int h  = blockIdx.x;
    const int i0 = blockIdx.y * 64;
    const int tid = threadIdx.x;
    const int lane = tid & 31;
    const int wq = tid >> 5;

    const float* Q = g_P;
    const float* K = g_P + (size_t)1 * ACT_ELEMS;
    const float* V = g_P + (size_t)2 * ACT_ELEMS;

    if (tid < HDIM) {
        const float* vb = V + h * HDIM + tid;
        Vg4[tid] = vb[0] + vb[DMODEL] + vb[2 * DMODEL] + vb[3 * DMODEL];
    }
    // stage KG/VG rows 0..3 for this head (512 floats)
    for (int i2 = tid; i2 < 2 * NGLOB * HDIM; i2 += 128) {
        int mm = i2 >> 8;
        int t = (i2 >> 6) & 3;
        int c = i2 & 63;
        float val = g_P[(size_t)(3 + mm) * ACT_ELEMS + (size_t)t * DMODEL + h * HDIM + c];
        (mm ? VG4 : KG4)[t * HDIM + c] = val;
    }

    unsigned qh[8][4], ql[8][4];
    {
        const int r0 = i0 + wq * 16 + (lane >> 2);
#pragma unroll
        for (int ks = 0; ks < 8; ks++) {
            int c = h * HDIM + ks * 8 + (lane & 3);
            float f[4];
            f[0] = Q[(size_t)r0 * DMODEL + c];
            f[1] = Q[(size_t)(r0 + 8) * DMODEL + c];
            f[2] = Q[(size_t)r0 * DMODEL + c + 4];
            f[3] = Q[(size_t)(r0 + 8) * DMODEL + c + 4];
#pragma unroll
            for (int e = 0; e < 4; e++) {
                unsigned hi = f2tf32(f[e]);
                qh[ks][e] = hi;
                ql[ks][e] = f2tf32(f[e] - __uint_as_float(hi));
            }
        }
    }

    float out[8][4];
#pragma unroll
    for (int nt = 0; nt < 8; nt++)
#pragma unroll
        for (int e = 0; e < 4; e++) out[nt][e] = 0.f;
    float m0 = -3.4e38f, m1 = -3.4e38f, sum0 = 0.f, sum1 = 0.f;

    const int j_start = (i0 - RADIUS) > 0 ? (i0 - RADIUS) : 0;

    for (int jc = j_start; jc < i0 + 64; jc += 64) {
        __syncthreads();
#pragma unroll
        for (int it = 0; it < 8; it++) {
            int idx = it * 128 + tid;
            int key = idx >> 4;
            int dq = (idx & 15) << 2;
            size_t gofs = (size_t)(jc + key) * DMODEL + h * HDIM + dq;
            float4 kv = *(const float4*)(K + gofs);
            float4 vv = *(const float4*)(V + gofs);
            float kf[4] = {kv.x, kv.y, kv.z, kv.w};
            float vf[4] = {vv.x, vv.y, vv.z, vv.w};
#pragma unroll
            for (int e = 0; e < 4; e++) {
                unsigned hk = f2tf32(kf[e]);
                Kh[key * KSTR + dq + e] = hk;
                Kl[key * KSTR + dq + e] = f2tf32(kf[e] - __uint_as_float(hk));
                unsigned hv = f2tf32(vf[e]);
                Vh[key * VSTR + dq + e] = hv;
                Vl[key * VSTR + dq + e] = f2tf32(vf[e] - __uint_as_float(hv));
            }
        }
        __syncthreads();

        float sc[8][4];
#pragma unroll
        for (int nt = 0; nt < 8; nt++)
#pragma unroll
            for (int e = 0; e < 4; e++) sc[nt][e] = 0.f;

#pragma unroll
        for (int ks = 0; ks < 8; ks++) {
#pragma unroll
            for (int nt = 0; nt < 8; nt++) {
                int n = nt * 8 + (lane >> 2);
                int k = ks * 8 + (lane & 3);
                unsigned bh[2], bl[2];
                bh[0] = Kh[n * KSTR + k];
                bh[1] = Kh[n * KSTR + k + 4];
                bl[0] = Kl[n * KSTR + k];
                bl[1] = Kl[n * KSTR + k + 4];
                mma_tf32(sc[nt], qh[ks], bh);
                mma_tf32(sc[nt], qh[ks], bl);
                mma_tf32(sc[nt], ql[ks], bh);
            }
        }

        const int ibase = i0 + wq * 16 + (lane >> 2);
        float mn0 = m0, mn1 = m1;
#pragma unroll
        for (int nt = 0; nt < 8; nt++) {
#pragma unroll
            for (int e = 0; e < 4; e++) {
                int i = ibase + ((e & 2) ? 8 : 0);
                int j = jc + nt * 8 + 2 * (lane & 3) + (e & 1);
                bool inw = (j <= i) && (i - j <= RADIUS);
                float raw = sc[nt][e] * 0.125f;
                float s;
                if (j < NGLOB) s = inw ? (raw + 1e9f) : 0.f;
                else           s = inw ? raw : -3.0e38f;
                sc[nt][e] = s;
                if (e & 2) mn1 = fmaxf(mn1, s); else mn0 = fmaxf(mn0, s);
            }
        }
#pragma unroll
        for (int o = 1; o < 4; o <<= 1) {
            mn0 = fmaxf(mn0, __shfl_xor_sync(0xffffffff, mn0, o));
            mn1 = fmaxf(mn1, __shfl_xor_sync(0xffffffff, mn1, o));
        }
        float esc0 = __expf(m0 - mn0);
        float esc1 = __expf(m1 - mn1);
        m0 = mn0; m1 = mn1;

        float ps0 = 0.f, ps1 = 0.f;
#pragma unroll
        for (int nt = 0; nt < 8; nt++) {
#pragma unroll
            for (int e = 0; e < 4; e++) {
                float p = __expf(sc[nt][e] - ((e & 2) ? m1 : m0));
                sc[nt][e] = p;
                if (e & 2) ps1 += p; else ps0 += p;
            }
        }
#pragma unroll
        for (int o = 1; o < 4; o <<= 1) {
            ps0 += __shfl_xor_sync(0xffffffff, ps0, o);
            ps1 += __shfl_xor_sync(0xffffffff, ps1, o);
        }
        sum0 = sum0 * esc0 + ps0;
        sum1 = sum1 * esc1 + ps1;
#pragma unroll
        for (int nt = 0; nt < 8; nt++) {
            out[nt][0] *= esc0; out[nt][1] *= esc0;
            out[nt][2] *= esc1; out[nt][3] *= esc1;
        }

#pragma unroll
        for (int nt = 0; nt < 8; nt++) {
#pragma unroll
            for (int e = 0; e < 4; e++) {
                int row = wq * 16 + (lane >> 2) + ((e & 2) ? 8 : 0);
                int col = nt * 8 + 2 * (lane & 3) + (e & 1);
                float p = sc[nt][e];
                unsigned hp = f2tf32(p);
                Ph[row * PSTR + col] = hp;
                Pl[row * PSTR + col] = f2tf32(p - __uint_as_float(hp));
            }
        }
        __syncwarp();

#pragma unroll
        for (int ks = 0; ks < 8; ks++) {
            int r = wq * 16 + (lane >> 2);
            int c = ks * 8 + (lane & 3);
            unsigned pah[4], pal[4];
            pah[0] = Ph[r * PSTR + c];
            pah[1] = Ph[(r + 8) * PSTR + c];
            pah[2] = Ph[r * PSTR + c + 4];
            pah[3] = Ph[(r + 8) * PSTR + c + 4];
            pal[0] = Pl[r * PSTR + c];
            pal[1] = Pl[(r + 8) * PSTR + c];
            pal[2] = Pl[r * PSTR + c + 4];
            pal[3] = Pl[(r + 8) * PSTR + c + 4];
#pragma unroll
            for (int nt = 0; nt < 8; nt++) {
                int k = ks * 8 + (lane & 3);
                int n = nt * 8 + (lane >> 2);
                unsigned vbh[2], vbl[2];
                vbh[0] = Vh[k * VSTR + n];
                vbh[1] = Vh[(k + 4) * VSTR + n];
                vbl[0] = Vl[k * VSTR + n];
                vbl[1] = Vl[(k + 4) * VSTR + n];
                mma_tf32(out[nt], pah, vbh);
                mma_tf32(out[nt], pah, vbl);
                mma_tf32(out[nt], pal, vbh);
            }
        }
        __syncwarp();
    }

    if (j_start > 0) {
        float mn0 = fmaxf(m0, 0.f), mn1 = fmaxf(m1, 0.f);
        float esc0 = __expf(m0 - mn0), esc1 = __expf(m1 - mn1);
        float e0 = __expf(0.f - mn0), e1 = __expf(0.f - mn1);
        sum0 = sum0 * esc0 + 4.f * e0;
        sum1 = sum1 * esc1 + 4.f * e1;
#pragma unroll
        for (int nt = 0; nt < 8; nt++) {
            int col = nt * 8 + 2 * (lane & 3);
            out[nt][0] = out[nt][0] * esc0 + e0 * Vg4[col];
            out[nt][1] = out[nt][1] * esc0 + e0 * Vg4[col + 1];
            out[nt][2] = out[nt][2] * esc1 + e1 * Vg4[col];
            out[nt][3] = out[nt][3] * esc1 + e1 * Vg4[col + 1];
        }
    }

    float inv0 = 1.f / sum0, inv1 = 1.f / sum1;
    const int r0 = i0 + wq * 16 + (lane >> 2);

    // ---- fused global attention: weights per row (exact fp32 Q reload) ----
    float w[2][4], deninv[2];
#pragma unroll
    for (int rr = 0; rr < 2; rr++) {
        int r = r0 + rr * 8;
        const float* qp = Q + (size_t)r * DMODEL + h * HDIM;
        float dot[4] = {0.f, 0.f, 0.f, 0.f};
#pragma unroll
        for (int ks = 0; ks < 8; ks++) {
#pragma unroll
            for (int e2 = 0; e2 < 2; e2++) {
                int c = ks * 8 + (lane & 3) + e2 * 4;
                float qv = qp[c];
#pragma unroll
                for (int t = 0; t < 4; t++)
                    dot[t] = fmaf(qv, KG4[t * HDIM + c], dot[t]);
            }
        }
#pragma unroll
        for (int t = 0; t < 4; t++) {
#pragma unroll
            for (int o = 1; o < 4; o <<= 1)
                dot[t] += __shfl_xor_sync(0xffffffff, dot[t], o);
            dot[t] *= 0.125f;
        }
        float mg = fmaxf(fmaxf(dot[0], dot[1]), fmaxf(dot[2], dot[3]));
        float den = 0.f;
#pragma unroll
        for (int t = 0; t < 4; t++) { w[rr][t] = __expf(dot[t] - mg); den += w[rr][t]; }
        deninv[rr] = 1.f / den;
    }

    // ---- combine + write tf32 hi/lo split directly (feeds out_gemm) ----
#pragma unroll
    for (int nt = 0; nt < 8; nt++) {
#pragma unroll
        for (int e = 0; e < 4; e++) {
            int rr = (e & 2) ? 1 : 0;
            int col = nt * 8 + 2 * (lane & 3) + (e & 1);
            float g = (w[rr][0] * VG4[0 * HDIM + col] + w[rr][1] * VG4[1 * HDIM + col] +
                       w[rr][2] * VG4[2 * HDIM + col] + w[rr][3] * VG4[3 * HDIM + col]) * deninv[rr];
            float v = out[nt][e] * (rr ? inv1 : inv0) + g;
            size_t idx = (size_t)(r0 + rr * 8) * DMODEL + h * HDIM + col;
            unsigned hb = f2tf32(v);
            g_Sh[idx] = hb;
            g_Sl[idx] = f2tf32(v - __uint_as_float(hb));
        }
    }
}

// ---------------------------------------------------------------------------
// launch
// ---------------------------------------------------------------------------
extern "C" void kernel_launch(void* const* d_in, const int* in_sizes, int n_in,
                              void* d_out, int out_size)
{
    const float* x     = (const float*)d_in[0];
    const float* cos_t = (const float*)d_in[1];
    const float* sin_t = (const float*)d_in[2];
    const int*   pos   = (const int*)d_in[3];
    P4 ws;
    ws.p[0] = (const float*)d_in[4];    // Wqs
    ws.p[1] = (const float*)d_in[5];    // Wks
    ws.p[2] = (const float*)d_in[6];    // Wvs
    ws.p[3] = (const float*)d_in[10];   // Wo
    const float* Wkg = (const float*)d_in[8];
    const float* Wvg = (const float*)d_in[9];
    float* out = (float*)d_out;

    static int attrs_set = 0;
    int attn_smem = ATT_SMEM_WORDS * 4;
    if (!attrs_set) {
        cudaFuncSetAttribute(attn_kernel,
                             cudaFuncAttributeMaxDynamicSharedMemorySize, attn_smem);
        cudaFuncSetAttribute(proj_kernel,
                             cudaFuncAttributeMaxDynamicSharedMemorySize, GEMM_SMEM_BYTES);
        cudaFuncSetAttribute(out_gemm_kernel,
                             cudaFuncAttributeMaxDynamicSharedMemorySize, GEMM_SMEM_BYTES);
        attrs_set = 1;
    }

    unsigned* Sh;
    unsigned* Sl;
    cudaGetSymbolAddress((void**)&Sh, g_Sh);
    cudaGetSymbolAddress((void**)&Sl, g_Sl);

    split_kernel<<<(ACT_ELEMS / 4 + 255) / 256, 256>>>(x, Sh, Sl, ACT_ELEMS / 4);
    dim3 gw(W_ELEMS / 4 / 256, 1, 4);
    split_w_kernel<<<gw, 256>>>(ws, Sh, Sl);

    dim3 gkg(DMODEL / 256, KGVG_KSPLIT);
    kgvg_part_kernel<<<gkg, 256>>>(x, Wkg, Wvg);
    kgvg_reduce_kernel<<<(2 * NGLOB * DMODEL) / 256, 256>>>();

    dim3 gp(DMODEL / 128, S_LEN / 128, 3);
    proj_kernel<<<gp, 256, GEMM_SMEM_BYTES>>>(cos_t, sin_t, pos);

    dim3 ga(NHEADS, S_LEN / 64);
    attn_kernel<<<ga, 128, attn_smem>>>();

    dim3 go(DMODEL / 128, S_LEN / 128);
    out_gemm_kernel<<<go, 256, GEMM_SMEM_BYTES>>>(out);
}

// round 8
// speedup vs baseline: 2.0269x; 1.2548x over previous
#include <cuda_runtime.h>
#include <cuda_bf16.h>
#include <math.h>

#define S_LEN 2048
#define DMODEL 1024
#define NHEADS 16
#define HDIM 64
#define RADIUS 256
#define NGLOB 4

__device__ float g_P[(size_t)5 * S_LEN * DMODEL];

#define KGVG_KSPLIT 32
__device__ float g_KVGp[KGVG_KSPLIT][2][NGLOB][DMODEL];

// pre-split bf16 hi/lo: [0:ACT) activations row-major [row][k],
// then 4 weights (Wqs,Wks,Wvs,Wo) TRANSPOSED [n][k]
#define ACT_ELEMS (S_LEN * DMODEL)
#define W_ELEMS   (DMODEL * DMODEL)
__device__ __nv_bfloat16 g_Bh[(size_t)ACT_ELEMS + 4 * W_ELEMS];
__device__ __nv_bfloat16 g_Bl[(size_t)ACT_ELEMS + 4 * W_ELEMS];

struct P4 { const float* p[4]; };

__device__ __forceinline__ unsigned f2tf32(float x) {
    unsigned r;
    asm("cvt.rna.tf32.f32 %0, %1;" : "=r"(r) : "f"(x));
    return r;
}

__device__ __forceinline__ void mma_tf32(float* c, const unsigned* a, const unsigned* b) {
    asm volatile(
        "mma.sync.aligned.m16n8k8.row.col.f32.tf32.tf32.f32 "
        "{%0,%1,%2,%3}, {%4,%5,%6,%7}, {%8,%9}, {%0,%1,%2,%3};"
        : "+f"(c[0]), "+f"(c[1]), "+f"(c[2]), "+f"(c[3])
        : "r"(a[0]), "r"(a[1]), "r"(a[2]), "r"(a[3]), "r"(b[0]), "r"(b[1]));
}

__device__ __forceinline__ void mma_bf16(float* c, const unsigned* a, const unsigned* b) {
    asm volatile(
        "mma.sync.aligned.m16n8k16.row.col.f32.bf16.bf16.f32 "
        "{%0,%1,%2,%3}, {%4,%5,%6,%7}, {%8,%9}, {%0,%1,%2,%3};"
        : "+f"(c[0]), "+f"(c[1]), "+f"(c[2]), "+f"(c[3])
        : "r"(a[0]), "r"(a[1]), "r"(a[2]), "r"(a[3]), "r"(b[0]), "r"(b[1]));
}

__device__ __forceinline__ void cpa16(void* dst, const void* src) {
    unsigned s = (unsigned)__cvta_generic_to_shared(dst);
    asm volatile("cp.async.cg.shared.global [%0], [%1], 16;" :: "r"(s), "l"(src));
}

__device__ __forceinline__ unsigned short bf16h(float x) {
    __nv_bfloat16 b = __float2bfloat16(x);
    return *reinterpret_cast<unsigned short*>(&b);
}

// ---------------------------------------------------------------------------
// split kernels: fp32 -> (bf16 hi, bf16 lo)
// ---------------------------------------------------------------------------
__global__ __launch_bounds__(256) void split_x_kernel(const float* __restrict__ src,
                                                      __nv_bfloat16* __restrict__ h,
                                                      __nv_bfloat16* __restrict__ l, int n4)
{
    int i = blockIdx.x * blockDim.x + threadIdx.x;
    if (i >= n4) return;
    float4 v = ((const float4*)src)[i];
    float f[4] = {v.x, v.y, v.z, v.w};
    ushort4 hv, lv;
    unsigned short* hp = &hv.x;
    unsigned short* lp = &lv.x;
#pragma unroll
    for (int e = 0; e < 4; e++) {
        __nv_bfloat16 hb = __float2bfloat16(f[e]);
        hp[e] = *reinterpret_cast<unsigned short*>(&hb);
        float lo = f[e] - __bfloat162float(hb);
        __nv_bfloat16 lb = __float2bfloat16(lo);
        lp[e] = *reinterpret_cast<unsigned short*>(&lb);
    }
    ((ushort4*)h)[i] = hv;
    ((ushort4*)l)[i] = lv;
}

// transpose + split weights: W[k][n] -> Wt[n][k] hi/lo
__global__ __launch_bounds__(256) void split_wt_kernel(P4 srcs,
                                                       __nv_bfloat16* __restrict__ hbase,
                                                       __nv_bfloat16* __restrict__ lbase)
{
    __shared__ float t[32][33];
    const int z = blockIdx.z;
    const float* W = srcs.p[z];
    const int n0 = blockIdx.x * 32, k0 = blockIdx.y * 32;
    const int tx = threadIdx.x & 31, ty = threadIdx.x >> 5;   // 32 x 8

#pragma unroll
    for (int j = 0; j < 4; j++)
        t[ty + j * 8][tx] = W[(size_t)(k0 + ty + j * 8) * DMODEL + n0 + tx];
    __syncthreads();

    size_t base = (size_t)ACT_ELEMS + (size_t)z * W_ELEMS;
#pragma unroll
    for (int j = 0; j < 4; j++) {
        int n = n0 + ty + j * 8;
        int k = k0 + tx;
        float v = t[tx][ty + j * 8];
        __nv_bfloat16 hb = __float2bfloat16(v);
        float lo = v - __bfloat162float(hb);
        size_t idx = base + (size_t)n * DMODEL + k;
        hbase[idx] = hb;
        lbase[idx] = __float2bfloat16(lo);
    }
}

// ---------------------------------------------------------------------------
// 3xBF16 GEMM (m16n8k16), pre-split inputs, 4-stage cp.async pipeline,
// optional fused RoPE. block 128x128x16, 8 warps (4M x 2N), warp 32x64.
// ---------------------------------------------------------------------------
#define GBK 16
#define STR 12                       // 32-bit words per row (8 data + 4 pad)
#define TILE_WORDS (128 * STR)       // 6144 B
#define NSTAGE 4
#define GEMM_SMEM_BYTES (NSTAGE * 4 * TILE_WORDS * 4)   // 98304

__device__ __forceinline__ void gemm3_body(const __nv_bfloat16* __restrict__ Agh,
                                           const __nv_bfloat16* __restrict__ Agl,
                                           const __nv_bfloat16* __restrict__ Bgh,
                                           const __nv_bfloat16* __restrict__ Bgl,
                                           float* __restrict__ C,
                                           bool do_rope,
                                           const float* __restrict__ cos_t,
                                           const float* __restrict__ sin_t,
                                           const int* __restrict__ pos)
{
    extern __shared__ unsigned sm[];
    unsigned* uAh = sm;
    unsigned* uAl = sm + NSTAGE * TILE_WORDS;
    unsigned* uBh = sm + 2 * NSTAGE * TILE_WORDS;
    unsigned* uBl = sm + 3 * NSTAGE * TILE_WORDS;

    const int tid = threadIdx.x;
    const int lane = tid & 31;
    const int warp = tid >> 5;
    const int wm = warp >> 1;
    const int wn = warp & 1;
    const int bx = blockIdx.x, by = blockIdx.y;

    float acc[2][8][4];
#pragma unroll
    for (int mt = 0; mt < 2; mt++)
#pragma unroll
        for (int nt = 0; nt < 8; nt++)
#pragma unroll
            for (int e = 0; e < 4; e++) acc[mt][nt][e] = 0.f;

    const int m_ = tid >> 1;           // 0..127
    const int half = tid & 1;          // 0,1 -> k chunk of 8 bf16 (16 B)

    auto load_stage = [&](int st, int k0) {
        unsigned* ah = uAh + st * TILE_WORDS;
        unsigned* al = uAl + st * TILE_WORDS;
        unsigned* bh = uBh + st * TILE_WORDS;
        unsigned* bl = uBl + st * TILE_WORDS;
        size_t ga = (size_t)(by * 128 + m_) * DMODEL + k0 + half * 8;
        size_t gb = (size_t)(bx * 128 + m_) * DMODEL + k0 + half * 8;
        int so = m_ * STR + half * 4;
        cpa16(ah + so, Agh + ga);
        cpa16(al + so, Agl + ga);
        cpa16(bh + so, Bgh + gb);
        cpa16(bl + so, Bgl + gb);
    };

    load_stage(0, 0);
    asm volatile("cp.async.commit_group;");
    load_stage(1, GBK);
    asm volatile("cp.async.commit_group;");
    load_stage(2, 2 * GBK);
    asm volatile("cp.async.commit_group;");

    const int NT = DMODEL / GBK;   // 64
#pragma unroll 1
    for (int i = 0; i < NT; i++) {
        int st = i & 3;
        asm volatile("cp.async.wait_group 2;");
        __syncthreads();

        unsigned* ah_s = uAh + st * TILE_WORDS;
        unsigned* al_s = uAl + st * TILE_WORDS;
        unsigned* bh_s = uBh + st * TILE_WORDS;
        unsigned* bl_s = uBl + st * TILE_WORDS;

        unsigned ah[2][4], al[2][4];
        const int c = lane & 3;
#pragma unroll
        for (int mt = 0; mt < 2; mt++) {
            int r = wm * 32 + mt * 16 + (lane >> 2);
            ah[mt][0] = ah_s[r * STR + c];
            ah[mt][1] = ah_s[(r + 8) * STR + c];
            ah[mt][2] = ah_s[r * STR + 4 + c];
            ah[mt][3] = ah_s[(r + 8) * STR + 4 + c];
            al[mt][0] = al_s[r * STR + c];
            al[mt][1] = al_s[(r + 8) * STR + c];
            al[mt][2] = al_s[r * STR + 4 + c];
            al[mt][3] = al_s[(r + 8) * STR + 4 + c];
        }
#pragma unroll
        for (int nt = 0; nt < 8; nt++) {
            int n = wn * 64 + nt * 8 + (lane >> 2);
            unsigned bh[2], bl[2];
            bh[0] = bh_s[n * STR + c];
            bh[1] = bh_s[n * STR + 4 + c];
            bl[0] = bl_s[n * STR + c];
            bl[1] = bl_s[n * STR + 4 + c];
#pragma unroll
            for (int mt = 0; mt < 2; mt++) {
                mma_bf16(acc[mt][nt], ah[mt], bh);
                mma_bf16(acc[mt][nt], ah[mt], bl);
                mma_bf16(acc[mt][nt], al[mt], bh);
            }
        }

        if (i + 3 < NT) load_stage((i + 3) & 3, (i + 3) * GBK);
        asm volatile("cp.async.commit_group;");
    }

    if (do_rope) {
#pragma unroll
        for (int mt = 0; mt < 2; mt++) {
            int r0 = by * 128 + wm * 32 + mt * 16 + (lane >> 2);
            int p0 = __ldg(pos + r0);
            int p1 = __ldg(pos + r0 + 8);
#pragma unroll
            for (int nt = 0; nt < 4; nt++) {
#pragma unroll
                for (int e = 0; e < 2; e++) {
                    int d = nt * 8 + 2 * (lane & 3) + e;
                    {
                        float c0 = __ldg(cos_t + p0 * HDIM + d);
                        float s0 = __ldg(sin_t + p0 * HDIM + d);
                        float c1 = __ldg(cos_t + p0 * HDIM + d + 32);
                        float s1 = __ldg(sin_t + p0 * HDIM + d + 32);
                        float x0 = acc[mt][nt][e];
                        float x1 = acc[mt][nt + 4][e];
                        acc[mt][nt][e]     = x0 * c0 - x1 * s0;
                        acc[mt][nt + 4][e] = x1 * c1 + x0 * s1;
                    }
                    {
                        float c0 = __ldg(cos_t + p1 * HDIM + d);
                        float s0 = __ldg(sin_t + p1 * HDIM + d);
                        float c1 = __ldg(cos_t + p1 * HDIM + d + 32);
                        float s1 = __ldg(sin_t + p1 * HDIM + d + 32);
                        float x0 = acc[mt][nt][e + 2];
                        float x1 = acc[mt][nt + 4][e + 2];
                        acc[mt][nt][e + 2]     = x0 * c0 - x1 * s0;
                        acc[mt][nt + 4][e + 2] = x1 * c1 + x0 * s1;
                    }
                }
            }
        }
    }

#pragma unroll
    for (int mt = 0; mt < 2; mt++) {
        int r0 = by * 128 + wm * 32 + mt * 16 + (lane >> 2);
#pragma unroll
        for (int nt = 0; nt < 8; nt++) {
            int cc = bx * 128 + wn * 64 + nt * 8 + ((lane & 3) << 1);
            *(float2*)(C + (size_t)r0 * DMODEL + cc) =
                make_float2(acc[mt][nt][0], acc[mt][nt][1]);
            *(float2*)(C + (size_t)(r0 + 8) * DMODEL + cc) =
                make_float2(acc[mt][nt][2], acc[mt][nt][3]);
        }
    }
}

__global__ __launch_bounds__(256, 2) void proj_kernel(const float* __restrict__ cos_t,
                                                      const float* __restrict__ sin_t,
                                                      const int* __restrict__ pos)
{
    int z = blockIdx.z;   // 0=Q(rope) 1=K(rope) 2=V
    gemm3_body(g_Bh, g_Bl,
               g_Bh + ACT_ELEMS + (size_t)z * W_ELEMS,
               g_Bl + ACT_ELEMS + (size_t)z * W_ELEMS,
               g_P + (size_t)z * ACT_ELEMS,
               z < 2, cos_t, sin_t, pos);
}

__global__ __launch_bounds__(256, 1) void out_gemm_kernel(float* __restrict__ out)
{
    gemm3_body(g_Bh, g_Bl,
               g_Bh + ACT_ELEMS + (size_t)3 * W_ELEMS,
               g_Bl + ACT_ELEMS + (size_t)3 * W_ELEMS,
               out, false, nullptr, nullptr, nullptr);
}

// ---------------------------------------------------------------------------
// KG/VG rows 0..3 only, split-K parallel (unchanged).
// ---------------------------------------------------------------------------
__global__ __launch_bounds__(256) void kgvg_part_kernel(const float* __restrict__ x,
                                                        const float* __restrict__ Wkg,
                                                        const float* __restrict__ Wvg)
{
    const int d = blockIdx.x * 256 + threadIdx.x;
    const int kz = blockIdx.y;
    __shared__ float xs[NGLOB][32];
    if (threadIdx.x < NGLOB * 32) {
        int t = threadIdx.x >> 5, k = threadIdx.x & 31;
        xs[t][k] = x[(size_t)t * DMODEL + kz * 32 + k];
    }
    __syncthreads();

    float ak[NGLOB] = {0.f, 0.f, 0.f, 0.f};
    float av[NGLOB] = {0.f, 0.f, 0.f, 0.f};
#pragma unroll 4
    for (int kk = 0; kk < 32; kk++) {
        size_t row = (size_t)(kz * 32 + kk) * DMODEL + d;
        float wk = __ldg(Wkg + row);
        float wv = __ldg(Wvg + row);
#pragma unroll
        for (int t = 0; t < NGLOB; t++) {
            ak[t] = fmaf(xs[t][kk], wk, ak[t]);
            av[t] = fmaf(xs[t][kk], wv, av[t]);
        }
    }
#pragma unroll
    for (int t = 0; t < NGLOB; t++) {
        g_KVGp[kz][0][t][d] = ak[t];
        g_KVGp[kz][1][t][d] = av[t];
    }
}

__global__ __launch_bounds__(256) void kgvg_reduce_kernel()
{
    int idx = blockIdx.x * 256 + threadIdx.x;
    int d = idx & (DMODEL - 1);
    int t = (idx >> 10) & 3;
    int m = idx >> 12;
    float s = 0.f;
#pragma unroll
    for (int kz = 0; kz < KGVG_KSPLIT; kz++) s += g_KVGp[kz][m][t][d];
    g_P[(size_t)(3 + m) * ACT_ELEMS + (size_t)t * DMODEL + d] = s;
}

// ---------------------------------------------------------------------------
// Block-tiled MMA flash attention (tf32x3) + fused global attn + bf16 O split.
// ---------------------------------------------------------------------------
#define KSTR 68
#define VSTR 72
#define PSTR 68
#define OFF_KH 0
#define OFF_KL (OFF_KH + 64 * KSTR)
#define OFF_VH (OFF_KL + 64 * KSTR)
#define OFF_VL (OFF_VH + 64 * VSTR)
#define OFF_PH (OFF_VL + 64 * VSTR)
#define OFF_PL (OFF_PH + 64 * PSTR)
#define OFF_VG (OFF_PL + 64 * PSTR)
#define OFF_KG4 (OFF_VG + HDIM)
#define OFF_VG4 (OFF_KG4 + NGLOB * HDIM)
#define ATT_SMEM_WORDS (OFF_VG4 + NGLOB * HDIM)

__global__ __launch_bounds__(128, 2) void attn_kernel()
{
    extern __shared__ unsigned smem_u[];
    unsigned* Kh = smem_u + OFF_KH;
    unsigned* Kl = smem_u + OFF_KL;
    unsigned* Vh = smem_u + OFF_VH;
    unsigned* Vl = smem_u + OFF_VL;
    unsigned* Ph = smem_u + OFF_PH;
    unsigned* Pl = smem_u + OFF_PL;
    float*    Vg4 = (float*)(smem_u + OFF_VG);
    float*    KG4 = (float*)(smem_u + OFF_KG4);
    float*    VG4 = (float*)(smem_u + OFF_VG4);

    const int h  = blockIdx.x;
    const int i0 = blockIdx.y * 64;
    const int tid = threadIdx.x;
    const int lane = tid & 31;
    const int wq = tid >> 5;

    const float* Q = g_P;
    const float* K = g_P + (size_t)1 * ACT_ELEMS;
    const float* V = g_P + (size_t)2 * ACT_ELEMS;

    if (tid < HDIM) {
        const float* vb = V + h * HDIM + tid;
        Vg4[tid] = vb[0] + vb[DMODEL] + vb[2 * DMODEL] + vb[3 * DMODEL];
    }
    for (int i2 = tid; i2 < 2 * NGLOB * HDIM; i2 += 128) {
        int mm = i2 >> 8;
        int t = (i2 >> 6) & 3;
        int c = i2 & 63;
        float val = g_P[(size_t)(3 + mm) * ACT_ELEMS + (size_t)t * DMODEL + h * HDIM + c];
        (mm ? VG4 : KG4)[t * HDIM + c] = val;
    }

    unsigned qh[8][4], ql[8][4];
    {
        const int r0 = i0 + wq * 16 + (lane >> 2);
#pragma unroll
        for (int ks = 0; ks < 8; ks++) {
            int c = h * HDIM + ks * 8 + (lane & 3);
            float f[4];
            f[0] = Q[(size_t)r0 * DMODEL + c];
            f[1] = Q[(size_t)(r0 + 8) * DMODEL + c];
            f[2] = Q[(size_t)r0 * DMODEL + c + 4];
            f[3] = Q[(size_t)(r0 + 8) * DMODEL + c + 4];
#pragma unroll
            for (int e = 0; e < 4; e++) {
                unsigned hi = f2tf32(f[e]);
                qh[ks][e] = hi;
                ql[ks][e] = f2tf32(f[e] - __uint_as_float(hi));
            }
        }
    }

    float out[8][4];
#pragma unroll
    for (int nt = 0; nt < 8; nt++)
#pragma unroll
        for (int e = 0; e < 4; e++) out[nt][e] = 0.f;
    float m0 = -3.4e38f, m1 = -3.4e38f, sum0 = 0.f, sum1 = 0.f;

    const int j_start = (i0 - RADIUS) > 0 ? (i0 - RADIUS) : 0;

    for (int jc = j_start; jc < i0 + 64; jc += 64) {
        __syncthreads();
#pragma unroll
        for (int it = 0; it < 8; it++) {
            int idx = it * 128 + tid;
            int key = idx >> 4;
            int dq = (idx & 15) << 2;
            size_t gofs = (size_t)(jc + key) * DMODEL + h * HDIM + dq;
            float4 kv = *(const float4*)(K + gofs);
            float4 vv = *(const float4*)(V + gofs);
            float kf[4] = {kv.x, kv.y, kv.z, kv.w};
            float vf[4] = {vv.x, vv.y, vv.z, vv.w};
#pragma unroll
            for (int e = 0; e < 4; e++) {
                unsigned hk = f2tf32(kf[e]);
                Kh[key * KSTR + dq + e] = hk;
                Kl[key * KSTR + dq + e] = f2tf32(kf[e] - __uint_as_float(hk));
                unsigned hv = f2tf32(vf[e]);
                Vh[key * VSTR + dq + e] = hv;
                Vl[key * VSTR + dq + e] = f2tf32(vf[e] - __uint_as_float(hv));
            }
        }
        __syncthreads();

        float sc[8][4];
#pragma unroll
        for (int nt = 0; nt < 8; nt++)
#pragma unroll
            for (int e = 0; e < 4; e++) sc[nt][e] = 0.f;

#pragma unroll
        for (int ks = 0; ks < 8; ks++) {
#pragma unroll
            for (int nt = 0; nt < 8; nt++) {
                int n = nt * 8 + (lane >> 2);
                int k = ks * 8 + (lane & 3);
                unsigned bh[2], bl[2];
                bh[0] = Kh[n * KSTR + k];
                bh[1] = Kh[n * KSTR + k + 4];
                bl[0] = Kl[n * KSTR + k];
                bl[1] = Kl[n * KSTR + k + 4];
                mma_tf32(sc[nt], qh[ks], bh);
                mma_tf32(sc[nt], qh[ks], bl);
                mma_tf32(sc[nt], ql[ks], bh);
            }
        }

        const int ibase = i0 + wq * 16 + (lane >> 2);
        float mn0 = m0, mn1 = m1;
#pragma unroll
        for (int nt = 0; nt < 8; nt++) {
#pragma unroll
            for (int e = 0; e < 4; e++) {
                int i = ibase + ((e & 2) ? 8 : 0);
                int j = jc + nt * 8 + 2 * (lane & 3) + (e & 1);
                bool inw = (j <= i) && (i - j <= RADIUS);
                float raw = sc[nt][e] * 0.125f;
                float s;
                if (j < NGLOB) s = inw ? (raw + 1e9f) : 0.f;
                else           s = inw ? raw : -3.0e38f;
                sc[nt][e] = s;
                if (e & 2) mn1 = fmaxf(mn1, s); else mn0 = fmaxf(mn0, s);
            }
        }
#pragma unroll
        for (int o = 1; o < 4; o <<= 1) {
            mn0 = fmaxf(mn0, __shfl_xor_sync(0xffffffff, mn0, o));
            mn1 = fmaxf(mn1, __shfl_xor_sync(0xffffffff, mn1, o));
        }
        float esc0 = __expf(m0 - mn0);
        float esc1 = __expf(m1 - mn1);
        m0 = mn0; m1 = mn1;

        float ps0 = 0.f, ps1 = 0.f;
#pragma unroll
        for (int nt = 0; nt < 8; nt++) {
#pragma unroll
            for (int e = 0; e < 4; e++) {
                float p = __expf(sc[nt][e] - ((e & 2) ? m1 : m0));
                sc[nt][e] = p;
                if (e & 2) ps1 += p; else ps0 += p;
            }
        }
#pragma unroll
        for (int o = 1; o < 4; o <<= 1) {
            ps0 += __shfl_xor_sync(0xffffffff, ps0, o);
            ps1 += __shfl_xor_sync(0xffffffff, ps1, o);
        }
        sum0 = sum0 * esc0 + ps0;
        sum1 = sum1 * esc1 + ps1;
#pragma unroll
        for (int nt = 0; nt < 8; nt++) {
            out[nt][0] *= esc0; out[nt][1] *= esc0;
            out[nt][2] *= esc1; out[nt][3] *= esc1;
        }

#pragma unroll
        for (int nt = 0; nt < 8; nt++) {
#pragma unroll
            for (int e = 0; e < 4; e++) {
                int row = wq * 16 + (lane >> 2) + ((e & 2) ? 8 : 0);
                int col = nt * 8 + 2 * (lane & 3) + (e & 1);
                float p = sc[nt][e];
                unsigned hp = f2tf32(p);
                Ph[row * PSTR + col] = hp;
                Pl[row * PSTR + col] = f2tf32(p - __uint_as_float(hp));
            }
        }
        __syncwarp();

#pragma unroll
        for (int ks = 0; ks < 8; ks++) {
            int r = wq * 16 + (lane >> 2);
            int c = ks * 8 + (lane & 3);
            unsigned pah[4], pal[4];
            pah[0] = Ph[r * PSTR + c];
            pah[1] = Ph[(r + 8) * PSTR + c];
            pah[2] = Ph[r * PSTR + c + 4];
            pah[3] = Ph[(r + 8) * PSTR + c + 4];
            pal[0] = Pl[r * PSTR + c];
            pal[1] = Pl[(r + 8) * PSTR + c];
            pal[2] = Pl[r * PSTR + c + 4];
            pal[3] = Pl[(r + 8) * PSTR + c + 4];
#pragma unroll
            for (int nt = 0; nt < 8; nt++) {
                int k = ks * 8 + (lane & 3);
                int n = nt * 8 + (lane >> 2);
                unsigned vbh[2], vbl[2];
                vbh[0] = Vh[k * VSTR + n];
                vbh[1] = Vh[(k + 4) * VSTR + n];
                vbl[0] = Vl[k * VSTR + n];
                vbl[1] = Vl[(k + 4) * VSTR + n];
                mma_tf32(out[nt], pah, vbh);
                mma_tf32(out[nt], pah, vbl);
                mma_tf32(out[nt], pal, vbh);
            }
        }
        __syncwarp();
    }

    if (j_start > 0) {
        float mn0 = fmaxf(m0, 0.f), mn1 = fmaxf(m1, 0.f);
        float esc0 = __expf(m0 - mn0), esc1 = __expf(m1 - mn1);
        float e0 = __expf(0.f - mn0), e1 = __expf(0.f - mn1);
        sum0 = sum0 * esc0 + 4.f * e0;
        sum1 = sum1 * esc1 + 4.f * e1;
#pragma unroll
        for (int nt = 0; nt < 8; nt++) {
            int col = nt * 8 + 2 * (lane & 3);
            out[nt][0] = out[nt][0] * esc0 + e0 * Vg4[col];
            out[nt][1] = out[nt][1] * esc0 + e0 * Vg4[col + 1];
            out[nt][2] = out[nt][2] * esc1 + e1 * Vg4[col];
            out[nt][3] = out[nt][3] * esc1 + e1 * Vg4[col + 1];
        }
    }

    float inv0 = 1.f / sum0, inv1 = 1.f / sum1;
    const int r0 = i0 + wq * 16 + (lane >> 2);

    float w[2][4], deninv[2];
#pragma unroll
    for (int rr = 0; rr < 2; rr++) {
        int r = r0 + rr * 8;
        const float* qp = Q + (size_t)r * DMODEL + h * HDIM;
        float dot[4] = {0.f, 0.f, 0.f, 0.f};
#pragma unroll
        for (int ks = 0; ks < 8; ks++) {
#pragma unroll
            for (int e2 = 0; e2 < 2; e2++) {
                int c = ks * 8 + (lane & 3) + e2 * 4;
                float qv = qp[c];
#pragma unroll
                for (int t = 0; t < 4; t++)
                    dot[t] = fmaf(qv, KG4[t * HDIM + c], dot[t]);
            }
        }
#pragma unroll
        for (int t = 0; t < 4; t++) {
#pragma unroll
            for (int o = 1; o < 4; o <<= 1)
                dot[t] += __shfl_xor_sync(0xffffffff, dot[t], o);
            dot[t] *= 0.125f;
        }
        float mg = fmaxf(fmaxf(dot[0], dot[1]), fmaxf(dot[2], dot[3]));
        float den = 0.f;
#pragma unroll
        for (int t = 0; t < 4; t++) { w[rr][t] = __expf(dot[t] - mg); den += w[rr][t]; }
        deninv[rr] = 1.f / den;
    }

#pragma unroll
    for (int nt = 0; nt < 8; nt++) {
#pragma unroll
        for (int e = 0; e < 4; e++) {
            int rr = (e & 2) ? 1 : 0;
            int col = nt * 8 + 2 * (lane & 3) + (e & 1);
            float g = (w[rr][0] * VG4[0 * HDIM + col] + w[rr][1] * VG4[1 * HDIM + col] +
                       w[rr][2] * VG4[2 * HDIM + col] + w[rr][3] * VG4[3 * HDIM + col]) * deninv[rr];
            float v = out[nt][e] * (rr ? inv1 : inv0) + g;
            size_t idx = (size_t)(r0 + rr * 8) * DMODEL + h * HDIM + col;
            __nv_bfloat16 hb = __float2bfloat16(v);
            g_Bh[idx] = hb;
            g_Bl[idx] = __float2bfloat16(v - __bfloat162float(hb));
        }
    }
}

// ---------------------------------------------------------------------------
// launch
// ---------------------------------------------------------------------------
extern "C" void kernel_launch(void* const* d_in, const int* in_sizes, int n_in,
                              void* d_out, int out_size)
{
    const float* x     = (const float*)d_in[0];
    const float* cos_t = (const float*)d_in[1];
    const float* sin_t = (const float*)d_in[2];
    const int*   pos   = (const int*)d_in[3];
    P4 ws;
    ws.p[0] = (const float*)d_in[4];    // Wqs
    ws.p[1] = (const float*)d_in[5];    // Wks
    ws.p[2] = (const float*)d_in[6];    // Wvs
    ws.p[3] = (const float*)d_in[10];   // Wo
    const float* Wkg = (const float*)d_in[8];
    const float* Wvg = (const float*)d_in[9];
    float* out = (float*)d_out;

    static int attrs_set = 0;
    int attn_smem = ATT_SMEM_WORDS * 4;
    if (!attrs_set) {
        cudaFuncSetAttribute(attn_kernel,
                             cudaFuncAttributeMaxDynamicSharedMemorySize, attn_smem);
        cudaFuncSetAttribute(proj_kernel,
                             cudaFuncAttributeMaxDynamicSharedMemorySize, GEMM_SMEM_BYTES);
        cudaFuncSetAttribute(out_gemm_kernel,
                             cudaFuncAttributeMaxDynamicSharedMemorySize, GEMM_SMEM_BYTES);
        attrs_set = 1;
    }

    __nv_bfloat16* Bh;
    __nv_bfloat16* Bl;
    cudaGetSymbolAddress((void**)&Bh, g_Bh);
    cudaGetSymbolAddress((void**)&Bl, g_Bl);

    split_x_kernel<<<(ACT_ELEMS / 4 + 255) / 256, 256>>>(x, Bh, Bl, ACT_ELEMS / 4);
    dim3 gw(DMODEL / 32, DMODEL / 32, 4);
    split_wt_kernel<<<gw, 256>>>(ws, Bh, Bl);

    dim3 gkg(DMODEL / 256, KGVG_KSPLIT);
    kgvg_part_kernel<<<gkg, 256>>>(x, Wkg, Wvg);
    kgvg_reduce_kernel<<<(2 * NGLOB * DMODEL) / 256, 256>>>();

    dim3 gp(DMODEL / 128, S_LEN / 128, 3);
    proj_kernel<<<gp, 256, GEMM_SMEM_BYTES>>>(cos_t, sin_t, pos);

    dim3 ga(NHEADS, S_LEN / 64);
    attn_kernel<<<ga, 128, attn_smem>>>();

    dim3 go(DMODEL / 128, S_LEN / 128);
    out_gemm_kernel<<<go, 256, GEMM_SMEM_BYTES>>>(out);
}

// round 9
// speedup vs baseline: 2.2156x; 1.0930x over previous
#include <cuda_runtime.h>
#include <cuda_bf16.h>
#include <math.h>

#define S_LEN 2048
#define DMODEL 1024
#define NHEADS 16
#define HDIM 64
#define RADIUS 256
#define NGLOB 4

__device__ float g_P[(size_t)5 * S_LEN * DMODEL];

#define KGVG_KSPLIT 32
__device__ float g_KVGp[KGVG_KSPLIT][2][NGLOB][DMODEL];

#define ACT_ELEMS (S_LEN * DMODEL)
#define W_ELEMS   (DMODEL * DMODEL)
// GEMM operand splits: [0:ACT) activations (x, later O), then 4 weights transposed [n][k]
__device__ __nv_bfloat16 g_Bh[(size_t)ACT_ELEMS + 4 * W_ELEMS];
__device__ __nv_bfloat16 g_Bl[(size_t)ACT_ELEMS + 4 * W_ELEMS];
// attention operand splits (post-rope): Q,K in [s][d]; V transposed [d][s]
__device__ __nv_bfloat16 g_Qbh[ACT_ELEMS], g_Qbl[ACT_ELEMS];
__device__ __nv_bfloat16 g_Kbh[ACT_ELEMS], g_Kbl[ACT_ELEMS];
__device__ __nv_bfloat16 g_Vth[ACT_ELEMS], g_Vtl[ACT_ELEMS];

struct P4 { const float* p[4]; };

__device__ __forceinline__ void mma_bf16(float* c, const unsigned* a, const unsigned* b) {
    asm volatile(
        "mma.sync.aligned.m16n8k16.row.col.f32.bf16.bf16.f32 "
        "{%0,%1,%2,%3}, {%4,%5,%6,%7}, {%8,%9}, {%0,%1,%2,%3};"
        : "+f"(c[0]), "+f"(c[1]), "+f"(c[2]), "+f"(c[3])
        : "r"(a[0]), "r"(a[1]), "r"(a[2]), "r"(a[3]), "r"(b[0]), "r"(b[1]));
}

__device__ __forceinline__ void cpa16(void* dst, const void* src) {
    unsigned s = (unsigned)__cvta_generic_to_shared(dst);
    asm volatile("cp.async.cg.shared.global [%0], [%1], 16;" :: "r"(s), "l"(src));
}

__device__ __forceinline__ unsigned pack_bf16(float a, float b) {
    __nv_bfloat162 t = __floats2bfloat162_rn(a, b);
    return *reinterpret_cast<unsigned*>(&t);
}

// ---------------------------------------------------------------------------
// split kernels
// ---------------------------------------------------------------------------
__global__ __launch_bounds__(256) void split_x_kernel(const float* __restrict__ src,
                                                      __nv_bfloat16* __restrict__ h,
                                                      __nv_bfloat16* __restrict__ l, int n4)
{
    int i = blockIdx.x * blockDim.x + threadIdx.x;
    if (i >= n4) return;
    float4 v = ((const float4*)src)[i];
    float f[4] = {v.x, v.y, v.z, v.w};
    ushort4 hv, lv;
    unsigned short* hp = &hv.x;
    unsigned short* lp = &lv.x;
#pragma unroll
    for (int e = 0; e < 4; e++) {
        __nv_bfloat16 hb = __float2bfloat16(f[e]);
        hp[e] = *reinterpret_cast<unsigned short*>(&hb);
        __nv_bfloat16 lb = __float2bfloat16(f[e] - __bfloat162float(hb));
        lp[e] = *reinterpret_cast<unsigned short*>(&lb);
    }
    ((ushort4*)h)[i] = hv;
    ((ushort4*)l)[i] = lv;
}

__global__ __launch_bounds__(256) void split_wt_kernel(P4 srcs,
                                                       __nv_bfloat16* __restrict__ hbase,
                                                       __nv_bfloat16* __restrict__ lbase)
{
    __shared__ float t[32][33];
    const int z = blockIdx.z;
    const float* W = srcs.p[z];
    const int n0 = blockIdx.x * 32, k0 = blockIdx.y * 32;
    const int tx = threadIdx.x & 31, ty = threadIdx.x >> 5;

#pragma unroll
    for (int j = 0; j < 4; j++)
        t[ty + j * 8][tx] = W[(size_t)(k0 + ty + j * 8) * DMODEL + n0 + tx];
    __syncthreads();

    size_t base = (size_t)ACT_ELEMS + (size_t)z * W_ELEMS;
#pragma unroll
    for (int j = 0; j < 4; j++) {
        int n = n0 + ty + j * 8;
        int k = k0 + tx;
        float v = t[tx][ty + j * 8];
        __nv_bfloat16 hb = __float2bfloat16(v);
        size_t idx = base + (size_t)n * DMODEL + k;
        hbase[idx] = hb;
        lbase[idx] = __float2bfloat16(v - __bfloat162float(hb));
    }
}

// V[s][d] (g_P slot 2) -> Vt bf16 hi/lo [d][s]
__global__ __launch_bounds__(256) void vt_split_kernel()
{
    __shared__ float t[32][33];
    const int s0 = blockIdx.x * 32, d0 = blockIdx.y * 32;
    const int tx = threadIdx.x & 31, ty = threadIdx.x >> 5;

#pragma unroll
    for (int j = 0; j < 4; j++)
        t[ty + j * 8][tx] = g_P[(size_t)2 * ACT_ELEMS + (size_t)(s0 + ty + j * 8) * DMODEL + d0 + tx];
    __syncthreads();

#pragma unroll
    for (int j = 0; j < 4; j++) {
        int d = d0 + ty + j * 8;
        int s = s0 + tx;
        float v = t[tx][ty + j * 8];
        __nv_bfloat16 hb = __float2bfloat16(v);
        size_t idx = (size_t)d * S_LEN + s;
        g_Vth[idx] = hb;
        g_Vtl[idx] = __float2bfloat16(v - __bfloat162float(hb));
    }
}

// ---------------------------------------------------------------------------
// 3xBF16 GEMM (m16n8k16), 4-stage cp.async pipeline, fused RoPE, optional
// bf16 hi/lo epilogue (for attention Q/K operands).
// ---------------------------------------------------------------------------
#define GBK 16
#define STR 12
#define TILE_WORDS (128 * STR)
#define NSTAGE 4
#define GEMM_SMEM_BYTES (NSTAGE * 4 * TILE_WORDS * 4)

__device__ __forceinline__ void gemm3_body(const __nv_bfloat16* __restrict__ Agh,
                                           const __nv_bfloat16* __restrict__ Agl,
                                           const __nv_bfloat16* __restrict__ Bgh,
                                           const __nv_bfloat16* __restrict__ Bgl,
                                           float* __restrict__ C,
                                           __nv_bfloat16* __restrict__ outBh,
                                           __nv_bfloat16* __restrict__ outBl,
                                           bool do_rope,
                                           const float* __restrict__ cos_t,
                                           const float* __restrict__ sin_t,
                                           const int* __restrict__ pos)
{
    extern __shared__ unsigned sm[];
    unsigned* uAh = sm;
    unsigned* uAl = sm + NSTAGE * TILE_WORDS;
    unsigned* uBh = sm + 2 * NSTAGE * TILE_WORDS;
    unsigned* uBl = sm + 3 * NSTAGE * TILE_WORDS;

    const int tid = threadIdx.x;
    const int lane = tid & 31;
    const int warp = tid >> 5;
    const int wm = warp >> 1;
    const int wn = warp & 1;
    const int bx = blockIdx.x, by = blockIdx.y;

    float acc[2][8][4];
#pragma unroll
    for (int mt = 0; mt < 2; mt++)
#pragma unroll
        for (int nt = 0; nt < 8; nt++)
#pragma unroll
            for (int e = 0; e < 4; e++) acc[mt][nt][e] = 0.f;

    const int m_ = tid >> 1;
    const int half = tid & 1;

    auto load_stage = [&](int st, int k0) {
        unsigned* ah = uAh + st * TILE_WORDS;
        unsigned* al = uAl + st * TILE_WORDS;
        unsigned* bh = uBh + st * TILE_WORDS;
        unsigned* bl = uBl + st * TILE_WORDS;
        size_t ga = (size_t)(by * 128 + m_) * DMODEL + k0 + half * 8;
        size_t gb = (size_t)(bx * 128 + m_) * DMODEL + k0 + half * 8;
        int so = m_ * STR + half * 4;
        cpa16(ah + so, Agh + ga);
        cpa16(al + so, Agl + ga);
        cpa16(bh + so, Bgh + gb);
        cpa16(bl + so, Bgl + gb);
    };

    load_stage(0, 0);
    asm volatile("cp.async.commit_group;");
    load_stage(1, GBK);
    asm volatile("cp.async.commit_group;");
    load_stage(2, 2 * GBK);
    asm volatile("cp.async.commit_group;");

    const int NT = DMODEL / GBK;
#pragma unroll 1
    for (int i = 0; i < NT; i++) {
        int st = i & 3;
        asm volatile("cp.async.wait_group 2;");
        __syncthreads();

        unsigned* ah_s = uAh + st * TILE_WORDS;
        unsigned* al_s = uAl + st * TILE_WORDS;
        unsigned* bh_s = uBh + st * TILE_WORDS;
        unsigned* bl_s = uBl + st * TILE_WORDS;

        unsigned ah[2][4], al[2][4];
        const int c = lane & 3;
#pragma unroll
        for (int mt = 0; mt < 2; mt++) {
            int r = wm * 32 + mt * 16 + (lane >> 2);
            ah[mt][0] = ah_s[r * STR + c];
            ah[mt][1] = ah_s[(r + 8) * STR + c];
            ah[mt][2] = ah_s[r * STR + 4 + c];
            ah[mt][3] = ah_s[(r + 8) * STR + 4 + c];
            al[mt][0] = al_s[r * STR + c];
            al[mt][1] = al_s[(r + 8) * STR + c];
            al[mt][2] = al_s[r * STR + 4 + c];
            al[mt][3] = al_s[(r + 8) * STR + 4 + c];
        }
#pragma unroll
        for (int nt = 0; nt < 8; nt++) {
            int n = wn * 64 + nt * 8 + (lane >> 2);
            unsigned bh[2], bl[2];
            bh[0] = bh_s[n * STR + c];
            bh[1] = bh_s[n * STR + 4 + c];
            bl[0] = bl_s[n * STR + c];
            bl[1] = bl_s[n * STR + 4 + c];
#pragma unroll
            for (int mt = 0; mt < 2; mt++) {
                mma_bf16(acc[mt][nt], ah[mt], bh);
                mma_bf16(acc[mt][nt], ah[mt], bl);
                mma_bf16(acc[mt][nt], al[mt], bh);
            }
        }

        if (i + 3 < NT) load_stage((i + 3) & 3, (i + 3) * GBK);
        asm volatile("cp.async.commit_group;");
    }

    if (do_rope) {
#pragma unroll
        for (int mt = 0; mt < 2; mt++) {
            int r0 = by * 128 + wm * 32 + mt * 16 + (lane >> 2);
            int p0 = __ldg(pos + r0);
            int p1 = __ldg(pos + r0 + 8);
#pragma unroll
            for (int nt = 0; nt < 4; nt++) {
#pragma unroll
                for (int e = 0; e < 2; e++) {
                    int d = nt * 8 + 2 * (lane & 3) + e;
                    {
                        float c0 = __ldg(cos_t + p0 * HDIM + d);
                        float s0 = __ldg(sin_t + p0 * HDIM + d);
                        float c1 = __ldg(cos_t + p0 * HDIM + d + 32);
                        float s1 = __ldg(sin_t + p0 * HDIM + d + 32);
                        float x0 = acc[mt][nt][e];
                        float x1 = acc[mt][nt + 4][e];
                        acc[mt][nt][e]     = x0 * c0 - x1 * s0;
                        acc[mt][nt + 4][e] = x1 * c1 + x0 * s1;
                    }
                    {
                        float c0 = __ldg(cos_t + p1 * HDIM + d);
                        float s0 = __ldg(sin_t + p1 * HDIM + d);
                        float c1 = __ldg(cos_t + p1 * HDIM + d + 32);
                        float s1 = __ldg(sin_t + p1 * HDIM + d + 32);
                        float x0 = acc[mt][nt][e + 2];
                        float x1 = acc[mt][nt + 4][e + 2];
                        acc[mt][nt][e + 2]     = x0 * c0 - x1 * s0;
                        acc[mt][nt + 4][e + 2] = x1 * c1 + x0 * s1;
                    }
                }
            }
        }
    }

#pragma unroll
    for (int mt = 0; mt < 2; mt++) {
        int r0 = by * 128 + wm * 32 + mt * 16 + (lane >> 2);
#pragma unroll
        for (int nt = 0; nt < 8; nt++) {
            int cc = bx * 128 + wn * 64 + nt * 8 + ((lane & 3) << 1);
            size_t i0x = (size_t)r0 * DMODEL + cc;
            size_t i1x = (size_t)(r0 + 8) * DMODEL + cc;
            *(float2*)(C + i0x) = make_float2(acc[mt][nt][0], acc[mt][nt][1]);
            *(float2*)(C + i1x) = make_float2(acc[mt][nt][2], acc[mt][nt][3]);
            if (outBh) {
                float v0 = acc[mt][nt][0], v1 = acc[mt][nt][1];
                float v2 = acc[mt][nt][2], v3 = acc[mt][nt][3];
                float h0 = __bfloat162float(__float2bfloat16(v0));
                float h1 = __bfloat162float(__float2bfloat16(v1));
                float h2 = __bfloat162float(__float2bfloat16(v2));
                float h3 = __bfloat162float(__float2bfloat16(v3));
                *(unsigned*)((__nv_bfloat16*)outBh + i0x) = pack_bf16(v0, v1);
                *(unsigned*)((__nv_bfloat16*)outBl + i0x) = pack_bf16(v0 - h0, v1 - h1);
                *(unsigned*)((__nv_bfloat16*)outBh + i1x) = pack_bf16(v2, v3);
                *(unsigned*)((__nv_bfloat16*)outBl + i1x) = pack_bf16(v2 - h2, v3 - h3);
            }
        }
    }
}

__global__ __launch_bounds__(256, 2) void proj_kernel(const float* __restrict__ cos_t,
                                                      const float* __restrict__ sin_t,
                                                      const int* __restrict__ pos)
{
    int z = blockIdx.z;   // 0=Q(rope) 1=K(rope) 2=V
    __nv_bfloat16* oh = (z == 0) ? g_Qbh : (z == 1) ? g_Kbh : nullptr;
    __nv_bfloat16* ol = (z == 0) ? g_Qbl : (z == 1) ? g_Kbl : nullptr;
    gemm3_body(g_Bh, g_Bl,
               g_Bh + ACT_ELEMS + (size_t)z * W_ELEMS,
               g_Bl + ACT_ELEMS + (size_t)z * W_ELEMS,
               g_P + (size_t)z * ACT_ELEMS,
               oh, ol,
               z < 2, cos_t, sin_t, pos);
}

__global__ __launch_bounds__(256, 1) void out_gemm_kernel(float* __restrict__ out)
{
    gemm3_body(g_Bh, g_Bl,
               g_Bh + ACT_ELEMS + (size_t)3 * W_ELEMS,
               g_Bl + ACT_ELEMS + (size_t)3 * W_ELEMS,
               out, nullptr, nullptr, false, nullptr, nullptr, nullptr);
}

// ---------------------------------------------------------------------------
// KG/VG rows 0..3 only, split-K parallel (unchanged).
// ---------------------------------------------------------------------------
__global__ __launch_bounds__(256) void kgvg_part_kernel(const float* __restrict__ x,
                                                        const float* __restrict__ Wkg,
                                                        const float* __restrict__ Wvg)
{
    const int d = blockIdx.x * 256 + threadIdx.x;
    const int kz = blockIdx.y;
    __shared__ float xs[NGLOB][32];
    if (threadIdx.x < NGLOB * 32) {
        int t = threadIdx.x >> 5, k = threadIdx.x & 31;
        xs[t][k] = x[(size_t)t * DMODEL + kz * 32 + k];
    }
    __syncthreads();

    float ak[NGLOB] = {0.f, 0.f, 0.f, 0.f};
    float av[NGLOB] = {0.f, 0.f, 0.f, 0.f};
#pragma unroll 4
    for (int kk = 0; kk < 32; kk++) {
        size_t row = (size_t)(kz * 32 + kk) * DMODEL + d;
        float wk = __ldg(Wkg + row);
        float wv = __ldg(Wvg + row);
#pragma unroll
        for (int t = 0; t < NGLOB; t++) {
            ak[t] = fmaf(xs[t][kk], wk, ak[t]);
            av[t] = fmaf(xs[t][kk], wv, av[t]);
        }
    }
#pragma unroll
    for (int t = 0; t < NGLOB; t++) {
        g_KVGp[kz][0][t][d] = ak[t];
        g_KVGp[kz][1][t][d] = av[t];
    }
}

__global__ __launch_bounds__(256) void kgvg_reduce_kernel()
{
    int idx = blockIdx.x * 256 + threadIdx.x;
    int d = idx & (DMODEL - 1);
    int t = (idx >> 10) & 3;
    int m = idx >> 12;
    float s = 0.f;
#pragma unroll
    for (int kz = 0; kz < KGVG_KSPLIT; kz++) s += g_KVGp[kz][m][t][d];
    g_P[(size_t)(3 + m) * ACT_ELEMS + (size_t)t * DMODEL + d] = s;
}

// ---------------------------------------------------------------------------
// bf16x3 flash attention, double-buffered cp.async staging, register-resident
// P, fused global attention + bf16 O split epilogue.
// ---------------------------------------------------------------------------
#define ATS 36                       // padded row stride (32 data words + 4)
#define CHUNK_WORDS (64 * ATS)       // one operand array per stage
#define OFF_EXTRA (2 * 4 * CHUNK_WORDS)
#define ATT_SMEM_WORDS (OFF_EXTRA + HDIM + 2 * NGLOB * HDIM)

__global__ __launch_bounds__(128, 3) void attn_kernel()
{
    extern __shared__ unsigned smem_u[];
    float* Vg4 = (float*)(smem_u + OFF_EXTRA);
    float* KG4 = Vg4 + HDIM;
    float* VG4 = KG4 + NGLOB * HDIM;

    const int h  = blockIdx.x;
    const int i0 = blockIdx.y * 64;
    const int tid = threadIdx.x;
    const int lane = tid & 31;
    const int wq = tid >> 5;

    const float* Q = g_P;
    const float* V = g_P + (size_t)2 * ACT_ELEMS;

    if (tid < HDIM) {
        const float* vb = V + h * HDIM + tid;
        Vg4[tid] = vb[0] + vb[DMODEL] + vb[2 * DMODEL] + vb[3 * DMODEL];
    }
    for (int i2 = tid; i2 < 2 * NGLOB * HDIM; i2 += 128) {
        int mm = i2 >> 8;
        int t = (i2 >> 6) & 3;
        int c = i2 & 63;
        float val = g_P[(size_t)(3 + mm) * ACT_ELEMS + (size_t)t * DMODEL + h * HDIM + c];
        (mm ? VG4 : KG4)[t * HDIM + c] = val;
    }

    // Q A-fragments from pre-split bf16 (4 k-steps of 16)
    unsigned qh[4][4], ql[4][4];
    {
        const int r0 = i0 + wq * 16 + (lane >> 2);
        const int cb = h * HDIM + 2 * (lane & 3);
#pragma unroll
        for (int ks = 0; ks < 4; ks++) {
            size_t e00 = (size_t)r0 * DMODEL + cb + ks * 16;
            size_t e10 = (size_t)(r0 + 8) * DMODEL + cb + ks * 16;
            qh[ks][0] = *(const unsigned*)(g_Qbh + e00);
            qh[ks][1] = *(const unsigned*)(g_Qbh + e10);
            qh[ks][2] = *(const unsigned*)(g_Qbh + e00 + 8);
            qh[ks][3] = *(const unsigned*)(g_Qbh + e10 + 8);
            ql[ks][0] = *(const unsigned*)(g_Qbl + e00);
            ql[ks][1] = *(const unsigned*)(g_Qbl + e10);
            ql[ks][2] = *(const unsigned*)(g_Qbl + e00 + 8);
            ql[ks][3] = *(const unsigned*)(g_Qbl + e10 + 8);
        }
    }

    float out[8][4];
#pragma unroll
    for (int nt = 0; nt < 8; nt++)
#pragma unroll
        for (int e = 0; e < 4; e++) out[nt][e] = 0.f;
    float m0 = -3.4e38f, m1 = -3.4e38f, sum0 = 0.f, sum1 = 0.f;

    const int j_start = (i0 - RADIUS) > 0 ? (i0 - RADIUS) : 0;
    const int nchunks = (i0 + 64 - j_start) >> 6;

    auto load_chunk = [&](int st, int jc) {
        unsigned* base = smem_u + st * 4 * CHUNK_WORDS;
#pragma unroll
        for (int it = 0; it < 4; it++) {
            int idx = it * 128 + tid;       // 0..511
            int row = idx >> 3, ch = idx & 7;
            int so = row * ATS + ch * 4;
            size_t gk = (size_t)(jc + row) * DMODEL + h * HDIM + ch * 8;
            cpa16(base + so, g_Kbh + gk);
            cpa16(base + CHUNK_WORDS + so, g_Kbl + gk);
            size_t gv = (size_t)(h * HDIM + row) * S_LEN + jc + ch * 8;
            cpa16(base + 2 * CHUNK_WORDS + so, g_Vth + gv);
            cpa16(base + 3 * CHUNK_WORDS + so, g_Vtl + gv);
        }
    };

    load_chunk(0, j_start);
    asm volatile("cp.async.commit_group;");

#pragma unroll 1
    for (int ci = 0; ci < nchunks; ci++) {
        const int jc = j_start + ci * 64;
        const int st = ci & 1;
        __syncthreads();                      // prior compute on buf st done
        if (ci + 1 < nchunks) load_chunk(st ^ 1, jc + 64);
        asm volatile("cp.async.commit_group;");
        asm volatile("cp.async.wait_group 1;");
        __syncthreads();                      // buf st data visible to all

        unsigned* Kh_s = smem_u + st * 4 * CHUNK_WORDS;
        unsigned* Kl_s = Kh_s + CHUNK_WORDS;
        unsigned* Vh_s = Kh_s + 2 * CHUNK_WORDS;
        unsigned* Vl_s = Kh_s + 3 * CHUNK_WORDS;

        // ---- scores ----
        float sc[8][4];
#pragma unroll
        for (int nt = 0; nt < 8; nt++)
#pragma unroll
            for (int e = 0; e < 4; e++) sc[nt][e] = 0.f;

        const int c = lane & 3;
#pragma unroll
        for (int ks = 0; ks < 4; ks++) {
#pragma unroll
            for (int nt = 0; nt < 8; nt++) {
                int n = nt * 8 + (lane >> 2);
                int kw = ks * 8 + c;
                unsigned bh[2], bl[2];
                bh[0] = Kh_s[n * ATS + kw];
                bh[1] = Kh_s[n * ATS + kw + 4];
                bl[0] = Kl_s[n * ATS + kw];
                bl[1] = Kl_s[n * ATS + kw + 4];
                mma_bf16(sc[nt], qh[ks], bh);
                mma_bf16(sc[nt], qh[ks], bl);
                mma_bf16(sc[nt], ql[ks], bh);
            }
        }

        // ---- mask + online softmax ----
        const int ibase = i0 + wq * 16 + (lane >> 2);
        float mn0 = m0, mn1 = m1;
#pragma unroll
        for (int nt = 0; nt < 8; nt++) {
#pragma unroll
            for (int e = 0; e < 4; e++) {
                int i = ibase + ((e & 2) ? 8 : 0);
                int j = jc + nt * 8 + 2 * c + (e & 1);
                bool inw = (j <= i) && (i - j <= RADIUS);
                float raw = sc[nt][e] * 0.125f;
                float s;
                if (j < NGLOB) s = inw ? (raw + 1e9f) : 0.f;
                else           s = inw ? raw : -3.0e38f;
                sc[nt][e] = s;
                if (e & 2) mn1 = fmaxf(mn1, s); else mn0 = fmaxf(mn0, s);
            }
        }
#pragma unroll
        for (int o = 1; o < 4; o <<= 1) {
            mn0 = fmaxf(mn0, __shfl_xor_sync(0xffffffff, mn0, o));
            mn1 = fmaxf(mn1, __shfl_xor_sync(0xffffffff, mn1, o));
        }
        float esc0 = __expf(m0 - mn0);
        float esc1 = __expf(m1 - mn1);
        m0 = mn0; m1 = mn1;

        float ps0 = 0.f, ps1 = 0.f;
#pragma unroll
        for (int nt = 0; nt < 8; nt++) {
#pragma unroll
            for (int e = 0; e < 4; e++) {
                float p = __expf(sc[nt][e] - ((e & 2) ? m1 : m0));
                sc[nt][e] = p;
                if (e & 2) ps1 += p; else ps0 += p;
            }
        }
#pragma unroll
        for (int o = 1; o < 4; o <<= 1) {
            ps0 += __shfl_xor_sync(0xffffffff, ps0, o);
            ps1 += __shfl_xor_sync(0xffffffff, ps1, o);
        }
        sum0 = sum0 * esc0 + ps0;
        sum1 = sum1 * esc1 + ps1;
#pragma unroll
        for (int nt = 0; nt < 8; nt++) {
            out[nt][0] *= esc0; out[nt][1] *= esc0;
            out[nt][2] *= esc1; out[nt][3] *= esc1;
        }

        // ---- P·V: P stays in registers (accumulator == A-fragment layout) ----
#pragma unroll
        for (int ks2 = 0; ks2 < 4; ks2++) {
            float* s0v = sc[2 * ks2];
            float* s1v = sc[2 * ks2 + 1];
            float h00 = __bfloat162float(__float2bfloat16(s0v[0]));
            float h01 = __bfloat162float(__float2bfloat16(s0v[1]));
            float h02 = __bfloat162float(__float2bfloat16(s0v[2]));
            float h03 = __bfloat162float(__float2bfloat16(s0v[3]));
            float h10 = __bfloat162float(__float2bfloat16(s1v[0]));
            float h11 = __bfloat162float(__float2bfloat16(s1v[1]));
            float h12 = __bfloat162float(__float2bfloat16(s1v[2]));
            float h13 = __bfloat162float(__float2bfloat16(s1v[3]));
            unsigned ph[4], pl[4];
            ph[0] = pack_bf16(s0v[0], s0v[1]);
            ph[1] = pack_bf16(s0v[2], s0v[3]);
            ph[2] = pack_bf16(s1v[0], s1v[1]);
            ph[3] = pack_bf16(s1v[2], s1v[3]);
            pl[0] = pack_bf16(s0v[0] - h00, s0v[1] - h01);
            pl[1] = pack_bf16(s0v[2] - h02, s0v[3] - h03);
            pl[2] = pack_bf16(s1v[0] - h10, s1v[1] - h11);
            pl[3] = pack_bf16(s1v[2] - h12, s1v[3] - h13);
#pragma unroll
            for (int nt = 0; nt < 8; nt++) {
                int n = nt * 8 + (lane >> 2);     // output dim
                int kw = ks2 * 8 + c;             // key word offset
                unsigned vbh[2], vbl[2];
                vbh[0] = Vh_s[n * ATS + kw];
                vbh[1] = Vh_s[n * ATS + kw + 4];
                vbl[0] = Vl_s[n * ATS + kw];
                vbl[1] = Vl_s[n * ATS + kw + 4];
                mma_bf16(out[nt], ph, vbh);
                mma_bf16(out[nt], ph, vbl);
                mma_bf16(out[nt], pl, vbh);
            }
        }
    }

    if (j_start > 0) {
        float mn0 = fmaxf(m0, 0.f), mn1 = fmaxf(m1, 0.f);
        float esc0 = __expf(m0 - mn0), esc1 = __expf(m1 - mn1);
        float e0 = __expf(0.f - mn0), e1 = __expf(0.f - mn1);
        sum0 = sum0 * esc0 + 4.f * e0;
        sum1 = sum1 * esc1 + 4.f * e1;
#pragma unroll
        for (int nt = 0; nt < 8; nt++) {
            int col = nt * 8 + 2 * (lane & 3);
            out[nt][0] = out[nt][0] * esc0 + e0 * Vg4[col];
            out[nt][1] = out[nt][1] * esc0 + e0 * Vg4[col + 1];
            out[nt][2] = out[nt][2] * esc1 + e1 * Vg4[col];
            out[nt][3] = out[nt][3] * esc1 + e1 * Vg4[col + 1];
        }
    }

    float inv0 = 1.f / sum0, inv1 = 1.f / sum1;
    const int r0 = i0 + wq * 16 + (lane >> 2);

    // ---- fused global attention (exact fp32 Q reload) ----
    float w[2][4], deninv[2];
#pragma unroll
    for (int rr = 0; rr < 2; rr++) {
        int r = r0 + rr * 8;
        const float* qp = Q + (size_t)r * DMODEL + h * HDIM;
        float dot[4] = {0.f, 0.f, 0.f, 0.f};
#pragma unroll
        for (int ks = 0; ks < 8; ks++) {
#pragma unroll
            for (int e2 = 0; e2 < 2; e2++) {
                int cc = ks * 8 + (lane & 3) + e2 * 4;
                float qv = qp[cc];
#pragma unroll
                for (int t = 0; t < 4; t++)
                    dot[t] = fmaf(qv, KG4[t * HDIM + cc], dot[t]);
            }
        }
#pragma unroll
        for (int t = 0; t < 4; t++) {
#pragma unroll
            for (int o = 1; o < 4; o <<= 1)
                dot[t] += __shfl_xor_sync(0xffffffff, dot[t], o);
            dot[t] *= 0.125f;
        }
        float mg = fmaxf(fmaxf(dot[0], dot[1]), fmaxf(dot[2], dot[3]));
        float den = 0.f;
#pragma unroll
        for (int t = 0; t < 4; t++) { w[rr][t] = __expf(dot[t] - mg); den += w[rr][t]; }
        deninv[rr] = 1.f / den;
    }

    // ---- combine + bf16 hi/lo split directly into out_gemm operand ----
#pragma unroll
    for (int nt = 0; nt < 8; nt++) {
#pragma unroll
        for (int e = 0; e < 4; e++) {
            int rr = (e & 2) ? 1 : 0;
            int col = nt * 8 + 2 * (lane & 3) + (e & 1);
            float g = (w[rr][0] * VG4[0 * HDIM + col] + w[rr][1] * VG4[1 * HDIM + col] +
                       w[rr][2] * VG4[2 * HDIM + col] + w[rr][3] * VG4[3 * HDIM + col]) * deninv[rr];
            float v = out[nt][e] * (rr ? inv1 : inv0) + g;
            size_t idx = (size_t)(r0 + rr * 8) * DMODEL + h * HDIM + col;
            __nv_bfloat16 hb = __float2bfloat16(v);
            g_Bh[idx] = hb;
            g_Bl[idx] = __float2bfloat16(v - __bfloat162float(hb));
        }
    }
}

// ---------------------------------------------------------------------------
// launch
// ---------------------------------------------------------------------------
extern "C" void kernel_launch(void* const* d_in, const int* in_sizes, int n_in,
                              void* d_out, int out_size)
{
    const float* x     = (const float*)d_in[0];
    const float* cos_t = (const float*)d_in[1];
    const float* sin_t = (const float*)d_in[2];
    const int*   pos   = (const int*)d_in[3];
    P4 ws;
    ws.p[0] = (const float*)d_in[4];    // Wqs
    ws.p[1] = (const float*)d_in[5];    // Wks
    ws.p[2] = (const float*)d_in[6];    // Wvs
    ws.p[3] = (const float*)d_in[10];   // Wo
    const float* Wkg = (const float*)d_in[8];
    const float* Wvg = (const float*)d_in[9];
    float* out = (float*)d_out;

    static int attrs_set = 0;
    int attn_smem = ATT_SMEM_WORDS * 4;
    if (!attrs_set) {
        cudaFuncSetAttribute(attn_kernel,
                             cudaFuncAttributeMaxDynamicSharedMemorySize, attn_smem);
        cudaFuncSetAttribute(proj_kernel,
                             cudaFuncAttributeMaxDynamicSharedMemorySize, GEMM_SMEM_BYTES);
        cudaFuncSetAttribute(out_gemm_kernel,
                             cudaFuncAttributeMaxDynamicSharedMemorySize, GEMM_SMEM_BYTES);
        attrs_set = 1;
    }

    __nv_bfloat16* Bh;
    __nv_bfloat16* Bl;
    cudaGetSymbolAddress((void**)&Bh, g_Bh);
    cudaGetSymbolAddress((void**)&Bl, g_Bl);

    split_x_kernel<<<(ACT_ELEMS / 4 + 255) / 256, 256>>>(x, Bh, Bl, ACT_ELEMS / 4);
    dim3 gw(DMODEL / 32, DMODEL / 32, 4);
    split_wt_kernel<<<gw, 256>>>(ws, Bh, Bl);

    dim3 gkg(DMODEL / 256, KGVG_KSPLIT);
    kgvg_part_kernel<<<gkg, 256>>>(x, Wkg, Wvg);
    kgvg_reduce_kernel<<<(2 * NGLOB * DMODEL) / 256, 256>>>();

    dim3 gp(DMODEL / 128, S_LEN / 128, 3);
    proj_kernel<<<gp, 256, GEMM_SMEM_BYTES>>>(cos_t, sin_t, pos);

    dim3 gvt(S_LEN / 32, DMODEL / 32);
    vt_split_kernel<<<gvt, 256>>>();

    dim3 ga(NHEADS, S_LEN / 64);
    attn_kernel<<<ga, 128, attn_smem>>>();

    dim3 go(DMODEL / 128, S_LEN / 128);
    out_gemm_kernel<<<go, 256, GEMM_SMEM_BYTES>>>(out);
}

// round 10
// speedup vs baseline: 2.4555x; 1.1083x over previous
#include <cuda_runtime.h>
#include <cuda_bf16.h>
#include <math.h>

#define S_LEN 2048
#define DMODEL 1024
#define NHEADS 16
#define HDIM 64
#define RADIUS 256
#define NGLOB 4

__device__ float g_P[(size_t)5 * S_LEN * DMODEL];

#define KGVG_KSPLIT 32
__device__ float g_KVGp[KGVG_KSPLIT][2][NGLOB][DMODEL];

#define ACT_ELEMS (S_LEN * DMODEL)
#define W_ELEMS   (DMODEL * DMODEL)
// GEMM operand splits: [0:ACT) activations (x, later O), then 4 weights transposed [n][k]
__device__ __nv_bfloat16 g_Bh[(size_t)ACT_ELEMS + 4 * W_ELEMS];
__device__ __nv_bfloat16 g_Bl[(size_t)ACT_ELEMS + 4 * W_ELEMS];
// attention operand splits (post-rope): Q,K in [s][d]; V transposed [d][s]
__device__ __nv_bfloat16 g_Qbh[ACT_ELEMS], g_Qbl[ACT_ELEMS];
__device__ __nv_bfloat16 g_Kbh[ACT_ELEMS], g_Kbl[ACT_ELEMS];
__device__ __nv_bfloat16 g_Vth[ACT_ELEMS], g_Vtl[ACT_ELEMS];

struct P4 { const float* p[4]; };

__device__ __forceinline__ void mma_bf16(float* c, const unsigned* a, const unsigned* b) {
    asm volatile(
        "mma.sync.aligned.m16n8k16.row.col.f32.bf16.bf16.f32 "
        "{%0,%1,%2,%3}, {%4,%5,%6,%7}, {%8,%9}, {%0,%1,%2,%3};"
        : "+f"(c[0]), "+f"(c[1]), "+f"(c[2]), "+f"(c[3])
        : "r"(a[0]), "r"(a[1]), "r"(a[2]), "r"(a[3]), "r"(b[0]), "r"(b[1]));
}

#define LDSM4(r, addr) \
    asm volatile("ldmatrix.sync.aligned.m8n8.x4.shared.b16 {%0,%1,%2,%3}, [%4];" \
        : "=r"((r)[0]), "=r"((r)[1]), "=r"((r)[2]), "=r"((r)[3]) : "r"(addr))

__device__ __forceinline__ void cpa16(void* dst, const void* src) {
    unsigned s = (unsigned)__cvta_generic_to_shared(dst);
    asm volatile("cp.async.cg.shared.global [%0], [%1], 16;" :: "r"(s), "l"(src));
}

__device__ __forceinline__ unsigned pack_bf16(float a, float b) {
    __nv_bfloat162 t = __floats2bfloat162_rn(a, b);
    return *reinterpret_cast<unsigned*>(&t);
}

// ---------------------------------------------------------------------------
// split kernels
// ---------------------------------------------------------------------------
__global__ __launch_bounds__(256) void split_x_kernel(const float* __restrict__ src,
                                                      __nv_bfloat16* __restrict__ h,
                                                      __nv_bfloat16* __restrict__ l, int n4)
{
    int i = blockIdx.x * blockDim.x + threadIdx.x;
    if (i >= n4) return;
    float4 v = ((const float4*)src)[i];
    float f[4] = {v.x, v.y, v.z, v.w};
    ushort4 hv, lv;
    unsigned short* hp = &hv.x;
    unsigned short* lp = &lv.x;
#pragma unroll
    for (int e = 0; e < 4; e++) {
        __nv_bfloat16 hb = __float2bfloat16(f[e]);
        hp[e] = *reinterpret_cast<unsigned short*>(&hb);
        __nv_bfloat16 lb = __float2bfloat16(f[e] - __bfloat162float(hb));
        lp[e] = *reinterpret_cast<unsigned short*>(&lb);
    }
    ((ushort4*)h)[i] = hv;
    ((ushort4*)l)[i] = lv;
}

__global__ __launch_bounds__(256) void split_wt_kernel(P4 srcs,
                                                       __nv_bfloat16* __restrict__ hbase,
                                                       __nv_bfloat16* __restrict__ lbase)
{
    __shared__ float t[32][33];
    const int z = blockIdx.z;
    const float* W = srcs.p[z];
    const int n0 = blockIdx.x * 32, k0 = blockIdx.y * 32;
    const int tx = threadIdx.x & 31, ty = threadIdx.x >> 5;

#pragma unroll
    for (int j = 0; j < 4; j++)
        t[ty + j * 8][tx] = W[(size_t)(k0 + ty + j * 8) * DMODEL + n0 + tx];
    __syncthreads();

    size_t base = (size_t)ACT_ELEMS + (size_t)z * W_ELEMS;
#pragma unroll
    for (int j = 0; j < 4; j++) {
        int n = n0 + ty + j * 8;
        int k = k0 + tx;
        float v = t[tx][ty + j * 8];
        __nv_bfloat16 hb = __float2bfloat16(v);
        size_t idx = base + (size_t)n * DMODEL + k;
        hbase[idx] = hb;
        lbase[idx] = __float2bfloat16(v - __bfloat162float(hb));
    }
}

// V[s][d] (g_P slot 2) -> Vt bf16 hi/lo [d][s]
__global__ __launch_bounds__(256) void vt_split_kernel()
{
    __shared__ float t[32][33];
    const int s0 = blockIdx.x * 32, d0 = blockIdx.y * 32;
    const int tx = threadIdx.x & 31, ty = threadIdx.x >> 5;

#pragma unroll
    for (int j = 0; j < 4; j++)
        t[ty + j * 8][tx] = g_P[(size_t)2 * ACT_ELEMS + (size_t)(s0 + ty + j * 8) * DMODEL + d0 + tx];
    __syncthreads();

#pragma unroll
    for (int j = 0; j < 4; j++) {
        int d = d0 + ty + j * 8;
        int s = s0 + tx;
        float v = t[tx][ty + j * 8];
        __nv_bfloat16 hb = __float2bfloat16(v);
        size_t idx = (size_t)d * S_LEN + s;
        g_Vth[idx] = hb;
        g_Vtl[idx] = __float2bfloat16(v - __bfloat162float(hb));
    }
}

// ---------------------------------------------------------------------------
// 3xBF16 GEMM (m16n8k16) with ldmatrix fragments, 4-stage cp.async pipeline,
// fused RoPE, optional bf16 hi/lo epilogue.
// ---------------------------------------------------------------------------
#define GBK 16
#define STR 12
#define TILE_WORDS (128 * STR)
#define TILE_BYTES (TILE_WORDS * 4)
#define NSTAGE 4
#define GEMM_SMEM_BYTES (NSTAGE * 4 * TILE_BYTES)

__device__ __forceinline__ void gemm3_body(const __nv_bfloat16* __restrict__ Agh,
                                           const __nv_bfloat16* __restrict__ Agl,
                                           const __nv_bfloat16* __restrict__ Bgh,
                                           const __nv_bfloat16* __restrict__ Bgl,
                                           float* __restrict__ C,
                                           __nv_bfloat16* __restrict__ outBh,
                                           __nv_bfloat16* __restrict__ outBl,
                                           bool do_rope,
                                           const float* __restrict__ cos_t,
                                           const float* __restrict__ sin_t,
                                           const int* __restrict__ pos)
{
    extern __shared__ unsigned sm[];
    unsigned* uAh = sm;
    unsigned* uAl = sm + NSTAGE * TILE_WORDS;
    unsigned* uBh = sm + 2 * NSTAGE * TILE_WORDS;
    unsigned* uBl = sm + 3 * NSTAGE * TILE_WORDS;

    const int tid = threadIdx.x;
    const int lane = tid & 31;
    const int warp = tid >> 5;
    const int wm = warp >> 1;
    const int wn = warp & 1;
    const int bx = blockIdx.x, by = blockIdx.y;

    float acc[2][8][4];
#pragma unroll
    for (int mt = 0; mt < 2; mt++)
#pragma unroll
        for (int nt = 0; nt < 8; nt++)
#pragma unroll
            for (int e = 0; e < 4; e++) acc[mt][nt][e] = 0.f;

    const int m_ = tid >> 1;
    const int half = tid & 1;

    auto load_stage = [&](int st, int k0) {
        unsigned* ah = uAh + st * TILE_WORDS;
        unsigned* al = uAl + st * TILE_WORDS;
        unsigned* bh = uBh + st * TILE_WORDS;
        unsigned* bl = uBl + st * TILE_WORDS;
        size_t ga = (size_t)(by * 128 + m_) * DMODEL + k0 + half * 8;
        size_t gb = (size_t)(bx * 128 + m_) * DMODEL + k0 + half * 8;
        int so = m_ * STR + half * 4;
        cpa16(ah + so, Agh + ga);
        cpa16(al + so, Agl + ga);
        cpa16(bh + so, Bgh + gb);
        cpa16(bl + so, Bgl + gb);
    };

    // ldmatrix lane-relative byte offsets
    const unsigned uAhS = (unsigned)__cvta_generic_to_shared(uAh);
    const unsigned uAlS = (unsigned)__cvta_generic_to_shared(uAl);
    const unsigned uBhS = (unsigned)__cvta_generic_to_shared(uBh);
    const unsigned uBlS = (unsigned)__cvta_generic_to_shared(uBl);
    unsigned aRel[2], bRel[4];
#pragma unroll
    for (int mt = 0; mt < 2; mt++)
        aRel[mt] = (unsigned)(((wm * 32 + mt * 16 + (lane & 15)) * STR) * 4 +
                              ((lane & 16) ? 16 : 0));
#pragma unroll
    for (int ntp = 0; ntp < 4; ntp++)
        bRel[ntp] = (unsigned)(((wn * 64 + ntp * 16 + ((lane & 16) ? 8 : 0) + (lane & 7)) * STR) * 4 +
                               ((lane & 8) ? 16 : 0));

    load_stage(0, 0);
    asm volatile("cp.async.commit_group;");
    load_stage(1, GBK);
    asm volatile("cp.async.commit_group;");
    load_stage(2, 2 * GBK);
    asm volatile("cp.async.commit_group;");

    const int NT = DMODEL / GBK;
#pragma unroll 1
    for (int i = 0; i < NT; i++) {
        int st = i & 3;
        asm volatile("cp.async.wait_group 2;");
        __syncthreads();

        const unsigned stB = (unsigned)(st * TILE_BYTES);

        unsigned ah[2][4], al[2][4];
#pragma unroll
        for (int mt = 0; mt < 2; mt++) {
            LDSM4(ah[mt], uAhS + stB + aRel[mt]);
            LDSM4(al[mt], uAlS + stB + aRel[mt]);
        }
        unsigned bh4[4][4], bl4[4][4];
#pragma unroll
        for (int ntp = 0; ntp < 4; ntp++) {
            LDSM4(bh4[ntp], uBhS + stB + bRel[ntp]);
            LDSM4(bl4[ntp], uBlS + stB + bRel[ntp]);
        }
#pragma unroll
        for (int ntp = 0; ntp < 4; ntp++) {
#pragma unroll
            for (int s = 0; s < 2; s++) {
                int nt = 2 * ntp + s;
                unsigned bhp[2] = {bh4[ntp][2 * s], bh4[ntp][2 * s + 1]};
                unsigned blp[2] = {bl4[ntp][2 * s], bl4[ntp][2 * s + 1]};
#pragma unroll
                for (int mt = 0; mt < 2; mt++) {
                    mma_bf16(acc[mt][nt], ah[mt], bhp);
                    mma_bf16(acc[mt][nt], ah[mt], blp);
                    mma_bf16(acc[mt][nt], al[mt], bhp);
                }
            }
        }

        if (i + 3 < NT) load_stage((i + 3) & 3, (i + 3) * GBK);
        asm volatile("cp.async.commit_group;");
    }

    if (do_rope) {
#pragma unroll
        for (int mt = 0; mt < 2; mt++) {
            int r0 = by * 128 + wm * 32 + mt * 16 + (lane >> 2);
            int p0 = __ldg(pos + r0);
            int p1 = __ldg(pos + r0 + 8);
#pragma unroll
            for (int nt = 0; nt < 4; nt++) {
#pragma unroll
                for (int e = 0; e < 2; e++) {
                    int d = nt * 8 + 2 * (lane & 3) + e;
                    {
                        float c0 = __ldg(cos_t + p0 * HDIM + d);
                        float s0 = __ldg(sin_t + p0 * HDIM + d);
                        float c1 = __ldg(cos_t + p0 * HDIM + d + 32);
                        float s1 = __ldg(sin_t + p0 * HDIM + d + 32);
                        float x0 = acc[mt][nt][e];
                        float x1 = acc[mt][nt + 4][e];
                        acc[mt][nt][e]     = x0 * c0 - x1 * s0;
                        acc[mt][nt + 4][e] = x1 * c1 + x0 * s1;
                    }
                    {
                        float c0 = __ldg(cos_t + p1 * HDIM + d);
                        float s0 = __ldg(sin_t + p1 * HDIM + d);
                        float c1 = __ldg(cos_t + p1 * HDIM + d + 32);
                        float s1 = __ldg(sin_t + p1 * HDIM + d + 32);
                        float x0 = acc[mt][nt][e + 2];
                        float x1 = acc[mt][nt + 4][e + 2];
                        acc[mt][nt][e + 2]     = x0 * c0 - x1 * s0;
                        acc[mt][nt + 4][e + 2] = x1 * c1 + x0 * s1;
                    }
                }
            }
        }
    }

#pragma unroll
    for (int mt = 0; mt < 2; mt++) {
        int r0 = by * 128 + wm * 32 + mt * 16 + (lane >> 2);
#pragma unroll
        for (int nt = 0; nt < 8; nt++) {
            int cc = bx * 128 + wn * 64 + nt * 8 + ((lane & 3) << 1);
            size_t i0x = (size_t)r0 * DMODEL + cc;
            size_t i1x = (size_t)(r0 + 8) * DMODEL + cc;
            *(float2*)(C + i0x) = make_float2(acc[mt][nt][0], acc[mt][nt][1]);
            *(float2*)(C + i1x) = make_float2(acc[mt][nt][2], acc[mt][nt][3]);
            if (outBh) {
                float v0 = acc[mt][nt][0], v1 = acc[mt][nt][1];
                float v2 = acc[mt][nt][2], v3 = acc[mt][nt][3];
                float h0 = __bfloat162float(__float2bfloat16(v0));
                float h1 = __bfloat162float(__float2bfloat16(v1));
                float h2 = __bfloat162float(__float2bfloat16(v2));
                float h3 = __bfloat162float(__float2bfloat16(v3));
                *(unsigned*)((__nv_bfloat16*)outBh + i0x) = pack_bf16(v0, v1);
                *(unsigned*)((__nv_bfloat16*)outBl + i0x) = pack_bf16(v0 - h0, v1 - h1);
                *(unsigned*)((__nv_bfloat16*)outBh + i1x) = pack_bf16(v2, v3);
                *(unsigned*)((__nv_bfloat16*)outBl + i1x) = pack_bf16(v2 - h2, v3 - h3);
            }
        }
    }
}

__global__ __launch_bounds__(256, 2) void proj_kernel(const float* __restrict__ cos_t,
                                                      const float* __restrict__ sin_t,
                                                      const int* __restrict__ pos)
{
    int z = blockIdx.z;   // 0=Q(rope) 1=K(rope) 2=V
    __nv_bfloat16* oh = (z == 0) ? g_Qbh : (z == 1) ? g_Kbh : nullptr;
    __nv_bfloat16* ol = (z == 0) ? g_Qbl : (z == 1) ? g_Kbl : nullptr;
    gemm3_body(g_Bh, g_Bl,
               g_Bh + ACT_ELEMS + (size_t)z * W_ELEMS,
               g_Bl + ACT_ELEMS + (size_t)z * W_ELEMS,
               g_P + (size_t)z * ACT_ELEMS,
               oh, ol,
               z < 2, cos_t, sin_t, pos);
}

__global__ __launch_bounds__(256, 1) void out_gemm_kernel(float* __restrict__ out)
{
    gemm3_body(g_Bh, g_Bl,
               g_Bh + ACT_ELEMS + (size_t)3 * W_ELEMS,
               g_Bl + ACT_ELEMS + (size_t)3 * W_ELEMS,
               out, nullptr, nullptr, false, nullptr, nullptr, nullptr);
}

// ---------------------------------------------------------------------------
// KG/VG rows 0..3 only, split-K parallel (unchanged).
// ---------------------------------------------------------------------------
__global__ __launch_bounds__(256) void kgvg_part_kernel(const float* __restrict__ x,
                                                        const float* __restrict__ Wkg,
                                                        const float* __restrict__ Wvg)
{
    const int d = blockIdx.x * 256 + threadIdx.x;
    const int kz = blockIdx.y;
    __shared__ float xs[NGLOB][32];
    if (threadIdx.x < NGLOB * 32) {
        int t = threadIdx.x >> 5, k = threadIdx.x & 31;
        xs[t][k] = x[(size_t)t * DMODEL + kz * 32 + k];
    }
    __syncthreads();

    float ak[NGLOB] = {0.f, 0.f, 0.f, 0.f};
    float av[NGLOB] = {0.f, 0.f, 0.f, 0.f};
#pragma unroll 4
    for (int kk = 0; kk < 32; kk++) {
        size_t row = (size_t)(kz * 32 + kk) * DMODEL + d;
        float wk = __ldg(Wkg + row);
        float wv = __ldg(Wvg + row);
#pragma unroll
        for (int t = 0; t < NGLOB; t++) {
            ak[t] = fmaf(xs[t][kk], wk, ak[t]);
            av[t] = fmaf(xs[t][kk], wv, av[t]);
        }
    }
#pragma unroll
    for (int t = 0; t < NGLOB; t++) {
        g_KVGp[kz][0][t][d] = ak[t];
        g_KVGp[kz][1][t][d] = av[t];
    }
}

__global__ __launch_bounds__(256) void kgvg_reduce_kernel()
{
    int idx = blockIdx.x * 256 + threadIdx.x;
    int d = idx & (DMODEL - 1);
    int t = (idx >> 10) & 3;
    int m = idx >> 12;
    float s = 0.f;
#pragma unroll
    for (int kz = 0; kz < KGVG_KSPLIT; kz++) s += g_KVGp[kz][m][t][d];
    g_P[(size_t)(3 + m) * ACT_ELEMS + (size_t)t * DMODEL + d] = s;
}

// ---------------------------------------------------------------------------
// bf16x3 flash attention with ldmatrix fragments, double-buffered cp.async
// staging, register-resident P, fused global attn + bf16 O split epilogue.
// ---------------------------------------------------------------------------
#define ATS 36
#define CHUNK_WORDS (64 * ATS)
#define OFF_EXTRA (2 * 4 * CHUNK_WORDS)
#define ATT_SMEM_WORDS (OFF_EXTRA + HDIM + 2 * NGLOB * HDIM)

__global__ __launch_bounds__(128, 3) void attn_kernel()
{
    extern __shared__ unsigned smem_u[];
    float* Vg4 = (float*)(smem_u + OFF_EXTRA);
    float* KG4 = Vg4 + HDIM;
    float* VG4 = KG4 + NGLOB * HDIM;

    const int h  = blockIdx.x;
    const int i0 = blockIdx.y * 64;
    const int tid = threadIdx.x;
    const int lane = tid & 31;
    const int wq = tid >> 5;

    const float* Q = g_P;
    const float* V = g_P + (size_t)2 * ACT_ELEMS;

    if (tid < HDIM) {
        const float* vb = V + h * HDIM + tid;
        Vg4[tid] = vb[0] + vb[DMODEL] + vb[2 * DMODEL] + vb[3 * DMODEL];
    }
    for (int i2 = tid; i2 < 2 * NGLOB * HDIM; i2 += 128) {
        int mm = i2 >> 8;
        int t = (i2 >> 6) & 3;
        int c = i2 & 63;
        float val = g_P[(size_t)(3 + mm) * ACT_ELEMS + (size_t)t * DMODEL + h * HDIM + c];
        (mm ? VG4 : KG4)[t * HDIM + c] = val;
    }

    // Q A-fragments from pre-split bf16 (4 k-steps of 16)
    unsigned qh[4][4], ql[4][4];
    {
        const int r0 = i0 + wq * 16 + (lane >> 2);
        const int cb = h * HDIM + 2 * (lane & 3);
#pragma unroll
        for (int ks = 0; ks < 4; ks++) {
            size_t e00 = (size_t)r0 * DMODEL + cb + ks * 16;
            size_t e10 = (size_t)(r0 + 8) * DMODEL + cb + ks * 16;
            qh[ks][0] = *(const unsigned*)(g_Qbh + e00);
            qh[ks][1] = *(const unsigned*)(g_Qbh + e10);
            qh[ks][2] = *(const unsigned*)(g_Qbh + e00 + 8);
            qh[ks][3] = *(const unsigned*)(g_Qbh + e10 + 8);
            ql[ks][0] = *(const unsigned*)(g_Qbl + e00);
            ql[ks][1] = *(const unsigned*)(g_Qbl + e10);
            ql[ks][2] = *(const unsigned*)(g_Qbl + e00 + 8);
            ql[ks][3] = *(const unsigned*)(g_Qbl + e10 + 8);
        }
    }

    float out[8][4];
#pragma unroll
    for (int nt = 0; nt < 8; nt++)
#pragma unroll
        for (int e = 0; e < 4; e++) out[nt][e] = 0.f;
    float m0 = -3.4e38f, m1 = -3.4e38f, sum0 = 0.f, sum1 = 0.f;

    const int j_start = (i0 - RADIUS) > 0 ? (i0 - RADIUS) : 0;
    const int nchunks = (i0 + 64 - j_start) >> 6;

    auto load_chunk = [&](int st, int jc) {
        unsigned* base = smem_u + st * 4 * CHUNK_WORDS;
#pragma unroll
        for (int it = 0; it < 4; it++) {
            int idx = it * 128 + tid;
            int row = idx >> 3, ch = idx & 7;
            int so = row * ATS + ch * 4;
            size_t gk = (size_t)(jc + row) * DMODEL + h * HDIM + ch * 8;
            cpa16(base + so, g_Kbh + gk);
            cpa16(base + CHUNK_WORDS + so, g_Kbl + gk);
            size_t gv = (size_t)(h * HDIM + row) * S_LEN + jc + ch * 8;
            cpa16(base + 2 * CHUNK_WORDS + so, g_Vth + gv);
            cpa16(base + 3 * CHUNK_WORDS + so, g_Vtl + gv);
        }
    };

    // ldmatrix lane-relative offsets (n-tile pairs over 64 rows)
    const unsigned smemS = (unsigned)__cvta_generic_to_shared(smem_u);
    unsigned bRelA[4];
#pragma unroll
    for (int ntp = 0; ntp < 4; ntp++)
        bRelA[ntp] = (unsigned)(((ntp * 16 + ((lane & 16) ? 8 : 0) + (lane & 7)) * ATS) * 4 +
                                ((lane & 8) ? 16 : 0));

    load_chunk(0, j_start);
    asm volatile("cp.async.commit_group;");

#pragma unroll 1
    for (int ci = 0; ci < nchunks; ci++) {
        const int jc = j_start + ci * 64;
        const int st = ci & 1;
        __syncthreads();
        if (ci + 1 < nchunks) load_chunk(st ^ 1, jc + 64);
        asm volatile("cp.async.commit_group;");
        asm volatile("cp.async.wait_group 1;");
        __syncthreads();

        const unsigned KhS = smemS + (unsigned)(st * 4 * CHUNK_WORDS * 4);
        const unsigned KlS = KhS + CHUNK_WORDS * 4;
        const unsigned VhS = KhS + 2 * CHUNK_WORDS * 4;
        const unsigned VlS = KhS + 3 * CHUNK_WORDS * 4;

        // ---- scores ----
        float sc[8][4];
#pragma unroll
        for (int nt = 0; nt < 8; nt++)
#pragma unroll
            for (int e = 0; e < 4; e++) sc[nt][e] = 0.f;

#pragma unroll
        for (int ks = 0; ks < 4; ks++) {
#pragma unroll
            for (int ntp = 0; ntp < 4; ntp++) {
                unsigned kb[4], kbl[4];
                LDSM4(kb,  KhS + bRelA[ntp] + ks * 32);
                LDSM4(kbl, KlS + bRelA[ntp] + ks * 32);
#pragma unroll
                for (int s = 0; s < 2; s++) {
                    int nt = 2 * ntp + s;
                    unsigned bhp[2] = {kb[2 * s], kb[2 * s + 1]};
                    unsigned blp[2] = {kbl[2 * s], kbl[2 * s + 1]};
                    mma_bf16(sc[nt], qh[ks], bhp);
                    mma_bf16(sc[nt], qh[ks], blp);
                    mma_bf16(sc[nt], ql[ks], bhp);
                }
            }
        }

        // ---- mask + online softmax ----
        const int c = lane & 3;
        const int ibase = i0 + wq * 16 + (lane >> 2);
        float mn0 = m0, mn1 = m1;
#pragma unroll
        for (int nt = 0; nt < 8; nt++) {
#pragma unroll
            for (int e = 0; e < 4; e++) {
                int i = ibase + ((e & 2) ? 8 : 0);
                int j = jc + nt * 8 + 2 * c + (e & 1);
                bool inw = (j <= i) && (i - j <= RADIUS);
                float raw = sc[nt][e] * 0.125f;
                float s;
                if (j < NGLOB) s = inw ? (raw + 1e9f) : 0.f;
                else           s = inw ? raw : -3.0e38f;
                sc[nt][e] = s;
                if (e & 2) mn1 = fmaxf(mn1, s); else mn0 = fmaxf(mn0, s);
            }
        }
#pragma unroll
        for (int o = 1; o < 4; o <<= 1) {
            mn0 = fmaxf(mn0, __shfl_xor_sync(0xffffffff, mn0, o));
            mn1 = fmaxf(mn1, __shfl_xor_sync(0xffffffff, mn1, o));
        }
        float esc0 = __expf(m0 - mn0);
        float esc1 = __expf(m1 - mn1);
        m0 = mn0; m1 = mn1;

        float ps0 = 0.f, ps1 = 0.f;
#pragma unroll
        for (int nt = 0; nt < 8; nt++) {
#pragma unroll
            for (int e = 0; e < 4; e++) {
                float p = __expf(sc[nt][e] - ((e & 2) ? m1 : m0));
                sc[nt][e] = p;
                if (e & 2) ps1 += p; else ps0 += p;
            }
        }
#pragma unroll
        for (int o = 1; o < 4; o <<= 1) {
            ps0 += __shfl_xor_sync(0xffffffff, ps0, o);
            ps1 += __shfl_xor_sync(0xffffffff, ps1, o);
        }
        sum0 = sum0 * esc0 + ps0;
        sum1 = sum1 * esc1 + ps1;
#pragma unroll
        for (int nt = 0; nt < 8; nt++) {
            out[nt][0] *= esc0; out[nt][1] *= esc0;
            out[nt][2] *= esc1; out[nt][3] *= esc1;
        }

        // ---- P·V: P stays in registers ----
#pragma unroll
        for (int ks2 = 0; ks2 < 4; ks2++) {
            float* s0v = sc[2 * ks2];
            float* s1v = sc[2 * ks2 + 1];
            float h00 = __bfloat162float(__float2bfloat16(s0v[0]));
            float h01 = __bfloat162float(__float2bfloat16(s0v[1]));
            float h02 = __bfloat162float(__float2bfloat16(s0v[2]));
            float h03 = __bfloat162float(__float2bfloat16(s0v[3]));
            float h10 = __bfloat162float(__float2bfloat16(s1v[0]));
            float h11 = __bfloat162float(__float2bfloat16(s1v[1]));
            float h12 = __bfloat162float(__float2bfloat16(s1v[2]));
            float h13 = __bfloat162float(__float2bfloat16(s1v[3]));
            unsigned ph[4], pl[4];
            ph[0] = pack_bf16(s0v[0], s0v[1]);
            ph[1] = pack_bf16(s0v[2], s0v[3]);
            ph[2] = pack_bf16(s1v[0], s1v[1]);
            ph[3] = pack_bf16(s1v[2], s1v[3]);
            pl[0] = pack_bf16(s0v[0] - h00, s0v[1] - h01);
            pl[1] = pack_bf16(s0v[2] - h02, s0v[3] - h03);
            pl[2] = pack_bf16(s1v[0] - h10, s1v[1] - h11);
            pl[3] = pack_bf16(s1v[2] - h12, s1v[3] - h13);
#pragma unroll
            for (int ntp = 0; ntp < 4; ntp++) {
                unsigned vb4[4], vbl4[4];
                LDSM4(vb4,  VhS + bRelA[ntp] + ks2 * 32);
                LDSM4(vbl4, VlS + bRelA[ntp] + ks2 * 32);
#pragma unroll
                for (int s = 0; s < 2; s++) {
                    int nt = 2 * ntp + s;
                    unsigned vbh[2] = {vb4[2 * s], vb4[2 * s + 1]};
                    unsigned vbl[2] = {vbl4[2 * s], vbl4[2 * s + 1]};
                    mma_bf16(out[nt], ph, vbh);
                    mma_bf16(out[nt], ph, vbl);
                    mma_bf16(out[nt], pl, vbh);
                }
            }
        }
    }

    if (j_start > 0) {
        float mn0 = fmaxf(m0, 0.f), mn1 = fmaxf(m1, 0.f);
        float esc0 = __expf(m0 - mn0), esc1 = __expf(m1 - mn1);
        float e0 = __expf(0.f - mn0), e1 = __expf(0.f - mn1);
        sum0 = sum0 * esc0 + 4.f * e0;
        sum1 = sum1 * esc1 + 4.f * e1;
#pragma unroll
        for (int nt = 0; nt < 8; nt++) {
            int col = nt * 8 + 2 * (lane & 3);
            out[nt][0] = out[nt][0] * esc0 + e0 * Vg4[col];
            out[nt][1] = out[nt][1] * esc0 + e0 * Vg4[col + 1];
            out[nt][2] = out[nt][2] * esc1 + e1 * Vg4[col];
            out[nt][3] = out[nt][3] * esc1 + e1 * Vg4[col + 1];
        }
    }

    float inv0 = 1.f / sum0, inv1 = 1.f / sum1;
    const int r0 = i0 + wq * 16 + (lane >> 2);

    // ---- fused global attention (exact fp32 Q reload) ----
    float w[2][4], deninv[2];
#pragma unroll
    for (int rr = 0; rr < 2; rr++) {
        int r = r0 + rr * 8;
        const float* qp = Q + (size_t)r * DMODEL + h * HDIM;
        float dot[4] = {0.f, 0.f, 0.f, 0.f};
#pragma unroll
        for (int ks = 0; ks < 8; ks++) {
#pragma unroll
            for (int e2 = 0; e2 < 2; e2++) {
                int cc = ks * 8 + (lane & 3) + e2 * 4;
                float qv = qp[cc];
#pragma unroll
                for (int t = 0; t < 4; t++)
                    dot[t] = fmaf(qv, KG4[t * HDIM + cc], dot[t]);
            }
        }
#pragma unroll
        for (int t = 0; t < 4; t++) {
#pragma unroll
            for (int o = 1; o < 4; o <<= 1)
                dot[t] += __shfl_xor_sync(0xffffffff, dot[t], o);
            dot[t] *= 0.125f;
        }
        float mg = fmaxf(fmaxf(dot[0], dot[1]), fmaxf(dot[2], dot[3]));
        float den = 0.f;
#pragma unroll
        for (int t = 0; t < 4; t++) { w[rr][t] = __expf(dot[t] - mg); den += w[rr][t]; }
        deninv[rr] = 1.f / den;
    }

    // ---- combine + bf16 hi/lo split directly into out_gemm operand ----
#pragma unroll
    for (int nt = 0; nt < 8; nt++) {
#pragma unroll
        for (int e = 0; e < 4; e++) {
            int rr = (e & 2) ? 1 : 0;
            int col = nt * 8 + 2 * (lane & 3) + (e & 1);
            float g = (w[rr][0] * VG4[0 * HDIM + col] + w[rr][1] * VG4[1 * HDIM + col] +
                       w[rr][2] * VG4[2 * HDIM + col] + w[rr][3] * VG4[3 * HDIM + col]) * deninv[rr];
            float v = out[nt][e] * (rr ? inv1 : inv0) + g;
            size_t idx = (size_t)(r0 + rr * 8) * DMODEL + h * HDIM + col;
            __nv_bfloat16 hb = __float2bfloat16(v);
            g_Bh[idx] = hb;
            g_Bl[idx] = __float2bfloat16(v - __bfloat162float(hb));
        }
    }
}

// ---------------------------------------------------------------------------
// launch
// ---------------------------------------------------------------------------
extern "C" void kernel_launch(void* const* d_in, const int* in_sizes, int n_in,
                              void* d_out, int out_size)
{
    const float* x     = (const float*)d_in[0];
    const float* cos_t = (const float*)d_in[1];
    const float* sin_t = (const float*)d_in[2];
    const int*   pos   = (const int*)d_in[3];
    P4 ws;
    ws.p[0] = (const float*)d_in[4];    // Wqs
    ws.p[1] = (const float*)d_in[5];    // Wks
    ws.p[2] = (const float*)d_in[6];    // Wvs
    ws.p[3] = (const float*)d_in[10];   // Wo
    const float* Wkg = (const float*)d_in[8];
    const float* Wvg = (const float*)d_in[9];
    float* out = (float*)d_out;

    static int attrs_set = 0;
    int attn_smem = ATT_SMEM_WORDS * 4;
    if (!attrs_set) {
        cudaFuncSetAttribute(attn_kernel,
                             cudaFuncAttributeMaxDynamicSharedMemorySize, attn_smem);
        cudaFuncSetAttribute(proj_kernel,
                             cudaFuncAttributeMaxDynamicSharedMemorySize, GEMM_SMEM_BYTES);
        cudaFuncSetAttribute(out_gemm_kernel,
                             cudaFuncAttributeMaxDynamicSharedMemorySize, GEMM_SMEM_BYTES);
        attrs_set = 1;
    }

    __nv_bfloat16* Bh;
    __nv_bfloat16* Bl;
    cudaGetSymbolAddress((void**)&Bh, g_Bh);
    cudaGetSymbolAddress((void**)&Bl, g_Bl);

    split_x_kernel<<<(ACT_ELEMS / 4 + 255) / 256, 256>>>(x, Bh, Bl, ACT_ELEMS / 4);
    dim3 gw(DMODEL / 32, DMODEL / 32, 4);
    split_wt_kernel<<<gw, 256>>>(ws, Bh, Bl);

    dim3 gkg(DMODEL / 256, KGVG_KSPLIT);
    kgvg_part_kernel<<<gkg, 256>>>(x, Wkg, Wvg);
    kgvg_reduce_kernel<<<(2 * NGLOB * DMODEL) / 256, 256>>>();

    dim3 gp(DMODEL / 128, S_LEN / 128, 3);
    proj_kernel<<<gp, 256, GEMM_SMEM_BYTES>>>(cos_t, sin_t, pos);

    dim3 gvt(S_LEN / 32, DMODEL / 32);
    vt_split_kernel<<<gvt, 256>>>();

    dim3 ga(NHEADS, S_LEN / 64);
    attn_kernel<<<ga, 128, attn_smem>>>();

    dim3 go(DMODEL / 128, S_LEN / 128);
    out_gemm_kernel<<<go, 256, GEMM_SMEM_BYTES>>>(out);
}

// round 14
// speedup vs baseline: 2.5239x; 1.0278x over previous
#include <cuda_runtime.h>
#include <cuda_bf16.h>
#include <cstdint>
#include <math.h>

#define S_LEN 2048
#define DMODEL 1024
#define NHEADS 16
#define HDIM 64
#define RADIUS 256
#define NGLOB 4

__device__ float g_P[(size_t)5 * S_LEN * DMODEL];

#define KGVG_KSPLIT 32
__device__ float g_KVGp[KGVG_KSPLIT][2][NGLOB][DMODEL];

#define ACT_ELEMS (S_LEN * DMODEL)
#define W_ELEMS   (DMODEL * DMODEL)
// GEMM operand splits: [0:ACT) activations (x, later O), then 4 weights transposed [n][k]
__device__ __nv_bfloat16 g_Bh[(size_t)ACT_ELEMS + 4 * W_ELEMS];
__device__ __nv_bfloat16 g_Bl[(size_t)ACT_ELEMS + 4 * W_ELEMS];
// attention operand splits (post-rope): Q,K in [s][d]; V transposed [d][s]
__device__ __nv_bfloat16 g_Qbh[ACT_ELEMS], g_Qbl[ACT_ELEMS];
__device__ __nv_bfloat16 g_Kbh[ACT_ELEMS], g_Kbl[ACT_ELEMS];
__device__ __nv_bfloat16 g_Vth[ACT_ELEMS], g_Vtl[ACT_ELEMS];

struct P4 { const float* p[4]; };

__device__ __forceinline__ void mma_bf16(float* c, const unsigned* a, const unsigned* b) {
    asm volatile(
        "mma.sync.aligned.m16n8k16.row.col.f32.bf16.bf16.f32 "
        "{%0,%1,%2,%3}, {%4,%5,%6,%7}, {%8,%9}, {%0,%1,%2,%3};"
        : "+f"(c[0]), "+f"(c[1]), "+f"(c[2]), "+f"(c[3])
        : "r"(a[0]), "r"(a[1]), "r"(a[2]), "r"(a[3]), "r"(b[0]), "r"(b[1]));
}

#define LDSM4(r, addr) \
    asm volatile("ldmatrix.sync.aligned.m8n8.x4.shared.b16 {%0,%1,%2,%3}, [%4];" \
        : "=r"((r)[0]), "=r"((r)[1]), "=r"((r)[2]), "=r"((r)[3]) : "r"(addr))

__device__ __forceinline__ void cpa16(void* dst, const void* src) {
    unsigned s = (unsigned)__cvta_generic_to_shared(dst);
    asm volatile("cp.async.cg.shared.global [%0], [%1], 16;" :: "r"(s), "l"(src));
}

__device__ __forceinline__ unsigned pack_bf16(float a, float b) {
    __nv_bfloat162 t = __floats2bfloat162_rn(a, b);
    return *reinterpret_cast<unsigned*>(&t);
}

// ---------------------------------------------------------------------------
// split kernels
// ---------------------------------------------------------------------------
__global__ __launch_bounds__(256) void split_x_kernel(const float* __restrict__ src,
                                                      __nv_bfloat16* __restrict__ h,
                                                      __nv_bfloat16* __restrict__ l, int n4)
{
    int i = blockIdx.x * blockDim.x + threadIdx.x;
    if (i >= n4) return;
    float4 v = ((const float4*)src)[i];
    float f[4] = {v.x, v.y, v.z, v.w};
    ushort4 hv, lv;
    unsigned short* hp = &hv.x;
    unsigned short* lp = &lv.x;
#pragma unroll
    for (int e = 0; e < 4; e++) {
        __nv_bfloat16 hb = __float2bfloat16(f[e]);
        hp[e] = *reinterpret_cast<unsigned short*>(&hb);
        __nv_bfloat16 lb = __float2bfloat16(f[e] - __bfloat162float(hb));
        lp[e] = *reinterpret_cast<unsigned short*>(&lb);
    }
    ((ushort4*)h)[i] = hv;
    ((ushort4*)l)[i] = lv;
}

__global__ __launch_bounds__(256) void split_wt_kernel(P4 srcs,
                                                       __nv_bfloat16* __restrict__ hbase,
                                                       __nv_bfloat16* __restrict__ lbase)
{
    __shared__ float t[32][33];
    const int z = blockIdx.z;
    const float* W = srcs.p[z];
    const int n0 = blockIdx.x * 32, k0 = blockIdx.y * 32;
    const int tx = threadIdx.x & 31, ty = threadIdx.x >> 5;

#pragma unroll
    for (int j = 0; j < 4; j++)
        t[ty + j * 8][tx] = W[(size_t)(k0 + ty + j * 8) * DMODEL + n0 + tx];
    __syncthreads();

    size_t base = (size_t)ACT_ELEMS + (size_t)z * W_ELEMS;
#pragma unroll
    for (int j = 0; j < 4; j++) {
        int n = n0 + ty + j * 8;
        int k = k0 + tx;
        float v = t[tx][ty + j * 8];
        __nv_bfloat16 hb = __float2bfloat16(v);
        size_t idx = base + (size_t)n * DMODEL + k;
        hbase[idx] = hb;
        lbase[idx] = __float2bfloat16(v - __bfloat162float(hb));
    }
}

// V[s][d] (g_P slot 2) -> Vt bf16 hi/lo [d][s]
__global__ __launch_bounds__(256) void vt_split_kernel()
{
    __shared__ float t[32][33];
    const int s0 = blockIdx.x * 32, d0 = blockIdx.y * 32;
    const int tx = threadIdx.x & 31, ty = threadIdx.x >> 5;

#pragma unroll
    for (int j = 0; j < 4; j++)
        t[ty + j * 8][tx] = g_P[(size_t)2 * ACT_ELEMS + (size_t)(s0 + ty + j * 8) * DMODEL + d0 + tx];
    __syncthreads();

#pragma unroll
    for (int j = 0; j < 4; j++) {
        int d = d0 + ty + j * 8;
        int s = s0 + tx;
        float v = t[tx][ty + j * 8];
        __nv_bfloat16 hb = __float2bfloat16(v);
        size_t idx = (size_t)d * S_LEN + s;
        g_Vth[idx] = hb;
        g_Vtl[idx] = __float2bfloat16(v - __bfloat162float(hb));
    }
}

// ---------------------------------------------------------------------------
// 3xBF16 GEMM (m16n8k16) with ldmatrix fragments, GBK=32, SAFE 2-stage
// double buffer (loads target the opposite buffer, guarded by top barrier),
// fused RoPE, optional bf16 hi/lo epilogue.
// ---------------------------------------------------------------------------
#define GBK 32
#define STR 20                        // words/row: 16 data + 4 pad
#define TILE_WORDS (128 * STR)
#define TILE_BYTES (TILE_WORDS * 4)
#define NSTAGE 2
#define GEMM_SMEM_BYTES (NSTAGE * 4 * TILE_BYTES)   // 81920

__device__ __forceinline__ void gemm3_body(const __nv_bfloat16* __restrict__ Agh,
                                           const __nv_bfloat16* __restrict__ Agl,
                                           const __nv_bfloat16* __restrict__ Bgh,
                                           const __nv_bfloat16* __restrict__ Bgl,
                                           float* __restrict__ C,
                                           __nv_bfloat16* __restrict__ outBh,
                                           __nv_bfloat16* __restrict__ outBl,
                                           bool do_rope,
                                           const float* __restrict__ cos_t,
                                           const float* __restrict__ sin_t,
                                           const int* __restrict__ pos)
{
    extern __shared__ unsigned sm[];
    unsigned* uAh = sm;
    unsigned* uAl = sm + NSTAGE * TILE_WORDS;
    unsigned* uBh = sm + 2 * NSTAGE * TILE_WORDS;
    unsigned* uBl = sm + 3 * NSTAGE * TILE_WORDS;

    const int tid = threadIdx.x;
    const int lane = tid & 31;
    const int warp = tid >> 5;
    const int wm = warp >> 1;
    const int wn = warp & 1;
    const int bx = blockIdx.x, by = blockIdx.y;

    float acc[2][8][4];
#pragma unroll
    for (int mt = 0; mt < 2; mt++)
#pragma unroll
        for (int nt = 0; nt < 8; nt++)
#pragma unroll
            for (int e = 0; e < 4; e++) acc[mt][nt][e] = 0.f;

    auto load_stage = [&](int st, int k0) {
        unsigned* ah = uAh + st * TILE_WORDS;
        unsigned* al = uAl + st * TILE_WORDS;
        unsigned* bh = uBh + st * TILE_WORDS;
        unsigned* bl = uBl + st * TILE_WORDS;
#pragma unroll
        for (int it = 0; it < 2; it++) {
            int idx = it * 256 + tid;          // 0..511
            int r = idx >> 2, ch = idx & 3;
            int so = r * STR + ch * 4;
            size_t ga = (size_t)(by * 128 + r) * DMODEL + k0 + ch * 8;
            size_t gb = (size_t)(bx * 128 + r) * DMODEL + k0 + ch * 8;
            cpa16(ah + so, Agh + ga);
            cpa16(al + so, Agl + ga);
            cpa16(bh + so, Bgh + gb);
            cpa16(bl + so, Bgl + gb);
        }
    };

    // ldmatrix lane-relative byte offsets
    const unsigned uAhS = (unsigned)__cvta_generic_to_shared(uAh);
    const unsigned uAlS = (unsigned)__cvta_generic_to_shared(uAl);
    const unsigned uBhS = (unsigned)__cvta_generic_to_shared(uBh);
    const unsigned uBlS = (unsigned)__cvta_generic_to_shared(uBl);
    unsigned aRel[2], bRel[4];
#pragma unroll
    for (int mt = 0; mt < 2; mt++)
        aRel[mt] = (unsigned)(((wm * 32 + mt * 16 + (lane & 15)) * STR) * 4 +
                              ((lane & 16) ? 16 : 0));
#pragma unroll
    for (int ntp = 0; ntp < 4; ntp++)
        bRel[ntp] = (unsigned)(((wn * 64 + ntp * 16 + ((lane & 16) ? 8 : 0) + (lane & 7)) * STR) * 4 +
                               ((lane & 8) ? 16 : 0));

    load_stage(0, 0);
    asm volatile("cp.async.commit_group;");

    const int NT = DMODEL / GBK;   // 32
#pragma unroll 1
    for (int i = 0; i < NT; i++) {
        const int st = i & 1;
        asm volatile("cp.async.wait_group 0;");
        __syncthreads();
        // safe: buffer st^1 was last computed at iteration i-1; the barrier
        // above guarantees every warp is past that compute before we write.
        if (i + 1 < NT) load_stage(st ^ 1, (i + 1) * GBK);
        asm volatile("cp.async.commit_group;");

        const unsigned stB = (unsigned)(st * TILE_BYTES);

#pragma unroll
        for (int ks = 0; ks < 2; ks++) {
            const unsigned ko = (unsigned)(ks * 32);
            unsigned ah[2][4], al[2][4];
#pragma unroll
            for (int mt = 0; mt < 2; mt++) {
                LDSM4(ah[mt], uAhS + stB + aRel[mt] + ko);
                LDSM4(al[mt], uAlS + stB + aRel[mt] + ko);
            }
            unsigned bh4[4][4], bl4[4][4];
#pragma unroll
            for (int ntp = 0; ntp < 4; ntp++) {
                LDSM4(bh4[ntp], uBhS + stB + bRel[ntp] + ko);
                LDSM4(bl4[ntp], uBlS + stB + bRel[ntp] + ko);
            }
#pragma unroll
            for (int ntp = 0; ntp < 4; ntp++) {
#pragma unroll
                for (int s = 0; s < 2; s++) {
                    int nt = 2 * ntp + s;
                    unsigned bhp[2] = {bh4[ntp][2 * s], bh4[ntp][2 * s + 1]};
                    unsigned blp[2] = {bl4[ntp][2 * s], bl4[ntp][2 * s + 1]};
#pragma unroll
                    for (int mt = 0; mt < 2; mt++) {
                        mma_bf16(acc[mt][nt], ah[mt], bhp);
                        mma_bf16(acc[mt][nt], ah[mt], blp);
                        mma_bf16(acc[mt][nt], al[mt], bhp);
                    }
                }
            }
        }
    }

    if (do_rope) {
#pragma unroll
        for (int mt = 0; mt < 2; mt++) {
            int r0 = by * 128 + wm * 32 + mt * 16 + (lane >> 2);
            int p0 = __ldg(pos + r0);
            int p1 = __ldg(pos + r0 + 8);
#pragma unroll
            for (int nt = 0; nt < 4; nt++) {
#pragma unroll
                for (int e = 0; e < 2; e++) {
                    int d = nt * 8 + 2 * (lane & 3) + e;
                    {
                        float c0 = __ldg(cos_t + p0 * HDIM + d);
                        float s0 = __ldg(sin_t + p0 * HDIM + d);
                        float c1 = __ldg(cos_t + p0 * HDIM + d + 32);
                        float s1 = __ldg(sin_t + p0 * HDIM + d + 32);
                        float x0 = acc[mt][nt][e];
                        float x1 = acc[mt][nt + 4][e];
                        acc[mt][nt][e]     = x0 * c0 - x1 * s0;
                        acc[mt][nt + 4][e] = x1 * c1 + x0 * s1;
                    }
                    {
                        float c0 = __ldg(cos_t + p1 * HDIM + d);
                        float s0 = __ldg(sin_t + p1 * HDIM + d);
                        float c1 = __ldg(cos_t + p1 * HDIM + d + 32);
                        float s1 = __ldg(sin_t + p1 * HDIM + d + 32);
                        float x0 = acc[mt][nt][e + 2];
                        float x1 = acc[mt][nt + 4][e + 2];
                        acc[mt][nt][e + 2]     = x0 * c0 - x1 * s0;
                        acc[mt][nt + 4][e + 2] = x1 * c1 + x0 * s1;
                    }
                }
            }
        }
    }

#pragma unroll
    for (int mt = 0; mt < 2; mt++) {
        int r0 = by * 128 + wm * 32 + mt * 16 + (lane >> 2);
#pragma unroll
        for (int nt = 0; nt < 8; nt++) {
            int cc = bx * 128 + wn * 64 + nt * 8 + ((lane & 3) << 1);
            size_t i0x = (size_t)r0 * DMODEL + cc;
            size_t i1x = (size_t)(r0 + 8) * DMODEL + cc;
            *(float2*)(C + i0x) = make_float2(acc[mt][nt][0], acc[mt][nt][1]);
            *(float2*)(C + i1x) = make_float2(acc[mt][nt][2], acc[mt][nt][3]);
            if (outBh) {
                float v0 = acc[mt][nt][0], v1 = acc[mt][nt][1];
                float v2 = acc[mt][nt][2], v3 = acc[mt][nt][3];
                float h0 = __bfloat162float(__float2bfloat16(v0));
                float h1 = __bfloat162float(__float2bfloat16(v1));
                float h2 = __bfloat162float(__float2bfloat16(v2));
                float h3 = __bfloat162float(__float2bfloat16(v3));
                *(unsigned*)((__nv_bfloat16*)outBh + i0x) = pack_bf16(v0, v1);
                *(unsigned*)((__nv_bfloat16*)outBl + i0x) = pack_bf16(v0 - h0, v1 - h1);
                *(unsigned*)((__nv_bfloat16*)outBh + i1x) = pack_bf16(v2, v3);
                *(unsigned*)((__nv_bfloat16*)outBl + i1x) = pack_bf16(v2 - h2, v3 - h3);
            }
        }
    }
}

__global__ __launch_bounds__(256, 2) void proj_kernel(const float* __restrict__ cos_t,
                                                      const float* __restrict__ sin_t,
                                                      const int* __restrict__ pos)
{
    int z = blockIdx.z;   // 0=Q(rope) 1=K(rope) 2=V
    __nv_bfloat16* oh = (z == 0) ? g_Qbh : (z == 1) ? g_Kbh : nullptr;
    __nv_bfloat16* ol = (z == 0) ? g_Qbl : (z == 1) ? g_Kbl : nullptr;
    gemm3_body(g_Bh, g_Bl,
               g_Bh + ACT_ELEMS + (size_t)z * W_ELEMS,
               g_Bl + ACT_ELEMS + (size_t)z * W_ELEMS,
               g_P + (size_t)z * ACT_ELEMS,
               oh, ol,
               z < 2, cos_t, sin_t, pos);
}

__global__ __launch_bounds__(256, 2) void out_gemm_kernel(float* __restrict__ out)
{
    gemm3_body(g_Bh, g_Bl,
               g_Bh + ACT_ELEMS + (size_t)3 * W_ELEMS,
               g_Bl + ACT_ELEMS + (size_t)3 * W_ELEMS,
               out, nullptr, nullptr, false, nullptr, nullptr, nullptr);
}

// ---------------------------------------------------------------------------
// KG/VG rows 0..3 only, split-K parallel (unchanged).
// ---------------------------------------------------------------------------
__global__ __launch_bounds__(256) void kgvg_part_kernel(const float* __restrict__ x,
                                                        const float* __restrict__ Wkg,
                                                        const float* __restrict__ Wvg)
{
    const int d = blockIdx.x * 256 + threadIdx.x;
    const int kz = blockIdx.y;
    __shared__ float xs[NGLOB][32];
    if (threadIdx.x < NGLOB * 32) {
        int t = threadIdx.x >> 5, k = threadIdx.x & 31;
        xs[t][k] = x[(size_t)t * DMODEL + kz * 32 + k];
    }
    __syncthreads();

    float ak[NGLOB] = {0.f, 0.f, 0.f, 0.f};
    float av[NGLOB] = {0.f, 0.f, 0.f, 0.f};
#pragma unroll 4
    for (int kk = 0; kk < 32; kk++) {
        size_t row = (size_t)(kz * 32 + kk) * DMODEL + d;
        float wk = __ldg(Wkg + row);
        float wv = __ldg(Wvg + row);
#pragma unroll
        for (int t = 0; t < NGLOB; t++) {
            ak[t] = fmaf(xs[t][kk], wk, ak[t]);
            av[t] = fmaf(xs[t][kk], wv, av[t]);
        }
    }
#pragma unroll
    for (int t = 0; t < NGLOB; t++) {
        g_KVGp[kz][0][t][d] = ak[t];
        g_KVGp[kz][1][t][d] = av[t];
    }
}

__global__ __launch_bounds__(256) void kgvg_reduce_kernel()
{
    int idx = blockIdx.x * 256 + threadIdx.x;
    int d = idx & (DMODEL - 1);
    int t = (idx >> 10) & 3;
    int m = idx >> 12;
    float s = 0.f;
#pragma unroll
    for (int kz = 0; kz < KGVG_KSPLIT; kz++) s += g_KVGp[kz][m][t][d];
    g_P[(size_t)(3 + m) * ACT_ELEMS + (size_t)t * DMODEL + d] = s;
}

// ---------------------------------------------------------------------------
// bf16x3 flash attention with ldmatrix fragments (unchanged round-10 winner)
// ---------------------------------------------------------------------------
#define ATS 36
#define CHUNK_WORDS (64 * ATS)
#define OFF_EXTRA (2 * 4 * CHUNK_WORDS)
#define ATT_SMEM_WORDS (OFF_EXTRA + HDIM + 2 * NGLOB * HDIM)

__global__ __launch_bounds__(128, 3) void attn_kernel()
{
    extern __shared__ unsigned smem_u[];
    float* Vg4 = (float*)(smem_u + OFF_EXTRA);
    float* KG4 = Vg4 + HDIM;
    float* VG4 = KG4 + NGLOB * HDIM;

    const int h  = blockIdx.x;
    const int i0 = blockIdx.y * 64;
    const int tid = threadIdx.x;
    const int lane = tid & 31;
    const int wq = tid >> 5;

    const float* Q = g_P;
    const float* V = g_P + (size_t)2 * ACT_ELEMS;

    if (tid < HDIM) {
        const float* vb = V + h * HDIM + tid;
        Vg4[tid] = vb[0] + vb[DMODEL] + vb[2 * DMODEL] + vb[3 * DMODEL];
    }
    for (int i2 = tid; i2 < 2 * NGLOB * HDIM; i2 += 128) {
        int mm = i2 >> 8;
        int t = (i2 >> 6) & 3;
        int c = i2 & 63;
        float val = g_P[(size_t)(3 + mm) * ACT_ELEMS + (size_t)t * DMODEL + h * HDIM + c];
        (mm ? VG4 : KG4)[t * HDIM + c] = val;
    }

    unsigned qh[4][4], ql[4][4];
    {
        const int r0 = i0 + wq * 16 + (lane >> 2);
        const int cb = h * HDIM + 2 * (lane & 3);
#pragma unroll
        for (int ks = 0; ks < 4; ks++) {
            size_t e00 = (size_t)r0 * DMODEL + cb + ks * 16;
            size_t e10 = (size_t)(r0 + 8) * DMODEL + cb + ks * 16;
            qh[ks][0] = *(const unsigned*)(g_Qbh + e00);
            qh[ks][1] = *(const unsigned*)(g_Qbh + e10);
            qh[ks][2] = *(const unsigned*)(g_Qbh + e00 + 8);
            qh[ks][3] = *(const unsigned*)(g_Qbh + e10 + 8);
            ql[ks][0] = *(const unsigned*)(g_Qbl + e00);
            ql[ks][1] = *(const unsigned*)(g_Qbl + e10);
            ql[ks][2] = *(const unsigned*)(g_Qbl + e00 + 8);
            ql[ks][3] = *(const unsigned*)(g_Qbl + e10 + 8);
        }
    }

    float out[8][4];
#pragma unroll
    for (int nt = 0; nt < 8; nt++)
#pragma unroll
        for (int e = 0; e < 4; e++) out[nt][e] = 0.f;
    float m0 = -3.4e38f, m1 = -3.4e38f, sum0 = 0.f, sum1 = 0.f;

    const int j_start = (i0 - RADIUS) > 0 ? (i0 - RADIUS) : 0;
    const int nchunks = (i0 + 64 - j_start) >> 6;

    auto load_chunk = [&](int st, int jc) {
        unsigned* base = smem_u + st * 4 * CHUNK_WORDS;
#pragma unroll
        for (int it = 0; it < 4; it++) {
            int idx = it * 128 + tid;
            int row = idx >> 3, ch = idx & 7;
            int so = row * ATS + ch * 4;
            size_t gk = (size_t)(jc + row) * DMODEL + h * HDIM + ch * 8;
            cpa16(base + so, g_Kbh + gk);
            cpa16(base + CHUNK_WORDS + so, g_Kbl + gk);
            size_t gv = (size_t)(h * HDIM + row) * S_LEN + jc + ch * 8;
            cpa16(base + 2 * CHUNK_WORDS + so, g_Vth + gv);
            cpa16(base + 3 * CHUNK_WORDS + so, g_Vtl + gv);
        }
    };

    const unsigned smemS = (unsigned)__cvta_generic_to_shared(smem_u);
    unsigned bRelA[4];
#pragma unroll
    for (int ntp = 0; ntp < 4; ntp++)
        bRelA[ntp] = (unsigned)(((ntp * 16 + ((lane & 16) ? 8 : 0) + (lane & 7)) * ATS) * 4 +
                                ((lane & 8) ? 16 : 0));

    load_chunk(0, j_start);
    asm volatile("cp.async.commit_group;");

#pragma unroll 1
    for (int ci = 0; ci < nchunks; ci++) {
        const int jc = j_start + ci * 64;
        const int st = ci & 1;
        __syncthreads();
        if (ci + 1 < nchunks) load_chunk(st ^ 1, jc + 64);
        asm volatile("cp.async.commit_group;");
        asm volatile("cp.async.wait_group 1;");
        __syncthreads();

        const unsigned KhS = smemS + (unsigned)(st * 4 * CHUNK_WORDS * 4);
        const unsigned KlS = KhS + CHUNK_WORDS * 4;
        const unsigned VhS = KhS + 2 * CHUNK_WORDS * 4;
        const unsigned VlS = KhS + 3 * CHUNK_WORDS * 4;

        float sc[8][4];
#pragma unroll
        for (int nt = 0; nt < 8; nt++)
#pragma unroll
            for (int e = 0; e < 4; e++) sc[nt][e] = 0.f;

#pragma unroll
        for (int ks = 0; ks < 4; ks++) {
#pragma unroll
            for (int ntp = 0; ntp < 4; ntp++) {
                unsigned kb[4], kbl[4];
                LDSM4(kb,  KhS + bRelA[ntp] + ks * 32);
                LDSM4(kbl, KlS + bRelA[ntp] + ks * 32);
#pragma unroll
                for (int s = 0; s < 2; s++) {
                    int nt = 2 * ntp + s;
                    unsigned bhp[2] = {kb[2 * s], kb[2 * s + 1]};
                    unsigned blp[2] = {kbl[2 * s], kbl[2 * s + 1]};
                    mma_bf16(sc[nt], qh[ks], bhp);
                    mma_bf16(sc[nt], qh[ks], blp);
                    mma_bf16(sc[nt], ql[ks], bhp);
                }
            }
        }

        const int c = lane & 3;
        const int ibase = i0 + wq * 16 + (lane >> 2);
        float mn0 = m0, mn1 = m1;
#pragma unroll
        for (int nt = 0; nt < 8; nt++) {
#pragma unroll
            for (int e = 0; e < 4; e++) {
                int i = ibase + ((e & 2) ? 8 : 0);
                int j = jc + nt * 8 + 2 * c + (e & 1);
                bool inw = (j <= i) && (i - j <= RADIUS);
                float raw = sc[nt][e] * 0.125f;
                float s;
                if (j < NGLOB) s = inw ? (raw + 1e9f) : 0.f;
                else           s = inw ? raw : -3.0e38f;
                sc[nt][e] = s;
                if (e & 2) mn1 = fmaxf(mn1, s); else mn0 = fmaxf(mn0, s);
            }
        }
#pragma unroll
        for (int o = 1; o < 4; o <<= 1) {
            mn0 = fmaxf(mn0, __shfl_xor_sync(0xffffffff, mn0, o));
            mn1 = fmaxf(mn1, __shfl_xor_sync(0xffffffff, mn1, o));
        }
        float esc0 = __expf(m0 - mn0);
        float esc1 = __expf(m1 - mn1);
        m0 = mn0; m1 = mn1;

        float ps0 = 0.f, ps1 = 0.f;
#pragma unroll
        for (int nt = 0; nt < 8; nt++) {
#pragma unroll
            for (int e = 0; e < 4; e++) {
                float p = __expf(sc[nt][e] - ((e & 2) ? m1 : m0));
                sc[nt][e] = p;
                if (e & 2) ps1 += p; else ps0 += p;
            }
        }
#pragma unroll
        for (int o = 1; o < 4; o <<= 1) {
            ps0 += __shfl_xor_sync(0xffffffff, ps0, o);
            ps1 += __shfl_xor_sync(0xffffffff, ps1, o);
        }
        sum0 = sum0 * esc0 + ps0;
        sum1 = sum1 * esc1 + ps1;
#pragma unroll
        for (int nt = 0; nt < 8; nt++) {
            out[nt][0] *= esc0; out[nt][1] *= esc0;
            out[nt][2] *= esc1; out[nt][3] *= esc1;
        }

#pragma unroll
        for (int ks2 = 0; ks2 < 4; ks2++) {
            float* s0v = sc[2 * ks2];
            float* s1v = sc[2 * ks2 + 1];
            float h00 = __bfloat162float(__float2bfloat16(s0v[0]));
            float h01 = __bfloat162float(__float2bfloat16(s0v[1]));
            float h02 = __bfloat162float(__float2bfloat16(s0v[2]));
            float h03 = __bfloat162float(__float2bfloat16(s0v[3]));
            float h10 = __bfloat162float(__float2bfloat16(s1v[0]));
            float h11 = __bfloat162float(__float2bfloat16(s1v[1]));
            float h12 = __bfloat162float(__float2bfloat16(s1v[2]));
            float h13 = __bfloat162float(__float2bfloat16(s1v[3]));
            unsigned ph[4], pl[4];
            ph[0] = pack_bf16(s0v[0], s0v[1]);
            ph[1] = pack_bf16(s0v[2], s0v[3]);
            ph[2] = pack_bf16(s1v[0], s1v[1]);
            ph[3] = pack_bf16(s1v[2], s1v[3]);
            pl[0] = pack_bf16(s0v[0] - h00, s0v[1] - h01);
            pl[1] = pack_bf16(s0v[2] - h02, s0v[3] - h03);
            pl[2] = pack_bf16(s1v[0] - h10, s1v[1] - h11);
            pl[3] = pack_bf16(s1v[2] - h12, s1v[3] - h13);
#pragma unroll
            for (int ntp = 0; ntp < 4; ntp++) {
                unsigned vb4[4], vbl4[4];
                LDSM4(vb4,  VhS + bRelA[ntp] + ks2 * 32);
                LDSM4(vbl4, VlS + bRelA[ntp] + ks2 * 32);
#pragma unroll
                for (int s = 0; s < 2; s++) {
                    int nt = 2 * ntp + s;
                    unsigned vbh[2] = {vb4[2 * s], vb4[2 * s + 1]};
                    unsigned vbl[2] = {vbl4[2 * s], vbl4[2 * s + 1]};
                    mma_bf16(out[nt], ph, vbh);
                    mma_bf16(out[nt], ph, vbl);
                    mma_bf16(out[nt], pl, vbh);
                }
            }
        }
    }

    if (j_start > 0) {
        float mn0 = fmaxf(m0, 0.f), mn1 = fmaxf(m1, 0.f);
        float esc0 = __expf(m0 - mn0), esc1 = __expf(m1 - mn1);
        float e0 = __expf(0.f - mn0), e1 = __expf(0.f - mn1);
        sum0 = sum0 * esc0 + 4.f * e0;
        sum1 = sum1 * esc1 + 4.f * e1;
#pragma unroll
        for (int nt = 0; nt < 8; nt++) {
            int col = nt * 8 + 2 * (lane & 3);
            out[nt][0] = out[nt][0] * esc0 + e0 * Vg4[col];
            out[nt][1] = out[nt][1] * esc0 + e0 * Vg4[col + 1];
            out[nt][2] = out[nt][2] * esc1 + e1 * Vg4[col];
            out[nt][3] = out[nt][3] * esc1 + e1 * Vg4[col + 1];
        }
    }

    float inv0 = 1.f / sum0, inv1 = 1.f / sum1;
    const int r0 = i0 + wq * 16 + (lane >> 2);

    float w[2][4], deninv[2];
#pragma unroll
    for (int rr = 0; rr < 2; rr++) {
        int r = r0 + rr * 8;
        const float* qp = Q + (size_t)r * DMODEL + h * HDIM;
        float dot[4] = {0.f, 0.f, 0.f, 0.f};
#pragma unroll
        for (int ks = 0; ks < 8; ks++) {
#pragma unroll
            for (int e2 = 0; e2 < 2; e2++) {
                int cc = ks * 8 + (lane & 3) + e2 * 4;
                float qv = qp[cc];
#pragma unroll
                for (int t = 0; t < 4; t++)
                    dot[t] = fmaf(qv, KG4[t * HDIM + cc], dot[t]);
            }
        }
#pragma unroll
        for (int t = 0; t < 4; t++) {
#pragma unroll
            for (int o = 1; o < 4; o <<= 1)
                dot[t] += __shfl_xor_sync(0xffffffff, dot[t], o);
            dot[t] *= 0.125f;
        }
        float mg = fmaxf(fmaxf(dot[0], dot[1]), fmaxf(dot[2], dot[3]));
        float den = 0.f;
#pragma unroll
        for (int t = 0; t < 4; t++) { w[rr][t] = __expf(dot[t] - mg); den += w[rr][t]; }
        deninv[rr] = 1.f / den;
    }

#pragma unroll
    for (int nt = 0; nt < 8; nt++) {
#pragma unroll
        for (int e = 0; e < 4; e++) {
            int rr = (e & 2) ? 1 : 0;
            int col = nt * 8 + 2 * (lane & 3) + (e & 1);
            float g = (w[rr][0] * VG4[0 * HDIM + col] + w[rr][1] * VG4[1 * HDIM + col] +
                       w[rr][2] * VG4[2 * HDIM + col] + w[rr][3] * VG4[3 * HDIM + col]) * deninv[rr];
            float v = out[nt][e] * (rr ? inv1 : inv0) + g;
            size_t idx = (size_t)(r0 + rr * 8) * DMODEL + h * HDIM + col;
            __nv_bfloat16 hb = __float2bfloat16(v);
            g_Bh[idx] = hb;
            g_Bl[idx] = __float2bfloat16(v - __bfloat162float(hb));
        }
    }
}

// ---------------------------------------------------------------------------
// launch
// ---------------------------------------------------------------------------
extern "C" void kernel_launch(void* const* d_in, const int* in_sizes, int n_in,
                              void* d_out, int out_size)
{
    const float* x     = (const float*)d_in[0];
    const float* cos_t = (const float*)d_in[1];
    const float* sin_t = (const float*)d_in[2];
    const int*   pos   = (const int*)d_in[3];
    P4 ws;
    ws.p[0] = (const float*)d_in[4];    // Wqs
    ws.p[1] = (const float*)d_in[5];    // Wks
    ws.p[2] = (const float*)d_in[6];    // Wvs
    ws.p[3] = (const float*)d_in[10];   // Wo
    const float* Wkg = (const float*)d_in[8];
    const float* Wvg = (const float*)d_in[9];
    float* out = (float*)d_out;

    static int attrs_set = 0;
    int attn_smem = ATT_SMEM_WORDS * 4;
    if (!attrs_set) {
        cudaFuncSetAttribute(attn_kernel,
                             cudaFuncAttributeMaxDynamicSharedMemorySize, attn_smem);
        cudaFuncSetAttribute(proj_kernel,
                             cudaFuncAttributeMaxDynamicSharedMemorySize, GEMM_SMEM_BYTES);
        cudaFuncSetAttribute(out_gemm_kernel,
                             cudaFuncAttributeMaxDynamicSharedMemorySize, GEMM_SMEM_BYTES);
        attrs_set = 1;
    }

    __nv_bfloat16* Bh;
    __nv_bfloat16* Bl;
    cudaGetSymbolAddress((void**)&Bh, g_Bh);
    cudaGetSymbolAddress((void**)&Bl, g_Bl);

    split_x_kernel<<<(ACT_ELEMS / 4 + 255) / 256, 256>>>(x, Bh, Bl, ACT_ELEMS / 4);
    dim3 gw(DMODEL / 32, DMODEL / 32, 4);
    split_wt_kernel<<<gw, 256>>>(ws, Bh, Bl);

    dim3 gkg(DMODEL / 256, KGVG_KSPLIT);
    kgvg_part_kernel<<<gkg, 256>>>(x, Wkg, Wvg);
    kgvg_reduce_kernel<<<(2 * NGLOB * DMODEL) / 256, 256>>>();

    dim3 gp(DMODEL / 128, S_LEN / 128, 3);
    proj_kernel<<<gp, 256, GEMM_SMEM_BYTES>>>(cos_t, sin_t, pos);

    dim3 gvt(S_LEN / 32, DMODEL / 32);
    vt_split_kernel<<<gvt, 256>>>();

    dim3 ga(NHEADS, S_LEN / 64);
    attn_kernel<<<ga, 128, attn_smem>>>();

    dim3 go(DMODEL / 128, S_LEN / 128);
    out_gemm_kernel<<<go, 256, GEMM_SMEM_BYTES>>>(out);
}